// round 1
// baseline (speedup 1.0000x reference)
#include <cuda_runtime.h>
#include <cuda_bf16.h>
#include <math.h>

// ---------------- problem constants ----------------
constexpr int BB     = 2;
constexpr int LL     = 2048;
constexpr int HID    = 2560;
constexpr int NH     = 16;
constexpr int NKV    = 4;
constexpr int HD     = 256;
constexpr int GQA    = NH / NKV;      // 4
constexpr int INNER  = NH * HD;       // 4096
constexpr int ROWS   = BB * LL;       // 4096
constexpr float EPS  = 1e-6f;

// ---------------- scratch (device globals; no allocation allowed) ----------
__device__ float g_qg  [(size_t)ROWS * 2 * INNER];   // X@Wq  : [4096, 8192]
__device__ float g_ktmp[(size_t)ROWS * NKV * HD];    // X@Wk  : [4096, 1024]
__device__ float g_vtmp[(size_t)ROWS * NKV * HD];    // X@Wv  : [4096, 1024]
__device__ float g_q   [(size_t)BB * NH  * LL * HD]; // normed+roped Q [b,h,l,d]
__device__ float g_kn  [(size_t)BB * NKV * LL * HD]; // normed+roped K [b,kv,l,d]
__device__ float g_vt  [(size_t)BB * NKV * LL * HD]; // V transposed   [b,kv,l,d]
__device__ float g_att [(size_t)ROWS * INNER];       // attn out [b*L+l, h*256+d]

// ---------------- fp32 tiled GEMM: C[M,N] = A[M,K] @ B[K,N] -----------------
// 128x128 block tile, k-tile 16, 256 threads, 8x8 per thread.
// All M,N divisible by 128 and K divisible by 16 in this problem -> no guards.
constexpr int TS = 128;
constexpr int KT = 16;

__global__ void __launch_bounds__(256) gemm_f32(
    const float* __restrict__ A, const float* __restrict__ Bm,
    float* __restrict__ C, int M, int N, int K)
{
    __shared__ float As[KT][TS + 4];   // +4 pad: reduce store conflicts
    __shared__ float Bs[KT][TS];

    const int tid = threadIdx.x;
    const int tx  = tid & 15;          // 0..15 (col group)
    const int ty  = tid >> 4;          // 0..15 (row group)
    const int row0 = blockIdx.y * TS;
    const int col0 = blockIdx.x * TS;

    float acc[8][8];
    #pragma unroll
    for (int i = 0; i < 8; i++)
        #pragma unroll
        for (int j = 0; j < 8; j++) acc[i][j] = 0.f;

    for (int k0 = 0; k0 < K; k0 += KT) {
        // load A tile (128 rows x 16 k) transposed into As[k][row]
        #pragma unroll
        for (int i = 0; i < 2; i++) {
            int idx = tid + i * 256;          // 0..511 float4 slots
            int ar  = idx >> 2;               // 0..127
            int ac  = (idx & 3) * 4;          // 0,4,8,12
            float4 v = *(const float4*)&A[(size_t)(row0 + ar) * K + k0 + ac];
            As[ac + 0][ar] = v.x;
            As[ac + 1][ar] = v.y;
            As[ac + 2][ar] = v.z;
            As[ac + 3][ar] = v.w;
        }
        // load B tile (16 k x 128 cols) straight
        #pragma unroll
        for (int i = 0; i < 2; i++) {
            int idx = tid + i * 256;          // 0..511 float4 slots
            int br  = idx >> 5;               // 0..15
            int bc  = (idx & 31) * 4;         // 0..124
            *(float4*)&Bs[br][bc] =
                *(const float4*)&Bm[(size_t)(k0 + br) * N + col0 + bc];
        }
        __syncthreads();

        #pragma unroll
        for (int k = 0; k < KT; k++) {
            float ra[8], rb[8];
            #pragma unroll
            for (int i = 0; i < 8; i++) ra[i] = As[k][ty * 8 + i];
            #pragma unroll
            for (int j = 0; j < 8; j++) rb[j] = Bs[k][tx * 8 + j];
            #pragma unroll
            for (int i = 0; i < 8; i++)
                #pragma unroll
                for (int j = 0; j < 8; j++)
                    acc[i][j] = fmaf(ra[i], rb[j], acc[i][j]);
        }
        __syncthreads();
    }

    #pragma unroll
    for (int i = 0; i < 8; i++) {
        size_t r = (size_t)(row0 + ty * 8 + i);
        #pragma unroll
        for (int j = 0; j < 8; j += 4) {
            float4 v = make_float4(acc[i][j], acc[i][j+1], acc[i][j+2], acc[i][j+3]);
            *(float4*)&C[r * N + col0 + tx * 8 + j] = v;
        }
    }
}

// ---------------- per-head RMSNorm + RoPE -----------------------------------
// One block = one (row, head). 256 threads = HEAD_DIM.
__device__ __forceinline__ float block_sumsq(float v, float* red)
{
    #pragma unroll
    for (int o = 16; o; o >>= 1) v += __shfl_xor_sync(0xffffffffu, v, o);
    int lane = threadIdx.x & 31, warp = threadIdx.x >> 5;
    if (lane == 0) red[warp] = v;
    __syncthreads();
    float t = red[0];
    #pragma unroll
    for (int w = 1; w < 8; w++) t += red[w];
    return t;
}

__global__ void __launch_bounds__(256) q_prep(
    const float* __restrict__ qg, const float* __restrict__ cosb,
    const float* __restrict__ sinb, const float* __restrict__ w)
{
    __shared__ float red[8];
    int row = blockIdx.x;             // b*L + l
    int h   = blockIdx.y;
    int d   = threadIdx.x;
    int l   = row & (LL - 1);
    int b   = row >> 11;

    const float* src = qg + (size_t)row * (2 * INNER) + h * HD;
    float x  = src[d];
    float ss = block_sumsq(x * x, red);
    float rms = rsqrtf(ss * (1.0f / HD) + EPS);

    int   dp  = (d < HD/2) ? d + HD/2 : d - HD/2;
    float xp  = src[dp];
    float xn  = x  * rms * w[d];
    float xpn = xp * rms * w[dp];
    float rot = (d < HD/2) ? -xpn : xpn;
    float c = cosb[(size_t)l * HD + d];
    float s = sinb[(size_t)l * HD + d];
    g_q[(((size_t)b * NH + h) * LL + l) * HD + d] = xn * c + rot * s;
}

__global__ void __launch_bounds__(256) kv_prep(
    const float* __restrict__ ktmp, const float* __restrict__ vtmp,
    const float* __restrict__ cosb, const float* __restrict__ sinb,
    const float* __restrict__ w)
{
    __shared__ float red[8];
    int row = blockIdx.x;
    int h   = blockIdx.y;              // kv head
    int d   = threadIdx.x;
    int l   = row & (LL - 1);
    int b   = row >> 11;

    const float* src = ktmp + (size_t)row * (NKV * HD) + h * HD;
    float x  = src[d];
    float ss = block_sumsq(x * x, red);
    float rms = rsqrtf(ss * (1.0f / HD) + EPS);

    int   dp  = (d < HD/2) ? d + HD/2 : d - HD/2;
    float xp  = src[dp];
    float xn  = x  * rms * w[d];
    float xpn = xp * rms * w[dp];
    float rot = (d < HD/2) ? -xpn : xpn;
    float c = cosb[(size_t)l * HD + d];
    float s = sinb[(size_t)l * HD + d];
    size_t dst = (((size_t)b * NKV + h) * LL + l) * HD + d;
    g_kn[dst] = xn * c + rot * s;
    g_vt[dst] = vtmp[(size_t)row * (NKV * HD) + h * HD + d];
}

// ---------------- causal flash attention (fp32) -----------------------------
// Block: 8 warps, each warp owns one query row. K/V tiles of 16 rows staged
// in shared memory. Lane owns dims d = lane + 32*j (conflict-free scalar LDS).
constexpr int ATK = 16;   // K/V tile rows

__global__ void __launch_bounds__(256) attn_kernel()
{
    __shared__ float Ks[ATK][HD];
    __shared__ float Vs[ATK][HD];

    const int b    = blockIdx.z;
    const int h    = blockIdx.y;
    const int warp = threadIdx.x >> 5;
    const int lane = threadIdx.x & 31;
    const int qi   = blockIdx.x * 8 + warp;

    const float* qptr  = g_q  + (((size_t)b * NH  + h)       * LL + qi) * HD;
    const float* kbase = g_kn + (((size_t)b * NKV + h / GQA) * LL)      * HD;
    const float* vbase = g_vt + (((size_t)b * NKV + h / GQA) * LL)      * HD;

    float qr[8], ov[8];
    #pragma unroll
    for (int j = 0; j < 8; j++) { qr[j] = qptr[lane + 32 * j]; ov[j] = 0.f; }

    float m = -INFINITY, lsum = 0.f;
    const float scale = 0.0625f;                 // 1/sqrt(256)
    const int kmax   = blockIdx.x * 8 + 7;       // max q row in block
    const int ntiles = (kmax + ATK) / ATK;       // ceil((kmax+1)/ATK)

    for (int t = 0; t < ntiles; t++) {
        const int kb = t * ATK;
        // cooperative stage of K and V tiles (16 x 256 each)
        #pragma unroll
        for (int i = 0; i < 4; i++) {
            int idx = threadIdx.x + i * 256;     // 0..1023 float4 slots
            int r   = idx >> 6;                  // row (64 float4 per row)
            int c   = (idx & 63) * 4;
            *(float4*)&Ks[r][c] = *(const float4*)&kbase[(size_t)(kb + r) * HD + c];
            *(float4*)&Vs[r][c] = *(const float4*)&vbase[(size_t)(kb + r) * HD + c];
        }
        __syncthreads();

        const int kk_end = min(ATK, qi - kb + 1);   // causal bound (can be <=0)
        for (int kk = 0; kk < kk_end; kk++) {
            float s = 0.f;
            #pragma unroll
            for (int j = 0; j < 8; j++)
                s = fmaf(qr[j], Ks[kk][lane + 32 * j], s);
            #pragma unroll
            for (int o = 16; o; o >>= 1) s += __shfl_xor_sync(0xffffffffu, s, o);
            s *= scale;

            float mnew = fmaxf(m, s);
            float corr = __expf(m - mnew);
            float p    = __expf(s - mnew);
            lsum = lsum * corr + p;
            #pragma unroll
            for (int j = 0; j < 8; j++)
                ov[j] = ov[j] * corr + p * Vs[kk][lane + 32 * j];
            m = mnew;
        }
        __syncthreads();
    }

    const float inv = 1.f / lsum;
    float* op = g_att + ((size_t)(b * LL + qi)) * INNER + h * HD;
    #pragma unroll
    for (int j = 0; j < 8; j++) op[lane + 32 * j] = ov[j] * inv;
}

// ---------------- gating: att *= silu(gate) ---------------------------------
__global__ void __launch_bounds__(256) gate_mul(const float* __restrict__ qg)
{
    size_t i  = (size_t)blockIdx.x * 256 + threadIdx.x;  // over ROWS*INNER
    size_t row = i >> 12;                                 // /4096
    int    col = (int)(i & 4095);
    float g  = qg[row * (2 * INNER) + INNER + col];
    float sg = g / (1.f + __expf(-g));
    g_att[i] *= sg;
}

// ---------------- launch ----------------------------------------------------
extern "C" void kernel_launch(void* const* d_in, const int* in_sizes, int n_in,
                              void* d_out, int out_size)
{
    const float* X    = (const float*)d_in[0];
    const float* cosb = (const float*)d_in[1];
    const float* sinb = (const float*)d_in[2];
    const float* Wq   = (const float*)d_in[3];
    const float* Wk   = (const float*)d_in[4];
    const float* Wv   = (const float*)d_in[5];
    const float* Wo   = (const float*)d_in[6];
    const float* qw   = (const float*)d_in[7];
    const float* kw   = (const float*)d_in[8];
    float* out = (float*)d_out;

    float *qg, *ktmp, *vtmp, *att;
    cudaGetSymbolAddress((void**)&qg,   g_qg);
    cudaGetSymbolAddress((void**)&ktmp, g_ktmp);
    cudaGetSymbolAddress((void**)&vtmp, g_vtmp);
    cudaGetSymbolAddress((void**)&att,  g_att);

    // 1) projections
    gemm_f32<<<dim3(2 * INNER / TS, ROWS / TS), 256>>>(X, Wq, qg,   ROWS, 2 * INNER, HID);
    gemm_f32<<<dim3(NKV * HD / TS,  ROWS / TS), 256>>>(X, Wk, ktmp, ROWS, NKV * HD,  HID);
    gemm_f32<<<dim3(NKV * HD / TS,  ROWS / TS), 256>>>(X, Wv, vtmp, ROWS, NKV * HD,  HID);

    // 2) per-head RMSNorm + RoPE (+ V transpose)
    q_prep <<<dim3(ROWS, NH),  256>>>(qg, cosb, sinb, qw);
    kv_prep<<<dim3(ROWS, NKV), 256>>>(ktmp, vtmp, cosb, sinb, kw);

    // 3) causal attention
    attn_kernel<<<dim3(LL / 8, NH, BB), 256>>>();

    // 4) gate
    gate_mul<<<(unsigned)((size_t)ROWS * INNER / 256), 256>>>(qg);

    // 5) output projection
    gemm_f32<<<dim3(HID / TS, ROWS / TS), 256>>>(att, Wo, out, ROWS, HID, INNER);
}

// round 3
// speedup vs baseline: 1.1644x; 1.1644x over previous
#include <cuda_runtime.h>
#include <cuda_bf16.h>
#include <mma.h>
#include <math.h>
#include <stdint.h>

using namespace nvcuda;

// ---------------- problem constants ----------------
constexpr int BB     = 2;
constexpr int LL     = 2048;
constexpr int HID    = 2560;
constexpr int NH     = 16;
constexpr int NKV    = 4;
constexpr int HD     = 256;
constexpr int GQA    = NH / NKV;      // 4
constexpr int INNER  = NH * HD;       // 4096
constexpr int ROWS   = BB * LL;       // 4096
constexpr float EPS  = 1e-6f;

// ---------------- scratch (device globals) ----------------------------------
__device__ float g_qg  [(size_t)ROWS * 2 * INNER];   // X@Wq  : [4096, 8192]
__device__ float g_ktmp[(size_t)ROWS * NKV * HD];    // X@Wk
__device__ float g_vtmp[(size_t)ROWS * NKV * HD];    // X@Wv
__device__ float g_q   [(size_t)BB * NH  * LL * HD]; // normed+roped Q
__device__ float g_kn  [(size_t)BB * NKV * LL * HD]; // normed+roped K
__device__ float g_vt  [(size_t)BB * NKV * LL * HD]; // V transposed
__device__ float g_att [(size_t)ROWS * INNER];       // attn out

// ================= tf32 WMMA GEMM: C[M,N] = A[M,K] @ B[K,N] ==================
// CTA tile 128x128, BK=32, 8 warps (4m x 2n), warp tile 32x64 (2x4 wmma 16x16).
// cp.async double-buffered SMEM pipeline.
constexpr int BM = 128, BN = 128, BK = 32;
constexpr int APAD = 4, BPAD = 4;                  // keep 16B cp.async alignment
constexpr int ALD  = BK + APAD;                    // 36 floats/row
constexpr int BLD  = BN + BPAD;                    // 132 floats/row
constexpr int ASTAGE = BM * ALD;                   // floats
constexpr int BSTAGE = BK * BLD;                   // floats
constexpr int GEMM_SMEM = 2 * (ASTAGE + BSTAGE) * 4;  // 70656 bytes

__device__ __forceinline__ void cp16(uint32_t dst, const float* src) {
    asm volatile("cp.async.cg.shared.global [%0], [%1], 16;" :: "r"(dst), "l"(src));
}

__global__ void __launch_bounds__(256) gemm_tc(
    const float* __restrict__ A, const float* __restrict__ Bm,
    float* __restrict__ C, int M, int N, int K)
{
    extern __shared__ float smem[];
    float* Abuf = smem;                       // [2][ASTAGE]
    float* Bbuf = smem + 2 * ASTAGE;          // [2][BSTAGE]
    const uint32_t sA = (uint32_t)__cvta_generic_to_shared(Abuf);
    const uint32_t sB = (uint32_t)__cvta_generic_to_shared(Bbuf);

    const int tid  = threadIdx.x;
    const int wid  = tid >> 5;
    const int wm   = wid & 3;                 // 0..3 -> m offset wm*32
    const int wn   = wid >> 2;                // 0..1 -> n offset wn*64
    const int row0 = blockIdx.y * BM;
    const int col0 = blockIdx.x * BN;

    wmma::fragment<wmma::accumulator, 16, 16, 8, float> acc[2][4];
    #pragma unroll
    for (int i = 0; i < 2; i++)
        #pragma unroll
        for (int j = 0; j < 4; j++) wmma::fill_fragment(acc[i][j], 0.f);

    const int S = K / BK;

    auto stage = [&](int buf, int s) {
        const int k0 = s * BK;
        #pragma unroll
        for (int i = 0; i < 4; i++) {         // A: 128x32 = 1024 float4
            int idx = tid + i * 256;
            int r = idx >> 3, c = (idx & 7) * 4;
            cp16(sA + (uint32_t)(buf * ASTAGE + r * ALD + c) * 4,
                 &A[(size_t)(row0 + r) * K + k0 + c]);
        }
        #pragma unroll
        for (int i = 0; i < 4; i++) {         // B: 32x128 = 1024 float4
            int idx = tid + i * 256;
            int r = idx >> 5, c = (idx & 31) * 4;
            cp16(sB + (uint32_t)(buf * BSTAGE + r * BLD + c) * 4,
                 &Bm[(size_t)(k0 + r) * N + col0 + c]);
        }
        asm volatile("cp.async.commit_group;" ::: "memory");
    };

    stage(0, 0);

    for (int s = 0; s < S; s++) {
        asm volatile("cp.async.wait_group 0;" ::: "memory");
        __syncthreads();
        if (s + 1 < S) stage((s + 1) & 1, s + 1);

        const float* At = Abuf + (s & 1) * ASTAGE;
        const float* Bt = Bbuf + (s & 1) * BSTAGE;
        #pragma unroll
        for (int kk = 0; kk < BK / 8; kk++) {
            wmma::fragment<wmma::matrix_a, 16, 16, 8, wmma::precision::tf32,
                           wmma::row_major> af[2];
            wmma::fragment<wmma::matrix_b, 16, 16, 8, wmma::precision::tf32,
                           wmma::row_major> bf[4];
            #pragma unroll
            for (int i = 0; i < 2; i++) {
                wmma::load_matrix_sync(af[i], At + (wm * 32 + i * 16) * ALD + kk * 8, ALD);
                #pragma unroll
                for (int t = 0; t < af[i].num_elements; t++)
                    af[i].x[t] = wmma::__float_to_tf32(af[i].x[t]);
            }
            #pragma unroll
            for (int j = 0; j < 4; j++) {
                wmma::load_matrix_sync(bf[j], Bt + (kk * 8) * BLD + wn * 64 + j * 16, BLD);
                #pragma unroll
                for (int t = 0; t < bf[j].num_elements; t++)
                    bf[j].x[t] = wmma::__float_to_tf32(bf[j].x[t]);
            }
            #pragma unroll
            for (int i = 0; i < 2; i++)
                #pragma unroll
                for (int j = 0; j < 4; j++)
                    wmma::mma_sync(acc[i][j], af[i], bf[j], acc[i][j]);
        }
        __syncthreads();
    }

    #pragma unroll
    for (int i = 0; i < 2; i++)
        #pragma unroll
        for (int j = 0; j < 4; j++)
            wmma::store_matrix_sync(
                &C[(size_t)(row0 + wm * 32 + i * 16) * N + col0 + wn * 64 + j * 16],
                acc[i][j], N, wmma::mem_row_major);
}

// ---------------- per-head RMSNorm + RoPE -----------------------------------
__device__ __forceinline__ float block_sumsq(float v, float* red)
{
    #pragma unroll
    for (int o = 16; o; o >>= 1) v += __shfl_xor_sync(0xffffffffu, v, o);
    int lane = threadIdx.x & 31, warp = threadIdx.x >> 5;
    if (lane == 0) red[warp] = v;
    __syncthreads();
    float t = red[0];
    #pragma unroll
    for (int w = 1; w < 8; w++) t += red[w];
    return t;
}

__global__ void __launch_bounds__(256) q_prep(
    const float* __restrict__ qg, const float* __restrict__ cosb,
    const float* __restrict__ sinb, const float* __restrict__ w)
{
    __shared__ float red[8];
    int row = blockIdx.x, h = blockIdx.y, d = threadIdx.x;
    int l = row & (LL - 1), b = row >> 11;

    const float* src = qg + (size_t)row * (2 * INNER) + h * HD;
    float x  = src[d];
    float ss = block_sumsq(x * x, red);
    float rms = rsqrtf(ss * (1.0f / HD) + EPS);

    int   dp  = (d < HD/2) ? d + HD/2 : d - HD/2;
    float xp  = src[dp];
    float xn  = x  * rms * w[d];
    float xpn = xp * rms * w[dp];
    float rot = (d < HD/2) ? -xpn : xpn;
    float c = cosb[(size_t)l * HD + d];
    float s = sinb[(size_t)l * HD + d];
    g_q[(((size_t)b * NH + h) * LL + l) * HD + d] = xn * c + rot * s;
}

__global__ void __launch_bounds__(256) kv_prep(
    const float* __restrict__ ktmp, const float* __restrict__ vtmp,
    const float* __restrict__ cosb, const float* __restrict__ sinb,
    const float* __restrict__ w)
{
    __shared__ float red[8];
    int row = blockIdx.x, h = blockIdx.y, d = threadIdx.x;
    int l = row & (LL - 1), b = row >> 11;

    const float* src = ktmp + (size_t)row * (NKV * HD) + h * HD;
    float x  = src[d];
    float ss = block_sumsq(x * x, red);
    float rms = rsqrtf(ss * (1.0f / HD) + EPS);

    int   dp  = (d < HD/2) ? d + HD/2 : d - HD/2;
    float xp  = src[dp];
    float xn  = x  * rms * w[d];
    float xpn = xp * rms * w[dp];
    float rot = (d < HD/2) ? -xpn : xpn;
    float c = cosb[(size_t)l * HD + d];
    float s = sinb[(size_t)l * HD + d];
    size_t dst = (((size_t)b * NKV + h) * LL + l) * HD + d;
    g_kn[dst] = xn * c + rot * s;
    g_vt[dst] = vtmp[(size_t)row * (NKV * HD) + h * HD + d];
}

// ---------------- causal flash attention (fp32) -----------------------------
constexpr int ATK = 16;

__global__ void __launch_bounds__(256) attn_kernel()
{
    __shared__ float Ks[ATK][HD];
    __shared__ float Vs[ATK][HD];

    const int b    = blockIdx.z;
    const int h    = blockIdx.y;
    const int warp = threadIdx.x >> 5;
    const int lane = threadIdx.x & 31;
    const int qi   = blockIdx.x * 8 + warp;

    const float* qptr  = g_q  + (((size_t)b * NH  + h)       * LL + qi) * HD;
    const float* kbase = g_kn + (((size_t)b * NKV + h / GQA) * LL)      * HD;
    const float* vbase = g_vt + (((size_t)b * NKV + h / GQA) * LL)      * HD;

    float qr[8], ov[8];
    #pragma unroll
    for (int j = 0; j < 8; j++) { qr[j] = qptr[lane + 32 * j]; ov[j] = 0.f; }

    float m = -INFINITY, lsum = 0.f;
    const float scale = 0.0625f;
    const int kmax   = blockIdx.x * 8 + 7;
    const int ntiles = (kmax + ATK) / ATK;

    for (int t = 0; t < ntiles; t++) {
        const int kb = t * ATK;
        #pragma unroll
        for (int i = 0; i < 4; i++) {
            int idx = threadIdx.x + i * 256;
            int r   = idx >> 6;
            int c   = (idx & 63) * 4;
            *(float4*)&Ks[r][c] = *(const float4*)&kbase[(size_t)(kb + r) * HD + c];
            *(float4*)&Vs[r][c] = *(const float4*)&vbase[(size_t)(kb + r) * HD + c];
        }
        __syncthreads();

        const int kk_end = min(ATK, qi - kb + 1);
        for (int kk = 0; kk < kk_end; kk++) {
            float s = 0.f;
            #pragma unroll
            for (int j = 0; j < 8; j++)
                s = fmaf(qr[j], Ks[kk][lane + 32 * j], s);
            #pragma unroll
            for (int o = 16; o; o >>= 1) s += __shfl_xor_sync(0xffffffffu, s, o);
            s *= scale;

            float mnew = fmaxf(m, s);
            float corr = __expf(m - mnew);
            float p    = __expf(s - mnew);
            lsum = lsum * corr + p;
            #pragma unroll
            for (int j = 0; j < 8; j++)
                ov[j] = ov[j] * corr + p * Vs[kk][lane + 32 * j];
            m = mnew;
        }
        __syncthreads();
    }

    const float inv = 1.f / lsum;
    float* op = g_att + ((size_t)(b * LL + qi)) * INNER + h * HD;
    #pragma unroll
    for (int j = 0; j < 8; j++) op[lane + 32 * j] = ov[j] * inv;
}

// ---------------- gating: att *= silu(gate) ---------------------------------
__global__ void __launch_bounds__(256) gate_mul(const float* __restrict__ qg)
{
    size_t i   = (size_t)blockIdx.x * 256 + threadIdx.x;
    size_t row = i >> 12;
    int    col = (int)(i & 4095);
    float g  = qg[row * (2 * INNER) + INNER + col];
    float sg = g / (1.f + __expf(-g));
    g_att[i] *= sg;
}

// ---------------- launch ----------------------------------------------------
extern "C" void kernel_launch(void* const* d_in, const int* in_sizes, int n_in,
                              void* d_out, int out_size)
{
    const float* X    = (const float*)d_in[0];
    const float* cosb = (const float*)d_in[1];
    const float* sinb = (const float*)d_in[2];
    const float* Wq   = (const float*)d_in[3];
    const float* Wk   = (const float*)d_in[4];
    const float* Wv   = (const float*)d_in[5];
    const float* Wo   = (const float*)d_in[6];
    const float* qw   = (const float*)d_in[7];
    const float* kw   = (const float*)d_in[8];
    float* out = (float*)d_out;

    float *qg, *ktmp, *vtmp, *att;
    cudaGetSymbolAddress((void**)&qg,   g_qg);
    cudaGetSymbolAddress((void**)&ktmp, g_ktmp);
    cudaGetSymbolAddress((void**)&vtmp, g_vtmp);
    cudaGetSymbolAddress((void**)&att,  g_att);

    static bool attr_set = false;
    if (!attr_set) {
        cudaFuncSetAttribute(gemm_tc, cudaFuncAttributeMaxDynamicSharedMemorySize,
                             GEMM_SMEM);
        attr_set = true;
    }

    // 1) projections (tf32 WMMA)
    gemm_tc<<<dim3(2 * INNER / BN, ROWS / BM), 256, GEMM_SMEM>>>(X, Wq, qg,   ROWS, 2 * INNER, HID);
    gemm_tc<<<dim3(NKV * HD / BN,  ROWS / BM), 256, GEMM_SMEM>>>(X, Wk, ktmp, ROWS, NKV * HD,  HID);
    gemm_tc<<<dim3(NKV * HD / BN,  ROWS / BM), 256, GEMM_SMEM>>>(X, Wv, vtmp, ROWS, NKV * HD,  HID);

    // 2) per-head RMSNorm + RoPE (+ V transpose)
    q_prep <<<dim3(ROWS, NH),  256>>>(qg, cosb, sinb, qw);
    kv_prep<<<dim3(ROWS, NKV), 256>>>(ktmp, vtmp, cosb, sinb, kw);

    // 3) causal attention
    attn_kernel<<<dim3(LL / 8, NH, BB), 256>>>();

    // 4) gate
    gate_mul<<<(unsigned)((size_t)ROWS * INNER / 256), 256>>>(qg);

    // 5) output projection (tf32 WMMA)
    gemm_tc<<<dim3(HID / BN, ROWS / BM), 256, GEMM_SMEM>>>(att, Wo, out, ROWS, HID, INNER);
}

// round 4
// speedup vs baseline: 1.6412x; 1.4095x over previous
#include <cuda_runtime.h>
#include <cuda_bf16.h>
#include <math.h>
#include <stdint.h>

// ---------------- problem constants ----------------
constexpr int BB     = 2;
constexpr int LL     = 2048;
constexpr int HID    = 2560;
constexpr int NH     = 16;
constexpr int NKV    = 4;
constexpr int HD     = 256;
constexpr int GQA    = NH / NKV;      // 4
constexpr int INNER  = NH * HD;       // 4096
constexpr int ROWS   = BB * LL;       // 4096
constexpr float EPS  = 1e-6f;

// ---------------- scratch (device globals) ----------------------------------
__device__ float g_qg  [(size_t)ROWS * 2 * INNER];
__device__ float g_ktmp[(size_t)ROWS * NKV * HD];
__device__ float g_vtmp[(size_t)ROWS * NKV * HD];
__device__ float g_q   [(size_t)BB * NH  * LL * HD];
__device__ float g_kn  [(size_t)BB * NKV * LL * HD];
__device__ float g_vt  [(size_t)BB * NKV * LL * HD];
__device__ float g_att [(size_t)ROWS * INNER];
// fragment-packed, tf32-rounded operands
__device__ float g_xp  [(size_t)ROWS * HID];         // packed A: X
__device__ float g_attp[(size_t)ROWS * INNER];       // packed A: att
__device__ float g_wqp [(size_t)HID * 2 * INNER];    // packed B
__device__ float g_wkp [(size_t)HID * NKV * HD];
__device__ float g_wvp [(size_t)HID * NKV * HD];
__device__ float g_wop [(size_t)INNER * HID];

__device__ __forceinline__ float tf32r(float x) {
    uint32_t b; asm("cvt.rna.tf32.f32 %0, %1;" : "=r"(b) : "f"(x));
    return __uint_as_float(b);
}

// ================= operand packing ==========================================
// mma.m16n8k8 fragment maps (g = lane>>2, t = lane&3):
//   A a0:(g,t) a1:(g+8,t) a2:(g,t+4) a3:(g+8,t+4)  [16x8, row-major]
//   B b0:(k=t,n=g) b1:(k=t+4,n=g)                   [8x8, col for mma.row.col]
// Packed A layout per (mtile,ktile): slot = (ks*8 + mb)*32 + lane, float4 regs.
// Packed B layout per (ntile,ktile): slot = (ks*16 + nb)*32 + lane, float2 regs.
__global__ void __launch_bounds__(256) pack_a(
    const float* __restrict__ A, float* __restrict__ Ap, int K)
{
    size_t slot = (size_t)blockIdx.x * 256 + threadIdx.x;
    int lane = slot & 31, mb = (slot >> 5) & 7, ks = (slot >> 8) & 3;
    size_t rest = slot >> 10;
    int KT = K / 32;
    int kt = (int)(rest % KT), mt = (int)(rest / KT);
    int g = lane >> 2, t = lane & 3;
    int row = mt * 128 + mb * 16 + g;
    int col = kt * 32 + ks * 8 + t;
    float4 v;
    v.x = tf32r(A[(size_t)row * K + col]);
    v.y = tf32r(A[(size_t)(row + 8) * K + col]);
    v.z = tf32r(A[(size_t)row * K + col + 4]);
    v.w = tf32r(A[(size_t)(row + 8) * K + col + 4]);
    *(float4*)&Ap[slot * 4] = v;
}

__global__ void __launch_bounds__(256) pack_b(
    const float* __restrict__ Bm, float* __restrict__ Bp, int K, int N)
{
    size_t slot = (size_t)blockIdx.x * 256 + threadIdx.x;
    int lane = slot & 31, nb = (slot >> 5) & 15, ks = (slot >> 9) & 3;
    size_t rest = slot >> 11;
    int KT = K / 32;
    int kt = (int)(rest % KT), nt = (int)(rest / KT);
    int g = lane >> 2, t = lane & 3;
    int k = kt * 32 + ks * 8 + t;
    int n = nt * 128 + nb * 8 + g;
    float2 v;
    v.x = tf32r(Bm[(size_t)k * N + n]);
    v.y = tf32r(Bm[(size_t)(k + 4) * N + n]);
    *(float2*)&Bp[slot * 2] = v;
}

// ================= tf32 mma.sync GEMM on packed operands =====================
// CTA tile 128x128, BK=32, 8 warps (4m x 2n), warp tile 32x64.
constexpr int PSTAGE    = 4096;                       // floats per operand stage
constexpr int GEMM_SMEM = 4 * PSTAGE * 4;             // 65536 B (2 bufs x A,B)

__device__ __forceinline__ void cp16(uint32_t dst, const float* src) {
    asm volatile("cp.async.cg.shared.global [%0], [%1], 16;" :: "r"(dst), "l"(src));
}

__device__ __forceinline__ void mma8(float* d, const float4& a, const float2& b) {
    asm volatile(
        "mma.sync.aligned.m16n8k8.row.col.f32.tf32.tf32.f32 "
        "{%0,%1,%2,%3}, {%4,%5,%6,%7}, {%8,%9}, {%0,%1,%2,%3};"
        : "+f"(d[0]), "+f"(d[1]), "+f"(d[2]), "+f"(d[3])
        : "r"(__float_as_uint(a.x)), "r"(__float_as_uint(a.y)),
          "r"(__float_as_uint(a.z)), "r"(__float_as_uint(a.w)),
          "r"(__float_as_uint(b.x)), "r"(__float_as_uint(b.y)));
}

__global__ void __launch_bounds__(256) gemm_tc(
    const float* __restrict__ Ap, const float* __restrict__ Bp,
    float* __restrict__ C, int M, int N, int K)
{
    extern __shared__ float smem[];
    float* Abuf = smem;                  // [2][PSTAGE]
    float* Bbuf = smem + 2 * PSTAGE;     // [2][PSTAGE]
    const uint32_t sA = (uint32_t)__cvta_generic_to_shared(Abuf);
    const uint32_t sB = (uint32_t)__cvta_generic_to_shared(Bbuf);

    const int tid  = threadIdx.x;
    const int wid  = tid >> 5;
    const int lane = tid & 31;
    const int wm   = wid & 3;
    const int wn   = wid >> 2;
    const int g    = lane >> 2;
    const int t    = lane & 3;
    const int KT   = K / 32;

    const size_t abase = (size_t)blockIdx.y * KT * PSTAGE;
    const size_t bbase = (size_t)blockIdx.x * KT * PSTAGE;

    float d[2][8][4];
    #pragma unroll
    for (int i = 0; i < 2; i++)
        #pragma unroll
        for (int j = 0; j < 8; j++)
            #pragma unroll
            for (int r = 0; r < 4; r++) d[i][j][r] = 0.f;

    auto stage = [&](int buf, int s) {
        #pragma unroll
        for (int i = 0; i < 4; i++) {
            int idx = tid + i * 256;     // 0..1023 float4 slots
            cp16(sA + (uint32_t)(buf * PSTAGE + idx * 4) * 4,
                 Ap + abase + (size_t)s * PSTAGE + idx * 4);
            cp16(sB + (uint32_t)(buf * PSTAGE + idx * 4) * 4,
                 Bp + bbase + (size_t)s * PSTAGE + idx * 4);
        }
        asm volatile("cp.async.commit_group;" ::: "memory");
    };

    stage(0, 0);

    for (int s = 0; s < KT; s++) {
        asm volatile("cp.async.wait_group 0;" ::: "memory");
        __syncthreads();
        if (s + 1 < KT) stage((s + 1) & 1, s + 1);

        const float* At = Abuf + (s & 1) * PSTAGE;
        const float* Bt = Bbuf + (s & 1) * PSTAGE;
        #pragma unroll
        for (int ks = 0; ks < 4; ks++) {
            float4 a[2];
            float2 b[8];
            #pragma unroll
            for (int i = 0; i < 2; i++)
                a[i] = *(const float4*)&At[((ks * 8 + wm * 2 + i) * 32 + lane) * 4];
            #pragma unroll
            for (int j = 0; j < 8; j++)
                b[j] = *(const float2*)&Bt[(ks * 16 + wn * 8 + j) * 64 + lane * 2];
            #pragma unroll
            for (int i = 0; i < 2; i++)
                #pragma unroll
                for (int j = 0; j < 8; j++)
                    mma8(d[i][j], a[i], b[j]);
        }
        __syncthreads();
    }

    const int row0 = blockIdx.y * 128 + wm * 32 + g;
    const int col0 = blockIdx.x * 128 + wn * 64 + 2 * t;
    #pragma unroll
    for (int i = 0; i < 2; i++) {
        int r = row0 + i * 16;
        #pragma unroll
        for (int j = 0; j < 8; j++) {
            int c = col0 + j * 8;
            *(float2*)&C[(size_t)r * N + c]       = make_float2(d[i][j][0], d[i][j][1]);
            *(float2*)&C[(size_t)(r + 8) * N + c] = make_float2(d[i][j][2], d[i][j][3]);
        }
    }
}

// ---------------- per-head RMSNorm + RoPE -----------------------------------
__device__ __forceinline__ float block_sumsq(float v, float* red)
{
    #pragma unroll
    for (int o = 16; o; o >>= 1) v += __shfl_xor_sync(0xffffffffu, v, o);
    int lane = threadIdx.x & 31, warp = threadIdx.x >> 5;
    if (lane == 0) red[warp] = v;
    __syncthreads();
    float s = red[0];
    #pragma unroll
    for (int w = 1; w < 8; w++) s += red[w];
    return s;
}

__global__ void __launch_bounds__(256) q_prep(
    const float* __restrict__ qg, const float* __restrict__ cosb,
    const float* __restrict__ sinb, const float* __restrict__ w)
{
    __shared__ float red[8];
    int row = blockIdx.x, h = blockIdx.y, d = threadIdx.x;
    int l = row & (LL - 1), b = row >> 11;

    const float* src = qg + (size_t)row * (2 * INNER) + h * HD;
    float x  = src[d];
    float ss = block_sumsq(x * x, red);
    float rms = rsqrtf(ss * (1.0f / HD) + EPS);

    int   dp  = (d < HD/2) ? d + HD/2 : d - HD/2;
    float xp  = src[dp];
    float xn  = x  * rms * w[d];
    float xpn = xp * rms * w[dp];
    float rot = (d < HD/2) ? -xpn : xpn;
    float c = cosb[(size_t)l * HD + d];
    float s = sinb[(size_t)l * HD + d];
    g_q[(((size_t)b * NH + h) * LL + l) * HD + d] = xn * c + rot * s;
}

__global__ void __launch_bounds__(256) kv_prep(
    const float* __restrict__ ktmp, const float* __restrict__ vtmp,
    const float* __restrict__ cosb, const float* __restrict__ sinb,
    const float* __restrict__ w)
{
    __shared__ float red[8];
    int row = blockIdx.x, h = blockIdx.y, d = threadIdx.x;
    int l = row & (LL - 1), b = row >> 11;

    const float* src = ktmp + (size_t)row * (NKV * HD) + h * HD;
    float x  = src[d];
    float ss = block_sumsq(x * x, red);
    float rms = rsqrtf(ss * (1.0f / HD) + EPS);

    int   dp  = (d < HD/2) ? d + HD/2 : d - HD/2;
    float xp  = src[dp];
    float xn  = x  * rms * w[d];
    float xpn = xp * rms * w[dp];
    float rot = (d < HD/2) ? -xpn : xpn;
    float c = cosb[(size_t)l * HD + d];
    float s = sinb[(size_t)l * HD + d];
    size_t dst = (((size_t)b * NKV + h) * LL + l) * HD + d;
    g_kn[dst] = xn * c + rot * s;
    g_vt[dst] = vtmp[(size_t)row * (NKV * HD) + h * HD + d];
}

// ---------------- causal flash attention (fp32) -----------------------------
constexpr int ATK = 16;

__global__ void __launch_bounds__(256) attn_kernel()
{
    __shared__ float Ks[ATK][HD];
    __shared__ float Vs[ATK][HD];

    const int b    = blockIdx.z;
    const int h    = blockIdx.y;
    const int warp = threadIdx.x >> 5;
    const int lane = threadIdx.x & 31;
    const int qi   = blockIdx.x * 8 + warp;

    const float* qptr  = g_q  + (((size_t)b * NH  + h)       * LL + qi) * HD;
    const float* kbase = g_kn + (((size_t)b * NKV + h / GQA) * LL)      * HD;
    const float* vbase = g_vt + (((size_t)b * NKV + h / GQA) * LL)      * HD;

    float qr[8], ov[8];
    #pragma unroll
    for (int j = 0; j < 8; j++) { qr[j] = qptr[lane + 32 * j]; ov[j] = 0.f; }

    float m = -INFINITY, lsum = 0.f;
    const float scale = 0.0625f;
    const int kmax   = blockIdx.x * 8 + 7;
    const int ntiles = (kmax + ATK) / ATK;

    for (int tt = 0; tt < ntiles; tt++) {
        const int kb = tt * ATK;
        #pragma unroll
        for (int i = 0; i < 4; i++) {
            int idx = threadIdx.x + i * 256;
            int r   = idx >> 6;
            int c   = (idx & 63) * 4;
            *(float4*)&Ks[r][c] = *(const float4*)&kbase[(size_t)(kb + r) * HD + c];
            *(float4*)&Vs[r][c] = *(const float4*)&vbase[(size_t)(kb + r) * HD + c];
        }
        __syncthreads();

        const int kk_end = min(ATK, qi - kb + 1);
        for (int kk = 0; kk < kk_end; kk++) {
            float s = 0.f;
            #pragma unroll
            for (int j = 0; j < 8; j++)
                s = fmaf(qr[j], Ks[kk][lane + 32 * j], s);
            #pragma unroll
            for (int o = 16; o; o >>= 1) s += __shfl_xor_sync(0xffffffffu, s, o);
            s *= scale;

            float mnew = fmaxf(m, s);
            float corr = __expf(m - mnew);
            float p    = __expf(s - mnew);
            lsum = lsum * corr + p;
            #pragma unroll
            for (int j = 0; j < 8; j++)
                ov[j] = ov[j] * corr + p * Vs[kk][lane + 32 * j];
            m = mnew;
        }
        __syncthreads();
    }

    const float inv = 1.f / lsum;
    float* op = g_att + ((size_t)(b * LL + qi)) * INNER + h * HD;
    #pragma unroll
    for (int j = 0; j < 8; j++) op[lane + 32 * j] = ov[j] * inv;
}

// ---------------- gating: att *= silu(gate) ---------------------------------
__global__ void __launch_bounds__(256) gate_mul(const float* __restrict__ qg)
{
    size_t i   = (size_t)blockIdx.x * 256 + threadIdx.x;
    size_t row = i >> 12;
    int    col = (int)(i & 4095);
    float g  = qg[row * (2 * INNER) + INNER + col];
    float sg = g / (1.f + __expf(-g));
    g_att[i] *= sg;
}

// ---------------- launch ----------------------------------------------------
extern "C" void kernel_launch(void* const* d_in, const int* in_sizes, int n_in,
                              void* d_out, int out_size)
{
    const float* X    = (const float*)d_in[0];
    const float* cosb = (const float*)d_in[1];
    const float* sinb = (const float*)d_in[2];
    const float* Wq   = (const float*)d_in[3];
    const float* Wk   = (const float*)d_in[4];
    const float* Wv   = (const float*)d_in[5];
    const float* Wo   = (const float*)d_in[6];
    const float* qw   = (const float*)d_in[7];
    const float* kw   = (const float*)d_in[8];
    float* out = (float*)d_out;

    float *qg, *ktmp, *vtmp, *att, *xp, *attp, *wqp, *wkp, *wvp, *wop;
    cudaGetSymbolAddress((void**)&qg,   g_qg);
    cudaGetSymbolAddress((void**)&ktmp, g_ktmp);
    cudaGetSymbolAddress((void**)&vtmp, g_vtmp);
    cudaGetSymbolAddress((void**)&att,  g_att);
    cudaGetSymbolAddress((void**)&xp,   g_xp);
    cudaGetSymbolAddress((void**)&attp, g_attp);
    cudaGetSymbolAddress((void**)&wqp,  g_wqp);
    cudaGetSymbolAddress((void**)&wkp,  g_wkp);
    cudaGetSymbolAddress((void**)&wvp,  g_wvp);
    cudaGetSymbolAddress((void**)&wop,  g_wop);

    static bool attr_set = false;
    if (!attr_set) {
        cudaFuncSetAttribute(gemm_tc, cudaFuncAttributeMaxDynamicSharedMemorySize,
                             GEMM_SMEM);
        attr_set = true;
    }

    // 0) operand packing (tf32-rounded, fragment layout)
    pack_a<<<(unsigned)((size_t)ROWS * HID       / 1024), 256>>>(X,  xp,  HID);
    pack_b<<<(unsigned)((size_t)HID * 2 * INNER  /  512), 256>>>(Wq, wqp, HID, 2 * INNER);
    pack_b<<<(unsigned)((size_t)HID * NKV * HD   /  512), 256>>>(Wk, wkp, HID, NKV * HD);
    pack_b<<<(unsigned)((size_t)HID * NKV * HD   /  512), 256>>>(Wv, wvp, HID, NKV * HD);
    pack_b<<<(unsigned)((size_t)INNER * HID      /  512), 256>>>(Wo, wop, INNER, HID);

    // 1) projections
    gemm_tc<<<dim3(2 * INNER / 128, ROWS / 128), 256, GEMM_SMEM>>>(xp, wqp, qg,   ROWS, 2 * INNER, HID);
    gemm_tc<<<dim3(NKV * HD / 128,  ROWS / 128), 256, GEMM_SMEM>>>(xp, wkp, ktmp, ROWS, NKV * HD,  HID);
    gemm_tc<<<dim3(NKV * HD / 128,  ROWS / 128), 256, GEMM_SMEM>>>(xp, wvp, vtmp, ROWS, NKV * HD,  HID);

    // 2) per-head RMSNorm + RoPE (+ V transpose)
    q_prep <<<dim3(ROWS, NH),  256>>>(qg, cosb, sinb, qw);
    kv_prep<<<dim3(ROWS, NKV), 256>>>(ktmp, vtmp, cosb, sinb, kw);

    // 3) causal attention
    attn_kernel<<<dim3(LL / 8, NH, BB), 256>>>();

    // 4) gate
    gate_mul<<<(unsigned)((size_t)ROWS * INNER / 256), 256>>>(qg);

    // 5) output projection (pack att, then GEMM)
    pack_a<<<(unsigned)((size_t)ROWS * INNER / 1024), 256>>>(att, attp, INNER);
    gemm_tc<<<dim3(HID / 128, ROWS / 128), 256, GEMM_SMEM>>>(attp, wop, out, ROWS, HID, INNER);
}

// round 5
// speedup vs baseline: 1.7813x; 1.0854x over previous
#include <cuda_runtime.h>
#include <cuda_fp16.h>
#include <math.h>
#include <stdint.h>

// ---------------- problem constants ----------------
constexpr int BB     = 2;
constexpr int LL     = 2048;
constexpr int HID    = 2560;
constexpr int NH     = 16;
constexpr int NKV    = 4;
constexpr int HD     = 256;
constexpr int GQA    = NH / NKV;      // 4
constexpr int INNER  = NH * HD;       // 4096
constexpr int ROWS   = BB * LL;       // 4096
constexpr float EPS  = 1e-6f;

// ---------------- scratch (device globals) ----------------------------------
__device__ float g_qg  [(size_t)ROWS * 2 * INNER];
__device__ float g_ktmp[(size_t)ROWS * NKV * HD];
__device__ float g_vtmp[(size_t)ROWS * NKV * HD];
__device__ float g_q   [(size_t)BB * NH  * LL * HD];
__device__ float g_kn  [(size_t)BB * NKV * LL * HD];
__device__ float g_vt  [(size_t)BB * NKV * LL * HD];
__device__ float g_att [(size_t)ROWS * INNER];
// fragment-packed fp16 operands
__device__ __half g_xp  [(size_t)ROWS * HID];
__device__ __half g_attp[(size_t)ROWS * INNER];
__device__ __half g_wqp [(size_t)HID * 2 * INNER];
__device__ __half g_wkp [(size_t)HID * NKV * HD];
__device__ __half g_wvp [(size_t)HID * NKV * HD];
__device__ __half g_wop [(size_t)INNER * HID];

// ================= operand packing (fp16 fragment layout) ====================
// m16n8k16 maps (g = lane>>2, t = lane&3):
//   A regs a0..a3 (.f16x2): a0=(g,2t),(g,2t+1) a1=(g+8,2t),(g+8,2t+1)
//                           a2=(g,2t+8),(g,2t+9) a3=(g+8,2t+8),(g+8,2t+9)
//   B regs b0,b1:  b0=(k=2t,n=g),(2t+1,g)  b1=(2t+8,g),(2t+9,g)
// A region per (mt,kt): slot=(ks*8+mb)*32+lane, 8 halves/slot (uint4).
// B region per (nt,kt): slot=(ks*16+nb)*32+lane, 4 halves/slot (uint2).
__global__ void __launch_bounds__(256) pack_a(
    const float* __restrict__ A, __half* __restrict__ Ap, int K)
{
    size_t slot = (size_t)blockIdx.x * 256 + threadIdx.x;
    int lane = slot & 31, mb = (slot >> 5) & 7, ks = (slot >> 8) & 1;
    size_t rest = slot >> 9;
    int KT = K / 32;
    int kt = (int)(rest % KT), mt = (int)(rest / KT);
    int g = lane >> 2, t = lane & 3;
    int row = mt * 128 + mb * 16 + g;
    int col = kt * 32 + ks * 16 + 2 * t;
    const float* r0 = &A[(size_t)row * K + col];
    const float* r1 = &A[(size_t)(row + 8) * K + col];
    __half h[8];
    h[0] = __float2half_rn(r0[0]); h[1] = __float2half_rn(r0[1]);
    h[2] = __float2half_rn(r1[0]); h[3] = __float2half_rn(r1[1]);
    h[4] = __float2half_rn(r0[8]); h[5] = __float2half_rn(r0[9]);
    h[6] = __float2half_rn(r1[8]); h[7] = __float2half_rn(r1[9]);
    *(uint4*)&Ap[slot * 8] = *(uint4*)h;
}

__global__ void __launch_bounds__(256) pack_b(
    const float* __restrict__ Bm, __half* __restrict__ Bp, int K, int N)
{
    size_t slot = (size_t)blockIdx.x * 256 + threadIdx.x;
    int lane = slot & 31, nb = (slot >> 5) & 15, ks = (slot >> 9) & 1;
    size_t rest = slot >> 10;
    int KT = K / 32;
    int kt = (int)(rest % KT), nt = (int)(rest / KT);
    int g = lane >> 2, t = lane & 3;
    int k = kt * 32 + ks * 16 + 2 * t;
    int n = nt * 128 + nb * 8 + g;
    __half h[4];
    h[0] = __float2half_rn(Bm[(size_t)k * N + n]);
    h[1] = __float2half_rn(Bm[(size_t)(k + 1) * N + n]);
    h[2] = __float2half_rn(Bm[(size_t)(k + 8) * N + n]);
    h[3] = __float2half_rn(Bm[(size_t)(k + 9) * N + n]);
    *(uint2*)&Bp[slot * 4] = *(uint2*)h;
}

// ================= fp16 mma.sync GEMM on packed operands =====================
// CTA tile 128x128, BK=32, 8 warps (4m x 2n), warp tile 32x64.
constexpr int ASTG_B = 8192;                         // bytes per A stage
constexpr int BSTG_B = 8192;                         // bytes per B stage
constexpr int GEMM_SMEM = 2 * (ASTG_B + BSTG_B);     // 32768 B

__device__ __forceinline__ void cp16(uint32_t dst, const void* src) {
    asm volatile("cp.async.cg.shared.global [%0], [%1], 16;" :: "r"(dst), "l"(src));
}

__device__ __forceinline__ void mma16(float* d, const uint4& a, const uint2& b) {
    asm volatile(
        "mma.sync.aligned.m16n8k16.row.col.f32.f16.f16.f32 "
        "{%0,%1,%2,%3}, {%4,%5,%6,%7}, {%8,%9}, {%0,%1,%2,%3};"
        : "+f"(d[0]), "+f"(d[1]), "+f"(d[2]), "+f"(d[3])
        : "r"(a.x), "r"(a.y), "r"(a.z), "r"(a.w), "r"(b.x), "r"(b.y));
}

__global__ void __launch_bounds__(256) gemm_tc(
    const __half* __restrict__ Ap, const __half* __restrict__ Bp,
    float* __restrict__ C, int M, int N, int K)
{
    extern __shared__ char smem[];
    char* Abuf = smem;                       // [2][8192]
    char* Bbuf = smem + 2 * ASTG_B;          // [2][8192]
    const uint32_t sA = (uint32_t)__cvta_generic_to_shared(Abuf);
    const uint32_t sB = (uint32_t)__cvta_generic_to_shared(Bbuf);

    const int tid  = threadIdx.x;
    const int wid  = tid >> 5;
    const int lane = tid & 31;
    const int wm   = wid & 3;
    const int wn   = wid >> 2;
    const int g    = lane >> 2;
    const int t    = lane & 3;
    const int KT   = K / 32;

    const size_t abase = (size_t)blockIdx.y * KT * 4096;  // halves
    const size_t bbase = (size_t)blockIdx.x * KT * 4096;

    float d[2][8][4];
    #pragma unroll
    for (int i = 0; i < 2; i++)
        #pragma unroll
        for (int j = 0; j < 8; j++)
            #pragma unroll
            for (int r = 0; r < 4; r++) d[i][j][r] = 0.f;

    auto stage = [&](int buf, int s) {
        #pragma unroll
        for (int i = 0; i < 2; i++) {
            int idx = tid + i * 256;         // 0..511 16B chunks
            cp16(sA + (uint32_t)(buf * ASTG_B + idx * 16),
                 Ap + abase + (size_t)s * 4096 + idx * 8);
            cp16(sB + (uint32_t)(buf * BSTG_B + idx * 16),
                 Bp + bbase + (size_t)s * 4096 + idx * 8);
        }
        asm volatile("cp.async.commit_group;" ::: "memory");
    };

    stage(0, 0);

    for (int s = 0; s < KT; s++) {
        asm volatile("cp.async.wait_group 0;" ::: "memory");
        __syncthreads();
        if (s + 1 < KT) stage((s + 1) & 1, s + 1);

        const uint4* At = (const uint4*)(Abuf + (s & 1) * ASTG_B);
        const uint2* Bt = (const uint2*)(Bbuf + (s & 1) * BSTG_B);
        #pragma unroll
        for (int ks = 0; ks < 2; ks++) {
            uint4 a[2];
            uint2 b[8];
            #pragma unroll
            for (int i = 0; i < 2; i++)
                a[i] = At[(ks * 8 + wm * 2 + i) * 32 + lane];
            #pragma unroll
            for (int j = 0; j < 8; j++)
                b[j] = Bt[(ks * 16 + wn * 8 + j) * 32 + lane];
            #pragma unroll
            for (int i = 0; i < 2; i++)
                #pragma unroll
                for (int j = 0; j < 8; j++)
                    mma16(d[i][j], a[i], b[j]);
        }
        __syncthreads();
    }

    const int row0 = blockIdx.y * 128 + wm * 32 + g;
    const int col0 = blockIdx.x * 128 + wn * 64 + 2 * t;
    #pragma unroll
    for (int i = 0; i < 2; i++) {
        int r = row0 + i * 16;
        #pragma unroll
        for (int j = 0; j < 8; j++) {
            int c = col0 + j * 8;
            *(float2*)&C[(size_t)r * N + c]       = make_float2(d[i][j][0], d[i][j][1]);
            *(float2*)&C[(size_t)(r + 8) * N + c] = make_float2(d[i][j][2], d[i][j][3]);
        }
    }
}

// ---------------- per-head RMSNorm + RoPE -----------------------------------
__device__ __forceinline__ float block_sumsq(float v, float* red)
{
    #pragma unroll
    for (int o = 16; o; o >>= 1) v += __shfl_xor_sync(0xffffffffu, v, o);
    int lane = threadIdx.x & 31, warp = threadIdx.x >> 5;
    if (lane == 0) red[warp] = v;
    __syncthreads();
    float s = red[0];
    #pragma unroll
    for (int w = 1; w < 8; w++) s += red[w];
    return s;
}

__global__ void __launch_bounds__(256) q_prep(
    const float* __restrict__ qg, const float* __restrict__ cosb,
    const float* __restrict__ sinb, const float* __restrict__ w)
{
    __shared__ float red[8];
    int row = blockIdx.x, h = blockIdx.y, d = threadIdx.x;
    int l = row & (LL - 1), b = row >> 11;

    const float* src = qg + (size_t)row * (2 * INNER) + h * HD;
    float x  = src[d];
    float ss = block_sumsq(x * x, red);
    float rms = rsqrtf(ss * (1.0f / HD) + EPS);

    int   dp  = (d < HD/2) ? d + HD/2 : d - HD/2;
    float xp  = src[dp];
    float xn  = x  * rms * w[d];
    float xpn = xp * rms * w[dp];
    float rot = (d < HD/2) ? -xpn : xpn;
    float c = cosb[(size_t)l * HD + d];
    float s = sinb[(size_t)l * HD + d];
    g_q[(((size_t)b * NH + h) * LL + l) * HD + d] = xn * c + rot * s;
}

__global__ void __launch_bounds__(256) kv_prep(
    const float* __restrict__ ktmp, const float* __restrict__ vtmp,
    const float* __restrict__ cosb, const float* __restrict__ sinb,
    const float* __restrict__ w)
{
    __shared__ float red[8];
    int row = blockIdx.x, h = blockIdx.y, d = threadIdx.x;
    int l = row & (LL - 1), b = row >> 11;

    const float* src = ktmp + (size_t)row * (NKV * HD) + h * HD;
    float x  = src[d];
    float ss = block_sumsq(x * x, red);
    float rms = rsqrtf(ss * (1.0f / HD) + EPS);

    int   dp  = (d < HD/2) ? d + HD/2 : d - HD/2;
    float xp  = src[dp];
    float xn  = x  * rms * w[d];
    float xpn = xp * rms * w[dp];
    float rot = (d < HD/2) ? -xpn : xpn;
    float c = cosb[(size_t)l * HD + d];
    float s = sinb[(size_t)l * HD + d];
    size_t dst = (((size_t)b * NKV + h) * LL + l) * HD + d;
    g_kn[dst] = xn * c + rot * s;
    g_vt[dst] = vtmp[(size_t)row * (NKV * HD) + h * HD + d];
}

// ---------------- causal flash attention (fp32) -----------------------------
constexpr int ATK = 16;

__global__ void __launch_bounds__(256) attn_kernel()
{
    __shared__ float Ks[ATK][HD];
    __shared__ float Vs[ATK][HD];

    const int b    = blockIdx.z;
    const int h    = blockIdx.y;
    const int warp = threadIdx.x >> 5;
    const int lane = threadIdx.x & 31;
    const int qi   = blockIdx.x * 8 + warp;

    const float* qptr  = g_q  + (((size_t)b * NH  + h)       * LL + qi) * HD;
    const float* kbase = g_kn + (((size_t)b * NKV + h / GQA) * LL)      * HD;
    const float* vbase = g_vt + (((size_t)b * NKV + h / GQA) * LL)      * HD;

    float qr[8], ov[8];
    #pragma unroll
    for (int j = 0; j < 8; j++) { qr[j] = qptr[lane + 32 * j]; ov[j] = 0.f; }

    float m = -INFINITY, lsum = 0.f;
    const float scale = 0.0625f;
    const int kmax   = blockIdx.x * 8 + 7;
    const int ntiles = (kmax + ATK) / ATK;

    for (int tt = 0; tt < ntiles; tt++) {
        const int kb = tt * ATK;
        #pragma unroll
        for (int i = 0; i < 4; i++) {
            int idx = threadIdx.x + i * 256;
            int r   = idx >> 6;
            int c   = (idx & 63) * 4;
            *(float4*)&Ks[r][c] = *(const float4*)&kbase[(size_t)(kb + r) * HD + c];
            *(float4*)&Vs[r][c] = *(const float4*)&vbase[(size_t)(kb + r) * HD + c];
        }
        __syncthreads();

        const int kk_end = min(ATK, qi - kb + 1);
        for (int kk = 0; kk < kk_end; kk++) {
            float s = 0.f;
            #pragma unroll
            for (int j = 0; j < 8; j++)
                s = fmaf(qr[j], Ks[kk][lane + 32 * j], s);
            #pragma unroll
            for (int o = 16; o; o >>= 1) s += __shfl_xor_sync(0xffffffffu, s, o);
            s *= scale;

            float mnew = fmaxf(m, s);
            float corr = __expf(m - mnew);
            float p    = __expf(s - mnew);
            lsum = lsum * corr + p;
            #pragma unroll
            for (int j = 0; j < 8; j++)
                ov[j] = ov[j] * corr + p * Vs[kk][lane + 32 * j];
            m = mnew;
        }
        __syncthreads();
    }

    const float inv = 1.f / lsum;
    float* op = g_att + ((size_t)(b * LL + qi)) * INNER + h * HD;
    #pragma unroll
    for (int j = 0; j < 8; j++) op[lane + 32 * j] = ov[j] * inv;
}

// ---------------- gating: att *= silu(gate) ---------------------------------
__global__ void __launch_bounds__(256) gate_mul(const float* __restrict__ qg)
{
    size_t i   = (size_t)blockIdx.x * 256 + threadIdx.x;
    size_t row = i >> 12;
    int    col = (int)(i & 4095);
    float g  = qg[row * (2 * INNER) + INNER + col];
    float sg = g / (1.f + __expf(-g));
    g_att[i] *= sg;
}

// ---------------- launch ----------------------------------------------------
extern "C" void kernel_launch(void* const* d_in, const int* in_sizes, int n_in,
                              void* d_out, int out_size)
{
    const float* X    = (const float*)d_in[0];
    const float* cosb = (const float*)d_in[1];
    const float* sinb = (const float*)d_in[2];
    const float* Wq   = (const float*)d_in[3];
    const float* Wk   = (const float*)d_in[4];
    const float* Wv   = (const float*)d_in[5];
    const float* Wo   = (const float*)d_in[6];
    const float* qw   = (const float*)d_in[7];
    const float* kw   = (const float*)d_in[8];
    float* out = (float*)d_out;

    float *qg, *ktmp, *vtmp, *att;
    __half *xp, *attp, *wqp, *wkp, *wvp, *wop;
    cudaGetSymbolAddress((void**)&qg,   g_qg);
    cudaGetSymbolAddress((void**)&ktmp, g_ktmp);
    cudaGetSymbolAddress((void**)&vtmp, g_vtmp);
    cudaGetSymbolAddress((void**)&att,  g_att);
    cudaGetSymbolAddress((void**)&xp,   g_xp);
    cudaGetSymbolAddress((void**)&attp, g_attp);
    cudaGetSymbolAddress((void**)&wqp,  g_wqp);
    cudaGetSymbolAddress((void**)&wkp,  g_wkp);
    cudaGetSymbolAddress((void**)&wvp,  g_wvp);
    cudaGetSymbolAddress((void**)&wop,  g_wop);

    static bool attr_set = false;
    if (!attr_set) {
        cudaFuncSetAttribute(gemm_tc, cudaFuncAttributeMaxDynamicSharedMemorySize,
                             GEMM_SMEM);
        attr_set = true;
    }

    // 0) operand packing (fp16, fragment layout)
    pack_a<<<(unsigned)((size_t)ROWS * HID      / 2048), 256>>>(X,  xp,  HID);
    pack_b<<<(unsigned)((size_t)HID * 2 * INNER / 1024), 256>>>(Wq, wqp, HID, 2 * INNER);
    pack_b<<<(unsigned)((size_t)HID * NKV * HD  / 1024), 256>>>(Wk, wkp, HID, NKV * HD);
    pack_b<<<(unsigned)((size_t)HID * NKV * HD  / 1024), 256>>>(Wv, wvp, HID, NKV * HD);
    pack_b<<<(unsigned)((size_t)INNER * HID     / 1024), 256>>>(Wo, wop, INNER, HID);

    // 1) projections
    gemm_tc<<<dim3(2 * INNER / 128, ROWS / 128), 256, GEMM_SMEM>>>(xp, wqp, qg,   ROWS, 2 * INNER, HID);
    gemm_tc<<<dim3(NKV * HD / 128,  ROWS / 128), 256, GEMM_SMEM>>>(xp, wkp, ktmp, ROWS, NKV * HD,  HID);
    gemm_tc<<<dim3(NKV * HD / 128,  ROWS / 128), 256, GEMM_SMEM>>>(xp, wvp, vtmp, ROWS, NKV * HD,  HID);

    // 2) per-head RMSNorm + RoPE (+ V transpose)
    q_prep <<<dim3(ROWS, NH),  256>>>(qg, cosb, sinb, qw);
    kv_prep<<<dim3(ROWS, NKV), 256>>>(ktmp, vtmp, cosb, sinb, kw);

    // 3) causal attention
    attn_kernel<<<dim3(LL / 8, NH, BB), 256>>>();

    // 4) gate
    gate_mul<<<(unsigned)((size_t)ROWS * INNER / 256), 256>>>(qg);

    // 5) output projection (pack att, then GEMM)
    pack_a<<<(unsigned)((size_t)ROWS * INNER / 2048), 256>>>(att, attp, INNER);
    gemm_tc<<<dim3(HID / 128, ROWS / 128), 256, GEMM_SMEM>>>(attp, wop, out, ROWS, HID, INNER);
}

// round 6
// speedup vs baseline: 1.7987x; 1.0098x over previous
#include <cuda_runtime.h>
#include <cuda_fp16.h>
#include <math.h>
#include <stdint.h>

// ---------------- problem constants ----------------
constexpr int BB     = 2;
constexpr int LL     = 2048;
constexpr int HID    = 2560;
constexpr int NH     = 16;
constexpr int NKV    = 4;
constexpr int HD     = 256;
constexpr int GQA    = NH / NKV;      // 4
constexpr int INNER  = NH * HD;       // 4096
constexpr int ROWS   = BB * LL;       // 4096
constexpr int NQKV   = 2 * INNER + 2 * NKV * HD;   // 10240 fused proj cols
constexpr float EPS  = 1e-6f;

// ---------------- scratch (device globals) ----------------------------------
__device__ float g_qkv [(size_t)ROWS * NQKV];        // fused q|gate|k|v
__device__ float g_q   [(size_t)BB * NH  * LL * HD];
__device__ float g_kn  [(size_t)BB * NKV * LL * HD];
__device__ float g_vt  [(size_t)BB * NKV * LL * HD];
__device__ float g_att [(size_t)ROWS * INNER];
// fragment-packed fp16 operands
__device__ __half g_xp   [(size_t)ROWS * HID];
__device__ __half g_attp [(size_t)ROWS * INNER];
__device__ __half g_wqkvp[(size_t)HID * NQKV];       // fused packed B
__device__ __half g_wop  [(size_t)INNER * HID];

// ================= operand packing (fp16 fragment layout) ====================
// m16n8k16 maps (g = lane>>2, t = lane&3):
//   A regs a0..a3 (.f16x2): a0=(g,2t),(g,2t+1) a1=(g+8,2t),(g+8,2t+1)
//                           a2=(g,2t+8),(g,2t+9) a3=(g+8,2t+8),(g+8,2t+9)
//   B regs b0,b1:  b0=(k=2t,n=g),(2t+1,g)  b1=(2t+8,g),(2t+9,g)
// A region per (mt,kt): slot=(ks*8+mb)*32+lane, 8 halves/slot (uint4).
// B region per (nt,kt): slot=(ks*16+nb)*32+lane, 4 halves/slot (uint2).
__global__ void __launch_bounds__(256) pack_a(
    const float* __restrict__ A, __half* __restrict__ Ap, int K)
{
    size_t slot = (size_t)blockIdx.x * 256 + threadIdx.x;
    int lane = slot & 31, mb = (slot >> 5) & 7, ks = (slot >> 8) & 1;
    size_t rest = slot >> 9;
    int KT = K / 32;
    int kt = (int)(rest % KT), mt = (int)(rest / KT);
    int g = lane >> 2, t = lane & 3;
    int row = mt * 128 + mb * 16 + g;
    int col = kt * 32 + ks * 16 + 2 * t;
    const float* r0 = &A[(size_t)row * K + col];
    const float* r1 = &A[(size_t)(row + 8) * K + col];
    __half h[8];
    h[0] = __float2half_rn(r0[0]); h[1] = __float2half_rn(r0[1]);
    h[2] = __float2half_rn(r1[0]); h[3] = __float2half_rn(r1[1]);
    h[4] = __float2half_rn(r0[8]); h[5] = __float2half_rn(r0[9]);
    h[6] = __float2half_rn(r1[8]); h[7] = __float2half_rn(r1[9]);
    *(uint4*)&Ap[slot * 8] = *(uint4*)h;
}

__global__ void __launch_bounds__(256) pack_b(
    const float* __restrict__ Bm, __half* __restrict__ Bp, int K, int N)
{
    size_t slot = (size_t)blockIdx.x * 256 + threadIdx.x;
    int lane = slot & 31, nb = (slot >> 5) & 15, ks = (slot >> 9) & 1;
    size_t rest = slot >> 10;
    int KT = K / 32;
    int kt = (int)(rest % KT), nt = (int)(rest / KT);
    int g = lane >> 2, t = lane & 3;
    int k = kt * 32 + ks * 16 + 2 * t;
    int n = nt * 128 + nb * 8 + g;
    __half h[4];
    h[0] = __float2half_rn(Bm[(size_t)k * N + n]);
    h[1] = __float2half_rn(Bm[(size_t)(k + 1) * N + n]);
    h[2] = __float2half_rn(Bm[(size_t)(k + 8) * N + n]);
    h[3] = __float2half_rn(Bm[(size_t)(k + 9) * N + n]);
    *(uint2*)&Bp[slot * 4] = *(uint2*)h;
}

// ================= fp16 mma.sync GEMM, 4-stage cp.async pipeline =============
// CTA tile 128x128, BK=32, 8 warps (4m x 2n), warp tile 32x64.
constexpr int NSTG   = 4;
constexpr int ASTG_B = 8192;                          // bytes per A stage
constexpr int BSTG_B = 8192;                          // bytes per B stage
constexpr int GEMM_SMEM = NSTG * (ASTG_B + BSTG_B);   // 65536 B

__device__ __forceinline__ void cp16(uint32_t dst, const void* src) {
    asm volatile("cp.async.cg.shared.global [%0], [%1], 16;" :: "r"(dst), "l"(src));
}

__device__ __forceinline__ void mma16(float* d, const uint4& a, const uint2& b) {
    asm volatile(
        "mma.sync.aligned.m16n8k16.row.col.f32.f16.f16.f32 "
        "{%0,%1,%2,%3}, {%4,%5,%6,%7}, {%8,%9}, {%0,%1,%2,%3};"
        : "+f"(d[0]), "+f"(d[1]), "+f"(d[2]), "+f"(d[3])
        : "r"(a.x), "r"(a.y), "r"(a.z), "r"(a.w), "r"(b.x), "r"(b.y));
}

__global__ void __launch_bounds__(256) gemm_tc(
    const __half* __restrict__ Ap, const __half* __restrict__ Bp,
    float* __restrict__ C, int K, int ldc)
{
    extern __shared__ char smem[];
    char* Abuf = smem;                        // [NSTG][8192]
    char* Bbuf = smem + NSTG * ASTG_B;        // [NSTG][8192]
    const uint32_t sA = (uint32_t)__cvta_generic_to_shared(Abuf);
    const uint32_t sB = (uint32_t)__cvta_generic_to_shared(Bbuf);

    const int tid  = threadIdx.x;
    const int wid  = tid >> 5;
    const int lane = tid & 31;
    const int wm   = wid & 3;
    const int wn   = wid >> 2;
    const int g    = lane >> 2;
    const int t    = lane & 3;
    const int KT   = K / 32;

    const size_t abase = (size_t)blockIdx.y * KT * 4096;  // halves
    const size_t bbase = (size_t)blockIdx.x * KT * 4096;

    float d[2][8][4];
    #pragma unroll
    for (int i = 0; i < 2; i++)
        #pragma unroll
        for (int j = 0; j < 8; j++)
            #pragma unroll
            for (int r = 0; r < 4; r++) d[i][j][r] = 0.f;

    auto stage = [&](int buf, int s) {
        #pragma unroll
        for (int i = 0; i < 2; i++) {
            int idx = tid + i * 256;          // 0..511 16B chunks
            cp16(sA + (uint32_t)(buf * ASTG_B + idx * 16),
                 Ap + abase + (size_t)s * 4096 + idx * 8);
            cp16(sB + (uint32_t)(buf * BSTG_B + idx * 16),
                 Bp + bbase + (size_t)s * 4096 + idx * 8);
        }
        asm volatile("cp.async.commit_group;" ::: "memory");
    };

    // prologue: 3 stages in flight
    stage(0, 0);
    stage(1, 1);
    stage(2, 2);

    for (int s = 0; s < KT; s++) {
        asm volatile("cp.async.wait_group 2;" ::: "memory");
        __syncthreads();
        if (s + 3 < KT) stage((s + 3) & (NSTG - 1), s + 3);
        else asm volatile("cp.async.commit_group;" ::: "memory");  // keep FIFO count

        const uint4* At = (const uint4*)(Abuf + (s & (NSTG - 1)) * ASTG_B);
        const uint2* Bt = (const uint2*)(Bbuf + (s & (NSTG - 1)) * BSTG_B);
        #pragma unroll
        for (int ks = 0; ks < 2; ks++) {
            uint4 a[2];
            uint2 b[8];
            #pragma unroll
            for (int i = 0; i < 2; i++)
                a[i] = At[(ks * 8 + wm * 2 + i) * 32 + lane];
            #pragma unroll
            for (int j = 0; j < 8; j++)
                b[j] = Bt[(ks * 16 + wn * 8 + j) * 32 + lane];
            #pragma unroll
            for (int i = 0; i < 2; i++)
                #pragma unroll
                for (int j = 0; j < 8; j++)
                    mma16(d[i][j], a[i], b[j]);
        }
    }

    const int row0 = blockIdx.y * 128 + wm * 32 + g;
    const int col0 = blockIdx.x * 128 + wn * 64 + 2 * t;
    #pragma unroll
    for (int i = 0; i < 2; i++) {
        int r = row0 + i * 16;
        #pragma unroll
        for (int j = 0; j < 8; j++) {
            int c = col0 + j * 8;
            *(float2*)&C[(size_t)r * ldc + c]       = make_float2(d[i][j][0], d[i][j][1]);
            *(float2*)&C[(size_t)(r + 8) * ldc + c] = make_float2(d[i][j][2], d[i][j][3]);
        }
    }
}

// ---------------- per-head RMSNorm + RoPE -----------------------------------
__device__ __forceinline__ float block_sumsq(float v, float* red)
{
    #pragma unroll
    for (int o = 16; o; o >>= 1) v += __shfl_xor_sync(0xffffffffu, v, o);
    int lane = threadIdx.x & 31, warp = threadIdx.x >> 5;
    if (lane == 0) red[warp] = v;
    __syncthreads();
    float s = red[0];
    #pragma unroll
    for (int w = 1; w < 8; w++) s += red[w];
    return s;
}

__global__ void __launch_bounds__(256) q_prep(
    const float* __restrict__ qkv, const float* __restrict__ cosb,
    const float* __restrict__ sinb, const float* __restrict__ w)
{
    __shared__ float red[8];
    int row = blockIdx.x, h = blockIdx.y, d = threadIdx.x;
    int l = row & (LL - 1), b = row >> 11;

    const float* src = qkv + (size_t)row * NQKV + h * HD;
    float x  = src[d];
    float ss = block_sumsq(x * x, red);
    float rms = rsqrtf(ss * (1.0f / HD) + EPS);

    int   dp  = (d < HD/2) ? d + HD/2 : d - HD/2;
    float xp  = src[dp];
    float xn  = x  * rms * w[d];
    float xpn = xp * rms * w[dp];
    float rot = (d < HD/2) ? -xpn : xpn;
    float c = cosb[(size_t)l * HD + d];
    float s = sinb[(size_t)l * HD + d];
    g_q[(((size_t)b * NH + h) * LL + l) * HD + d] = xn * c + rot * s;
}

__global__ void __launch_bounds__(256) kv_prep(
    const float* __restrict__ qkv, const float* __restrict__ cosb,
    const float* __restrict__ sinb, const float* __restrict__ w)
{
    __shared__ float red[8];
    int row = blockIdx.x, h = blockIdx.y, d = threadIdx.x;
    int l = row & (LL - 1), b = row >> 11;

    const float* src = qkv + (size_t)row * NQKV + 2 * INNER + h * HD;
    float x  = src[d];
    float ss = block_sumsq(x * x, red);
    float rms = rsqrtf(ss * (1.0f / HD) + EPS);

    int   dp  = (d < HD/2) ? d + HD/2 : d - HD/2;
    float xp  = src[dp];
    float xn  = x  * rms * w[d];
    float xpn = xp * rms * w[dp];
    float rot = (d < HD/2) ? -xpn : xpn;
    float c = cosb[(size_t)l * HD + d];
    float s = sinb[(size_t)l * HD + d];
    size_t dst = (((size_t)b * NKV + h) * LL + l) * HD + d;
    g_kn[dst] = xn * c + rot * s;
    g_vt[dst] = qkv[(size_t)row * NQKV + 2 * INNER + NKV * HD + h * HD + d];
}

// ---------------- causal flash attention (fp32) -----------------------------
constexpr int ATK = 16;

__global__ void __launch_bounds__(256) attn_kernel()
{
    __shared__ float Ks[ATK][HD];
    __shared__ float Vs[ATK][HD];

    const int b    = blockIdx.z;
    const int h    = blockIdx.y;
    const int warp = threadIdx.x >> 5;
    const int lane = threadIdx.x & 31;
    const int qi   = blockIdx.x * 8 + warp;

    const float* qptr  = g_q  + (((size_t)b * NH  + h)       * LL + qi) * HD;
    const float* kbase = g_kn + (((size_t)b * NKV + h / GQA) * LL)      * HD;
    const float* vbase = g_vt + (((size_t)b * NKV + h / GQA) * LL)      * HD;

    float qr[8], ov[8];
    #pragma unroll
    for (int j = 0; j < 8; j++) { qr[j] = qptr[lane + 32 * j]; ov[j] = 0.f; }

    float m = -INFINITY, lsum = 0.f;
    const float scale = 0.0625f;
    const int kmax   = blockIdx.x * 8 + 7;
    const int ntiles = (kmax + ATK) / ATK;

    for (int tt = 0; tt < ntiles; tt++) {
        const int kb = tt * ATK;
        #pragma unroll
        for (int i = 0; i < 4; i++) {
            int idx = threadIdx.x + i * 256;
            int r   = idx >> 6;
            int c   = (idx & 63) * 4;
            *(float4*)&Ks[r][c] = *(const float4*)&kbase[(size_t)(kb + r) * HD + c];
            *(float4*)&Vs[r][c] = *(const float4*)&vbase[(size_t)(kb + r) * HD + c];
        }
        __syncthreads();

        const int kk_end = min(ATK, qi - kb + 1);
        for (int kk = 0; kk < kk_end; kk++) {
            float s = 0.f;
            #pragma unroll
            for (int j = 0; j < 8; j++)
                s = fmaf(qr[j], Ks[kk][lane + 32 * j], s);
            #pragma unroll
            for (int o = 16; o; o >>= 1) s += __shfl_xor_sync(0xffffffffu, s, o);
            s *= scale;

            float mnew = fmaxf(m, s);
            float corr = __expf(m - mnew);
            float p    = __expf(s - mnew);
            lsum = lsum * corr + p;
            #pragma unroll
            for (int j = 0; j < 8; j++)
                ov[j] = ov[j] * corr + p * Vs[kk][lane + 32 * j];
            m = mnew;
        }
        __syncthreads();
    }

    const float inv = 1.f / lsum;
    float* op = g_att + ((size_t)(b * LL + qi)) * INNER + h * HD;
    #pragma unroll
    for (int j = 0; j < 8; j++) op[lane + 32 * j] = ov[j] * inv;
}

// ---------------- gating: att *= silu(gate) ---------------------------------
__global__ void __launch_bounds__(256) gate_mul(const float* __restrict__ qkv)
{
    size_t i   = (size_t)blockIdx.x * 256 + threadIdx.x;
    size_t row = i >> 12;
    int    col = (int)(i & 4095);
    float g  = qkv[row * NQKV + INNER + col];
    float sg = g / (1.f + __expf(-g));
    g_att[i] *= sg;
}

// ---------------- launch ----------------------------------------------------
extern "C" void kernel_launch(void* const* d_in, const int* in_sizes, int n_in,
                              void* d_out, int out_size)
{
    const float* X    = (const float*)d_in[0];
    const float* cosb = (const float*)d_in[1];
    const float* sinb = (const float*)d_in[2];
    const float* Wq   = (const float*)d_in[3];
    const float* Wk   = (const float*)d_in[4];
    const float* Wv   = (const float*)d_in[5];
    const float* Wo   = (const float*)d_in[6];
    const float* qw   = (const float*)d_in[7];
    const float* kw   = (const float*)d_in[8];
    float* out = (float*)d_out;

    float *qkv, *att;
    __half *xp, *attp, *wqkvp, *wop;
    cudaGetSymbolAddress((void**)&qkv,   g_qkv);
    cudaGetSymbolAddress((void**)&att,   g_att);
    cudaGetSymbolAddress((void**)&xp,    g_xp);
    cudaGetSymbolAddress((void**)&attp,  g_attp);
    cudaGetSymbolAddress((void**)&wqkvp, g_wqkvp);
    cudaGetSymbolAddress((void**)&wop,   g_wop);

    static bool attr_set = false;
    if (!attr_set) {
        cudaFuncSetAttribute(gemm_tc, cudaFuncAttributeMaxDynamicSharedMemorySize,
                             GEMM_SMEM);
        attr_set = true;
    }

    constexpr int KTH = HID / 32;   // 80 k-tiles for projections
    // packed-B region offsets (halves): nt-major, KT*4096 halves per n-tile
    __half* wq_dst = wqkvp;
    __half* wk_dst = wqkvp + (size_t)(2 * INNER / 128) * KTH * 4096;
    __half* wv_dst = wk_dst + (size_t)(NKV * HD / 128) * KTH * 4096;

    // 0) operand packing (fp16, fragment layout)
    pack_a<<<(unsigned)((size_t)ROWS * HID      / 2048), 256>>>(X,  xp,  HID);
    pack_b<<<(unsigned)((size_t)HID * 2 * INNER / 1024), 256>>>(Wq, wq_dst, HID, 2 * INNER);
    pack_b<<<(unsigned)((size_t)HID * NKV * HD  / 1024), 256>>>(Wk, wk_dst, HID, NKV * HD);
    pack_b<<<(unsigned)((size_t)HID * NKV * HD  / 1024), 256>>>(Wv, wv_dst, HID, NKV * HD);
    pack_b<<<(unsigned)((size_t)INNER * HID     / 1024), 256>>>(Wo, wop, INNER, HID);

    // 1) fused QKV projection: [4096, 10240]
    gemm_tc<<<dim3(NQKV / 128, ROWS / 128), 256, GEMM_SMEM>>>(xp, wqkvp, qkv, HID, NQKV);

    // 2) per-head RMSNorm + RoPE (+ V transpose)
    q_prep <<<dim3(ROWS, NH),  256>>>(qkv, cosb, sinb, qw);
    kv_prep<<<dim3(ROWS, NKV), 256>>>(qkv, cosb, sinb, kw);

    // 3) causal attention
    attn_kernel<<<dim3(LL / 8, NH, BB), 256>>>();

    // 4) gate
    gate_mul<<<(unsigned)((size_t)ROWS * INNER / 256), 256>>>(qkv);

    // 5) output projection
    pack_a<<<(unsigned)((size_t)ROWS * INNER / 2048), 256>>>(att, attp, INNER);
    gemm_tc<<<dim3(HID / 128, ROWS / 128), 256, GEMM_SMEM>>>(attp, wop, out, INNER, HID);
}

// round 7
// speedup vs baseline: 7.6959x; 4.2785x over previous
#include <cuda_runtime.h>
#include <cuda_fp16.h>
#include <math.h>
#include <stdint.h>

// ---------------- problem constants ----------------
constexpr int BB     = 2;
constexpr int LL     = 2048;
constexpr int HID    = 2560;
constexpr int NH     = 16;
constexpr int NKV    = 4;
constexpr int HD     = 256;
constexpr int GQA    = NH / NKV;      // 4
constexpr int INNER  = NH * HD;       // 4096
constexpr int ROWS   = BB * LL;       // 4096
constexpr int NQKV   = 2 * INNER + 2 * NKV * HD;   // 10240
constexpr float EPS  = 1e-6f;

// ---------------- scratch (device globals) ----------------------------------
__device__ float  g_qkv [(size_t)ROWS * NQKV];       // fused q|gate|k|v
__device__ float  g_att [(size_t)ROWS * INNER];
__device__ __half g_q16 [(size_t)BB * NH  * LL * HD];
__device__ __half g_k16 [(size_t)BB * NKV * LL * HD];
__device__ __half g_v16 [(size_t)BB * NKV * LL * HD];
// fragment-packed fp16 GEMM operands
__device__ __half g_xp   [(size_t)ROWS * HID];
__device__ __half g_attp [(size_t)ROWS * INNER];
__device__ __half g_wqkvp[(size_t)HID * NQKV];
__device__ __half g_wop  [(size_t)INNER * HID];

// ================= shared mma helper =========================================
__device__ __forceinline__ void mma16(float* d, uint32_t a0, uint32_t a1,
                                      uint32_t a2, uint32_t a3,
                                      uint32_t b0, uint32_t b1) {
    asm volatile(
        "mma.sync.aligned.m16n8k16.row.col.f32.f16.f16.f32 "
        "{%0,%1,%2,%3}, {%4,%5,%6,%7}, {%8,%9}, {%0,%1,%2,%3};"
        : "+f"(d[0]), "+f"(d[1]), "+f"(d[2]), "+f"(d[3])
        : "r"(a0), "r"(a1), "r"(a2), "r"(a3), "r"(b0), "r"(b1));
}

__device__ __forceinline__ float ex2f(float x) {
    float r; asm("ex2.approx.f32 %0, %1;" : "=f"(r) : "f"(x));
    return r;
}

// ================= operand packing (fp16 fragment layout) ====================
__global__ void __launch_bounds__(256) pack_a(
    const float* __restrict__ A, __half* __restrict__ Ap, int K)
{
    size_t slot = (size_t)blockIdx.x * 256 + threadIdx.x;
    int lane = slot & 31, mb = (slot >> 5) & 7, ks = (slot >> 8) & 1;
    size_t rest = slot >> 9;
    int KT = K / 32;
    int kt = (int)(rest % KT), mt = (int)(rest / KT);
    int g = lane >> 2, t = lane & 3;
    int row = mt * 128 + mb * 16 + g;
    int col = kt * 32 + ks * 16 + 2 * t;
    const float* r0 = &A[(size_t)row * K + col];
    const float* r1 = &A[(size_t)(row + 8) * K + col];
    __half h[8];
    h[0] = __float2half_rn(r0[0]); h[1] = __float2half_rn(r0[1]);
    h[2] = __float2half_rn(r1[0]); h[3] = __float2half_rn(r1[1]);
    h[4] = __float2half_rn(r0[8]); h[5] = __float2half_rn(r0[9]);
    h[6] = __float2half_rn(r1[8]); h[7] = __float2half_rn(r1[9]);
    *(uint4*)&Ap[slot * 8] = *(uint4*)h;
}

__global__ void __launch_bounds__(256) pack_b(
    const float* __restrict__ Bm, __half* __restrict__ Bp, int K, int N)
{
    size_t slot = (size_t)blockIdx.x * 256 + threadIdx.x;
    int lane = slot & 31, nb = (slot >> 5) & 15, ks = (slot >> 9) & 1;
    size_t rest = slot >> 10;
    int KT = K / 32;
    int kt = (int)(rest % KT), nt = (int)(rest / KT);
    int g = lane >> 2, t = lane & 3;
    int k = kt * 32 + ks * 16 + 2 * t;
    int n = nt * 128 + nb * 8 + g;
    __half h[4];
    h[0] = __float2half_rn(Bm[(size_t)k * N + n]);
    h[1] = __float2half_rn(Bm[(size_t)(k + 1) * N + n]);
    h[2] = __float2half_rn(Bm[(size_t)(k + 8) * N + n]);
    h[3] = __float2half_rn(Bm[(size_t)(k + 9) * N + n]);
    *(uint2*)&Bp[slot * 4] = *(uint2*)h;
}

// ================= fp16 mma GEMM, 4-stage cp.async pipeline ==================
constexpr int NSTG   = 4;
constexpr int ASTG_B = 8192;
constexpr int BSTG_B = 8192;
constexpr int GEMM_SMEM = NSTG * (ASTG_B + BSTG_B);   // 65536

__device__ __forceinline__ void cp16(uint32_t dst, const void* src) {
    asm volatile("cp.async.cg.shared.global [%0], [%1], 16;" :: "r"(dst), "l"(src));
}

__global__ void __launch_bounds__(256) gemm_tc(
    const __half* __restrict__ Ap, const __half* __restrict__ Bp,
    float* __restrict__ C, int K, int ldc)
{
    extern __shared__ char smem[];
    char* Abuf = smem;
    char* Bbuf = smem + NSTG * ASTG_B;
    const uint32_t sA = (uint32_t)__cvta_generic_to_shared(Abuf);
    const uint32_t sB = (uint32_t)__cvta_generic_to_shared(Bbuf);

    const int tid  = threadIdx.x;
    const int wid  = tid >> 5;
    const int lane = tid & 31;
    const int wm   = wid & 3;
    const int wn   = wid >> 2;
    const int g    = lane >> 2;
    const int t    = lane & 3;
    const int KT   = K / 32;

    const size_t abase = (size_t)blockIdx.y * KT * 4096;
    const size_t bbase = (size_t)blockIdx.x * KT * 4096;

    float d[2][8][4];
    #pragma unroll
    for (int i = 0; i < 2; i++)
        #pragma unroll
        for (int j = 0; j < 8; j++)
            #pragma unroll
            for (int r = 0; r < 4; r++) d[i][j][r] = 0.f;

    auto stage = [&](int buf, int s) {
        #pragma unroll
        for (int i = 0; i < 2; i++) {
            int idx = tid + i * 256;
            cp16(sA + (uint32_t)(buf * ASTG_B + idx * 16),
                 Ap + abase + (size_t)s * 4096 + idx * 8);
            cp16(sB + (uint32_t)(buf * BSTG_B + idx * 16),
                 Bp + bbase + (size_t)s * 4096 + idx * 8);
        }
        asm volatile("cp.async.commit_group;" ::: "memory");
    };

    stage(0, 0);
    stage(1, 1);
    stage(2, 2);

    for (int s = 0; s < KT; s++) {
        asm volatile("cp.async.wait_group 2;" ::: "memory");
        __syncthreads();
        if (s + 3 < KT) stage((s + 3) & (NSTG - 1), s + 3);
        else asm volatile("cp.async.commit_group;" ::: "memory");

        const uint4* At = (const uint4*)(Abuf + (s & (NSTG - 1)) * ASTG_B);
        const uint2* Bt = (const uint2*)(Bbuf + (s & (NSTG - 1)) * BSTG_B);
        #pragma unroll
        for (int ks = 0; ks < 2; ks++) {
            uint4 a[2];
            uint2 b[8];
            #pragma unroll
            for (int i = 0; i < 2; i++)
                a[i] = At[(ks * 8 + wm * 2 + i) * 32 + lane];
            #pragma unroll
            for (int j = 0; j < 8; j++)
                b[j] = Bt[(ks * 16 + wn * 8 + j) * 32 + lane];
            #pragma unroll
            for (int i = 0; i < 2; i++)
                #pragma unroll
                for (int j = 0; j < 8; j++)
                    mma16(d[i][j], a[i].x, a[i].y, a[i].z, a[i].w, b[j].x, b[j].y);
        }
    }

    const int row0 = blockIdx.y * 128 + wm * 32 + g;
    const int col0 = blockIdx.x * 128 + wn * 64 + 2 * t;
    #pragma unroll
    for (int i = 0; i < 2; i++) {
        int r = row0 + i * 16;
        #pragma unroll
        for (int j = 0; j < 8; j++) {
            int c = col0 + j * 8;
            *(float2*)&C[(size_t)r * ldc + c]       = make_float2(d[i][j][0], d[i][j][1]);
            *(float2*)&C[(size_t)(r + 8) * ldc + c] = make_float2(d[i][j][2], d[i][j][3]);
        }
    }
}

// ---------------- per-head RMSNorm + RoPE (fp16 outputs) --------------------
__device__ __forceinline__ float block_sumsq(float v, float* red)
{
    #pragma unroll
    for (int o = 16; o; o >>= 1) v += __shfl_xor_sync(0xffffffffu, v, o);
    int lane = threadIdx.x & 31, warp = threadIdx.x >> 5;
    if (lane == 0) red[warp] = v;
    __syncthreads();
    float s = red[0];
    #pragma unroll
    for (int w = 1; w < 8; w++) s += red[w];
    return s;
}

__global__ void __launch_bounds__(256) q_prep(
    const float* __restrict__ qkv, const float* __restrict__ cosb,
    const float* __restrict__ sinb, const float* __restrict__ w)
{
    __shared__ float red[8];
    int row = blockIdx.x, h = blockIdx.y, d = threadIdx.x;
    int l = row & (LL - 1), b = row >> 11;

    const float* src = qkv + (size_t)row * NQKV + h * HD;
    float x  = src[d];
    float ss = block_sumsq(x * x, red);
    float rms = rsqrtf(ss * (1.0f / HD) + EPS);

    int   dp  = (d < HD/2) ? d + HD/2 : d - HD/2;
    float xp  = src[dp];
    float xn  = x  * rms * w[d];
    float xpn = xp * rms * w[dp];
    float rot = (d < HD/2) ? -xpn : xpn;
    float c = cosb[(size_t)l * HD + d];
    float s = sinb[(size_t)l * HD + d];
    g_q16[(((size_t)b * NH + h) * LL + l) * HD + d] = __float2half_rn(xn * c + rot * s);
}

__global__ void __launch_bounds__(256) kv_prep(
    const float* __restrict__ qkv, const float* __restrict__ cosb,
    const float* __restrict__ sinb, const float* __restrict__ w)
{
    __shared__ float red[8];
    int row = blockIdx.x, h = blockIdx.y, d = threadIdx.x;
    int l = row & (LL - 1), b = row >> 11;

    const float* src = qkv + (size_t)row * NQKV + 2 * INNER + h * HD;
    float x  = src[d];
    float ss = block_sumsq(x * x, red);
    float rms = rsqrtf(ss * (1.0f / HD) + EPS);

    int   dp  = (d < HD/2) ? d + HD/2 : d - HD/2;
    float xp  = src[dp];
    float xn  = x  * rms * w[d];
    float xpn = xp * rms * w[dp];
    float rot = (d < HD/2) ? -xpn : xpn;
    float c = cosb[(size_t)l * HD + d];
    float s = sinb[(size_t)l * HD + d];
    size_t dst = (((size_t)b * NKV + h) * LL + l) * HD + d;
    g_k16[dst] = __float2half_rn(xn * c + rot * s);
    g_v16[dst] = __float2half_rn(qkv[(size_t)row * NQKV + 2 * INNER + NKV * HD + h * HD + d]);
}

// ---------------- mma-based causal flash attention ---------------------------
// CTA: 128 thr, 4 warps; warp owns 16 q-rows x d=256. K-tiles of 16.
constexpr int QTILE = 64;
constexpr int KTILE = 16;
constexpr int QS_LD = 264;   // halves per Q smem row (pad: conflict-free frags)
constexpr int KS_LD = 264;
constexpr int VT_LD = 18;    // V^T row = 16 k + 2 pad
constexpr int ATT_SMEM = (QTILE * QS_LD + KTILE * KS_LD + HD * VT_LD) * 2; // 51456

__global__ void __launch_bounds__(128) attn_mma()
{
    extern __shared__ __half sm[];
    __half* Qs = sm;                        // [64][264]
    __half* Ks = Qs + QTILE * QS_LD;        // [16][264]
    __half* VT = Ks + KTILE * KS_LD;        // [256][18]

    const int b  = blockIdx.z, h = blockIdx.y;
    const int q0 = (gridDim.x - 1 - blockIdx.x) * QTILE;   // heavy CTAs first
    const int kv = h >> 2;
    const int tid = threadIdx.x, wid = tid >> 5, lane = tid & 31;
    const int g = lane >> 2, t = lane & 3;
    const int wr = wid * 16;

    const __half* Qg = g_q16 + (((size_t)b * NH  + h)  * LL + q0) * HD;
    const __half* Kg = g_k16 + (((size_t)b * NKV + kv) * LL) * HD;
    const __half* Vg = g_v16 + (((size_t)b * NKV + kv) * LL) * HD;

    // stage Q once: 64 x 256 halves
    #pragma unroll
    for (int i = 0; i < 16; i++) {
        int idx = tid + i * 128;            // 0..2047 uint4 slots
        int r = idx >> 5, c = (idx & 31) * 8;
        *(uint4*)&Qs[r * QS_LD + c] = *(const uint4*)&Qg[(size_t)r * HD + c];
    }

    float m2[2]   = {-1e30f, -1e30f};
    float lrow[2] = {0.f, 0.f};
    float O[32][4];
    #pragma unroll
    for (int n = 0; n < 32; n++) { O[n][0] = O[n][1] = O[n][2] = O[n][3] = 0.f; }

    const float cscale = 0.09016994f;       // (1/16) * log2(e)
    const int ntiles = q0 / KTILE + 4;

    for (int tile = 0; tile < ntiles; tile++) {
        const int kb = tile * KTILE;
        __syncthreads();                     // protect previous K/V reads
        // stage K (row-major) and V (transposed)
        #pragma unroll
        for (int i = 0; i < 4; i++) {
            int idx = tid + i * 128;         // 0..511 uint4 slots
            int r = idx >> 5, c = (idx & 31) * 8;
            *(uint4*)&Ks[r * KS_LD + c] = *(const uint4*)&Kg[(size_t)(kb + r) * HD + c];
            uint4 v = *(const uint4*)&Vg[(size_t)(kb + r) * HD + c];
            const __half* hv = (const __half*)&v;
            #pragma unroll
            for (int j = 0; j < 8; j++) VT[(c + j) * VT_LD + r] = hv[j];
        }
        __syncthreads();

        if (kb > q0 + wr + 15) continue;     // tile entirely above warp's rows

        // ---- QK^T: scores 16x16 in accum regs ----
        float s[2][4] = {{0.f,0.f,0.f,0.f},{0.f,0.f,0.f,0.f}};
        #pragma unroll
        for (int c = 0; c < 16; c++) {
            const int col = c * 16 + 2 * t;
            uint32_t a0 = *(const uint32_t*)&Qs[(wr + g)     * QS_LD + col];
            uint32_t a1 = *(const uint32_t*)&Qs[(wr + 8 + g) * QS_LD + col];
            uint32_t a2 = *(const uint32_t*)&Qs[(wr + g)     * QS_LD + col + 8];
            uint32_t a3 = *(const uint32_t*)&Qs[(wr + 8 + g) * QS_LD + col + 8];
            #pragma unroll
            for (int nt = 0; nt < 2; nt++) {
                uint32_t b0 = *(const uint32_t*)&Ks[(nt * 8 + g) * KS_LD + col];
                uint32_t b1 = *(const uint32_t*)&Ks[(nt * 8 + g) * KS_LD + col + 8];
                mma16(s[nt], a0, a1, a2, a3, b0, b1);
            }
        }

        // ---- causal mask (only near-diagonal tiles) ----
        if (kb + 15 > q0 + wr) {
            int r0 = q0 + wr + g, r8 = r0 + 8;
            #pragma unroll
            for (int nt = 0; nt < 2; nt++) {
                int kp = kb + nt * 8 + 2 * t;
                if (kp     > r0) s[nt][0] = -1e30f;
                if (kp + 1 > r0) s[nt][1] = -1e30f;
                if (kp     > r8) s[nt][2] = -1e30f;
                if (kp + 1 > r8) s[nt][3] = -1e30f;
            }
        }

        // ---- online softmax (rows g and g+8) ----
        float r0m = fmaxf(fmaxf(s[0][0], s[0][1]), fmaxf(s[1][0], s[1][1]));
        float r8m = fmaxf(fmaxf(s[0][2], s[0][3]), fmaxf(s[1][2], s[1][3]));
        r0m = fmaxf(r0m, __shfl_xor_sync(0xffffffffu, r0m, 1));
        r0m = fmaxf(r0m, __shfl_xor_sync(0xffffffffu, r0m, 2));
        r8m = fmaxf(r8m, __shfl_xor_sync(0xffffffffu, r8m, 1));
        r8m = fmaxf(r8m, __shfl_xor_sync(0xffffffffu, r8m, 2));
        float m2n0 = fmaxf(m2[0], r0m * cscale);
        float m2n8 = fmaxf(m2[1], r8m * cscale);
        float corr0 = ex2f(m2[0] - m2n0);
        float corr8 = ex2f(m2[1] - m2n8);
        m2[0] = m2n0; m2[1] = m2n8;

        float p[2][4];
        #pragma unroll
        for (int nt = 0; nt < 2; nt++) {
            p[nt][0] = ex2f(fmaf(s[nt][0], cscale, -m2n0));
            p[nt][1] = ex2f(fmaf(s[nt][1], cscale, -m2n0));
            p[nt][2] = ex2f(fmaf(s[nt][2], cscale, -m2n8));
            p[nt][3] = ex2f(fmaf(s[nt][3], cscale, -m2n8));
        }
        lrow[0] = lrow[0] * corr0 + (p[0][0] + p[0][1]) + (p[1][0] + p[1][1]);
        lrow[1] = lrow[1] * corr8 + (p[0][2] + p[0][3]) + (p[1][2] + p[1][3]);

        // P accum layout == A-fragment layout: pack directly
        __half2 h0 = __float22half2_rn(make_float2(p[0][0], p[0][1]));
        __half2 h1 = __float22half2_rn(make_float2(p[0][2], p[0][3]));
        __half2 h2 = __float22half2_rn(make_float2(p[1][0], p[1][1]));
        __half2 h3 = __float22half2_rn(make_float2(p[1][2], p[1][3]));
        uint32_t pa0 = *(uint32_t*)&h0;      // (g, k=2t..2t+1)
        uint32_t pa1 = *(uint32_t*)&h1;      // (g+8, k=2t..2t+1)
        uint32_t pa2 = *(uint32_t*)&h2;      // (g, k=2t+8..2t+9)
        uint32_t pa3 = *(uint32_t*)&h3;      // (g+8, k=2t+8..2t+9)

        // ---- rescale O and accumulate P*V ----
        #pragma unroll
        for (int n = 0; n < 32; n++) {
            O[n][0] *= corr0; O[n][1] *= corr0;
            O[n][2] *= corr8; O[n][3] *= corr8;
            uint32_t b0 = *(const uint32_t*)&VT[(n * 8 + g) * VT_LD + 2 * t];
            uint32_t b1 = *(const uint32_t*)&VT[(n * 8 + g) * VT_LD + 2 * t + 8];
            mma16(O[n], pa0, pa1, pa2, pa3, b0, b1);
        }
    }

    // ---- epilogue ----
    float l0 = lrow[0];
    l0 += __shfl_xor_sync(0xffffffffu, l0, 1);
    l0 += __shfl_xor_sync(0xffffffffu, l0, 2);
    float l8 = lrow[1];
    l8 += __shfl_xor_sync(0xffffffffu, l8, 1);
    l8 += __shfl_xor_sync(0xffffffffu, l8, 2);
    float inv0 = __fdividef(1.f, l0);
    float inv8 = __fdividef(1.f, l8);

    const int r0 = q0 + wr + g, r8 = r0 + 8;
    float* o0 = g_att + ((size_t)(b * LL + r0)) * INNER + h * HD;
    float* o8 = g_att + ((size_t)(b * LL + r8)) * INNER + h * HD;
    #pragma unroll
    for (int n = 0; n < 32; n++) {
        int cc = n * 8 + 2 * t;
        *(float2*)&o0[cc] = make_float2(O[n][0] * inv0, O[n][1] * inv0);
        *(float2*)&o8[cc] = make_float2(O[n][2] * inv8, O[n][3] * inv8);
    }
}

// ---------------- gating: att *= silu(gate) ---------------------------------
__global__ void __launch_bounds__(256) gate_mul(const float* __restrict__ qkv)
{
    size_t i   = (size_t)blockIdx.x * 256 + threadIdx.x;
    size_t row = i >> 12;
    int    col = (int)(i & 4095);
    float g  = qkv[row * NQKV + INNER + col];
    float sg = g / (1.f + __expf(-g));
    g_att[i] *= sg;
}

// ---------------- launch ----------------------------------------------------
extern "C" void kernel_launch(void* const* d_in, const int* in_sizes, int n_in,
                              void* d_out, int out_size)
{
    const float* X    = (const float*)d_in[0];
    const float* cosb = (const float*)d_in[1];
    const float* sinb = (const float*)d_in[2];
    const float* Wq   = (const float*)d_in[3];
    const float* Wk   = (const float*)d_in[4];
    const float* Wv   = (const float*)d_in[5];
    const float* Wo   = (const float*)d_in[6];
    const float* qw   = (const float*)d_in[7];
    const float* kw   = (const float*)d_in[8];
    float* out = (float*)d_out;

    float *qkv, *att;
    __half *xp, *attp, *wqkvp, *wop;
    cudaGetSymbolAddress((void**)&qkv,   g_qkv);
    cudaGetSymbolAddress((void**)&att,   g_att);
    cudaGetSymbolAddress((void**)&xp,    g_xp);
    cudaGetSymbolAddress((void**)&attp,  g_attp);
    cudaGetSymbolAddress((void**)&wqkvp, g_wqkvp);
    cudaGetSymbolAddress((void**)&wop,   g_wop);

    static bool attr_set = false;
    if (!attr_set) {
        cudaFuncSetAttribute(gemm_tc, cudaFuncAttributeMaxDynamicSharedMemorySize,
                             GEMM_SMEM);
        cudaFuncSetAttribute(attn_mma, cudaFuncAttributeMaxDynamicSharedMemorySize,
                             ATT_SMEM);
        attr_set = true;
    }

    constexpr int KTH = HID / 32;
    __half* wq_dst = wqkvp;
    __half* wk_dst = wqkvp + (size_t)(2 * INNER / 128) * KTH * 4096;
    __half* wv_dst = wk_dst + (size_t)(NKV * HD / 128) * KTH * 4096;

    // 0) operand packing
    pack_a<<<(unsigned)((size_t)ROWS * HID      / 2048), 256>>>(X,  xp,  HID);
    pack_b<<<(unsigned)((size_t)HID * 2 * INNER / 1024), 256>>>(Wq, wq_dst, HID, 2 * INNER);
    pack_b<<<(unsigned)((size_t)HID * NKV * HD  / 1024), 256>>>(Wk, wk_dst, HID, NKV * HD);
    pack_b<<<(unsigned)((size_t)HID * NKV * HD  / 1024), 256>>>(Wv, wv_dst, HID, NKV * HD);
    pack_b<<<(unsigned)((size_t)INNER * HID     / 1024), 256>>>(Wo, wop, INNER, HID);

    // 1) fused QKV projection
    gemm_tc<<<dim3(NQKV / 128, ROWS / 128), 256, GEMM_SMEM>>>(xp, wqkvp, qkv, HID, NQKV);

    // 2) per-head RMSNorm + RoPE -> fp16
    q_prep <<<dim3(ROWS, NH),  256>>>(qkv, cosb, sinb, qw);
    kv_prep<<<dim3(ROWS, NKV), 256>>>(qkv, cosb, sinb, kw);

    // 3) mma flash attention
    attn_mma<<<dim3(LL / QTILE, NH, BB), 128, ATT_SMEM>>>();

    // 4) gate
    gate_mul<<<(unsigned)((size_t)ROWS * INNER / 256), 256>>>(qkv);

    // 5) output projection
    pack_a<<<(unsigned)((size_t)ROWS * INNER / 2048), 256>>>(att, attp, INNER);
    gemm_tc<<<dim3(HID / 128, ROWS / 128), 256, GEMM_SMEM>>>(attp, wop, out, INNER, HID);
}

// round 8
// speedup vs baseline: 7.9711x; 1.0358x over previous
#include <cuda_runtime.h>
#include <cuda_fp16.h>
#include <math.h>
#include <stdint.h>

// ---------------- problem constants ----------------
constexpr int BB     = 2;
constexpr int LL     = 2048;
constexpr int HID    = 2560;
constexpr int NH     = 16;
constexpr int NKV    = 4;
constexpr int HD     = 256;
constexpr int GQA    = NH / NKV;      // 4
constexpr int INNER  = NH * HD;       // 4096
constexpr int ROWS   = BB * LL;       // 4096
constexpr int NQKV   = 2 * INNER + 2 * NKV * HD;   // 10240
constexpr float EPS  = 1e-6f;

// ---------------- scratch (device globals) ----------------------------------
__device__ float  g_qkv [(size_t)ROWS * NQKV];       // fused q|gate|k|v
__device__ __half g_q16 [(size_t)BB * NH  * LL * HD];
__device__ __half g_k16 [(size_t)BB * NKV * LL * HD];
__device__ __half g_v16 [(size_t)BB * NKV * LL * HD];
// fragment-packed fp16 GEMM operands
__device__ __half g_xp   [(size_t)ROWS * HID];
__device__ __half g_attp [(size_t)ROWS * INNER];     // written by attn epilogue
__device__ __half g_wqkvp[(size_t)HID * NQKV];
__device__ __half g_wop  [(size_t)INNER * HID];

// ================= shared mma helper =========================================
__device__ __forceinline__ void mma16(float* d, uint32_t a0, uint32_t a1,
                                      uint32_t a2, uint32_t a3,
                                      uint32_t b0, uint32_t b1) {
    asm volatile(
        "mma.sync.aligned.m16n8k16.row.col.f32.f16.f16.f32 "
        "{%0,%1,%2,%3}, {%4,%5,%6,%7}, {%8,%9}, {%0,%1,%2,%3};"
        : "+f"(d[0]), "+f"(d[1]), "+f"(d[2]), "+f"(d[3])
        : "r"(a0), "r"(a1), "r"(a2), "r"(a3), "r"(b0), "r"(b1));
}

__device__ __forceinline__ float ex2f(float x) {
    float r; asm("ex2.approx.f32 %0, %1;" : "=f"(r) : "f"(x));
    return r;
}

// ================= operand packing (fp16 fragment layout) ====================
__global__ void __launch_bounds__(256) pack_a(
    const float* __restrict__ A, __half* __restrict__ Ap, int K)
{
    size_t slot = (size_t)blockIdx.x * 256 + threadIdx.x;
    int lane = slot & 31, mb = (slot >> 5) & 7, ks = (slot >> 8) & 1;
    size_t rest = slot >> 9;
    int KT = K / 32;
    int kt = (int)(rest % KT), mt = (int)(rest / KT);
    int g = lane >> 2, t = lane & 3;
    int row = mt * 128 + mb * 16 + g;
    int col = kt * 32 + ks * 16 + 2 * t;
    const float* r0 = &A[(size_t)row * K + col];
    const float* r1 = &A[(size_t)(row + 8) * K + col];
    __half h[8];
    h[0] = __float2half_rn(r0[0]); h[1] = __float2half_rn(r0[1]);
    h[2] = __float2half_rn(r1[0]); h[3] = __float2half_rn(r1[1]);
    h[4] = __float2half_rn(r0[8]); h[5] = __float2half_rn(r0[9]);
    h[6] = __float2half_rn(r1[8]); h[7] = __float2half_rn(r1[9]);
    *(uint4*)&Ap[slot * 8] = *(uint4*)h;
}

__global__ void __launch_bounds__(256) pack_b(
    const float* __restrict__ Bm, __half* __restrict__ Bp, int K, int N)
{
    size_t slot = (size_t)blockIdx.x * 256 + threadIdx.x;
    int lane = slot & 31, nb = (slot >> 5) & 15, ks = (slot >> 9) & 1;
    size_t rest = slot >> 10;
    int KT = K / 32;
    int kt = (int)(rest % KT), nt = (int)(rest / KT);
    int g = lane >> 2, t = lane & 3;
    int k = kt * 32 + ks * 16 + 2 * t;
    int n = nt * 128 + nb * 8 + g;
    __half h[4];
    h[0] = __float2half_rn(Bm[(size_t)k * N + n]);
    h[1] = __float2half_rn(Bm[(size_t)(k + 1) * N + n]);
    h[2] = __float2half_rn(Bm[(size_t)(k + 8) * N + n]);
    h[3] = __float2half_rn(Bm[(size_t)(k + 9) * N + n]);
    *(uint2*)&Bp[slot * 4] = *(uint2*)h;
}

// ================= fp16 mma GEMM, 4-stage cp.async pipeline ==================
constexpr int NSTG   = 4;
constexpr int ASTG_B = 8192;
constexpr int BSTG_B = 8192;
constexpr int GEMM_SMEM = NSTG * (ASTG_B + BSTG_B);   // 65536

__device__ __forceinline__ void cp16(uint32_t dst, const void* src) {
    asm volatile("cp.async.cg.shared.global [%0], [%1], 16;" :: "r"(dst), "l"(src));
}

__global__ void __launch_bounds__(256) gemm_tc(
    const __half* __restrict__ Ap, const __half* __restrict__ Bp,
    float* __restrict__ C, int K, int ldc)
{
    extern __shared__ char smem[];
    char* Abuf = smem;
    char* Bbuf = smem + NSTG * ASTG_B;
    const uint32_t sA = (uint32_t)__cvta_generic_to_shared(Abuf);
    const uint32_t sB = (uint32_t)__cvta_generic_to_shared(Bbuf);

    const int tid  = threadIdx.x;
    const int wid  = tid >> 5;
    const int lane = tid & 31;
    const int wm   = wid & 3;
    const int wn   = wid >> 2;
    const int g    = lane >> 2;
    const int t    = lane & 3;
    const int KT   = K / 32;

    const size_t abase = (size_t)blockIdx.y * KT * 4096;
    const size_t bbase = (size_t)blockIdx.x * KT * 4096;

    float d[2][8][4];
    #pragma unroll
    for (int i = 0; i < 2; i++)
        #pragma unroll
        for (int j = 0; j < 8; j++)
            #pragma unroll
            for (int r = 0; r < 4; r++) d[i][j][r] = 0.f;

    auto stage = [&](int buf, int s) {
        #pragma unroll
        for (int i = 0; i < 2; i++) {
            int idx = tid + i * 256;
            cp16(sA + (uint32_t)(buf * ASTG_B + idx * 16),
                 Ap + abase + (size_t)s * 4096 + idx * 8);
            cp16(sB + (uint32_t)(buf * BSTG_B + idx * 16),
                 Bp + bbase + (size_t)s * 4096 + idx * 8);
        }
        asm volatile("cp.async.commit_group;" ::: "memory");
    };

    stage(0, 0);
    stage(1, 1);
    stage(2, 2);

    for (int s = 0; s < KT; s++) {
        asm volatile("cp.async.wait_group 2;" ::: "memory");
        __syncthreads();
        if (s + 3 < KT) stage((s + 3) & (NSTG - 1), s + 3);
        else asm volatile("cp.async.commit_group;" ::: "memory");

        const uint4* At = (const uint4*)(Abuf + (s & (NSTG - 1)) * ASTG_B);
        const uint2* Bt = (const uint2*)(Bbuf + (s & (NSTG - 1)) * BSTG_B);
        #pragma unroll
        for (int ks = 0; ks < 2; ks++) {
            uint4 a[2];
            uint2 b[8];
            #pragma unroll
            for (int i = 0; i < 2; i++)
                a[i] = At[(ks * 8 + wm * 2 + i) * 32 + lane];
            #pragma unroll
            for (int j = 0; j < 8; j++)
                b[j] = Bt[(ks * 16 + wn * 8 + j) * 32 + lane];
            #pragma unroll
            for (int i = 0; i < 2; i++)
                #pragma unroll
                for (int j = 0; j < 8; j++)
                    mma16(d[i][j], a[i].x, a[i].y, a[i].z, a[i].w, b[j].x, b[j].y);
        }
    }

    const int row0 = blockIdx.y * 128 + wm * 32 + g;
    const int col0 = blockIdx.x * 128 + wn * 64 + 2 * t;
    #pragma unroll
    for (int i = 0; i < 2; i++) {
        int r = row0 + i * 16;
        #pragma unroll
        for (int j = 0; j < 8; j++) {
            int c = col0 + j * 8;
            *(float2*)&C[(size_t)r * ldc + c]       = make_float2(d[i][j][0], d[i][j][1]);
            *(float2*)&C[(size_t)(r + 8) * ldc + c] = make_float2(d[i][j][2], d[i][j][3]);
        }
    }
}

// ---------------- per-head RMSNorm + RoPE (fp16 outputs) --------------------
__device__ __forceinline__ float block_sumsq(float v, float* red)
{
    #pragma unroll
    for (int o = 16; o; o >>= 1) v += __shfl_xor_sync(0xffffffffu, v, o);
    int lane = threadIdx.x & 31, warp = threadIdx.x >> 5;
    if (lane == 0) red[warp] = v;
    __syncthreads();
    float s = red[0];
    #pragma unroll
    for (int w = 1; w < 8; w++) s += red[w];
    return s;
}

__global__ void __launch_bounds__(256) q_prep(
    const float* __restrict__ qkv, const float* __restrict__ cosb,
    const float* __restrict__ sinb, const float* __restrict__ w)
{
    __shared__ float red[8];
    int row = blockIdx.x, h = blockIdx.y, d = threadIdx.x;
    int l = row & (LL - 1), b = row >> 11;

    const float* src = qkv + (size_t)row * NQKV + h * HD;
    float x  = src[d];
    float ss = block_sumsq(x * x, red);
    float rms = rsqrtf(ss * (1.0f / HD) + EPS);

    int   dp  = (d < HD/2) ? d + HD/2 : d - HD/2;
    float xp  = src[dp];
    float xn  = x  * rms * w[d];
    float xpn = xp * rms * w[dp];
    float rot = (d < HD/2) ? -xpn : xpn;
    float c = cosb[(size_t)l * HD + d];
    float s = sinb[(size_t)l * HD + d];
    g_q16[(((size_t)b * NH + h) * LL + l) * HD + d] = __float2half_rn(xn * c + rot * s);
}

__global__ void __launch_bounds__(256) kv_prep(
    const float* __restrict__ qkv, const float* __restrict__ cosb,
    const float* __restrict__ sinb, const float* __restrict__ w)
{
    __shared__ float red[8];
    int row = blockIdx.x, h = blockIdx.y, d = threadIdx.x;
    int l = row & (LL - 1), b = row >> 11;

    const float* src = qkv + (size_t)row * NQKV + 2 * INNER + h * HD;
    float x  = src[d];
    float ss = block_sumsq(x * x, red);
    float rms = rsqrtf(ss * (1.0f / HD) + EPS);

    int   dp  = (d < HD/2) ? d + HD/2 : d - HD/2;
    float xp  = src[dp];
    float xn  = x  * rms * w[d];
    float xpn = xp * rms * w[dp];
    float rot = (d < HD/2) ? -xpn : xpn;
    float c = cosb[(size_t)l * HD + d];
    float s = sinb[(size_t)l * HD + d];
    size_t dst = (((size_t)b * NKV + h) * LL + l) * HD + d;
    g_k16[dst] = __float2half_rn(xn * c + rot * s);
    g_v16[dst] = __float2half_rn(qkv[(size_t)row * NQKV + 2 * INNER + NKV * HD + h * HD + d]);
}

// ---------------- mma flash attention + fused gate + packed-A epilogue ------
constexpr int QTILE = 64;
constexpr int KTILE = 16;
constexpr int QS_LD = 264;
constexpr int KS_LD = 264;
constexpr int VT_LD = 18;
constexpr int ATT_SMEM = (QTILE * QS_LD + KTILE * KS_LD + HD * VT_LD) * 2; // 51456

__global__ void __launch_bounds__(128) attn_mma()
{
    extern __shared__ __half sm[];
    __half* Qs = sm;                        // [64][264]
    __half* Ks = Qs + QTILE * QS_LD;        // [16][264]
    __half* VT = Ks + KTILE * KS_LD;        // [256][18]

    const int b  = blockIdx.z, h = blockIdx.y;
    const int q0 = (gridDim.x - 1 - blockIdx.x) * QTILE;   // heavy CTAs first
    const int kv = h >> 2;
    const int tid = threadIdx.x, wid = tid >> 5, lane = tid & 31;
    const int g = lane >> 2, t = lane & 3;
    const int wr = wid * 16;

    const __half* Qg = g_q16 + (((size_t)b * NH  + h)  * LL + q0) * HD;
    const __half* Kg = g_k16 + (((size_t)b * NKV + kv) * LL) * HD;
    const __half* Vg = g_v16 + (((size_t)b * NKV + kv) * LL) * HD;

    // stage Q once
    #pragma unroll
    for (int i = 0; i < 16; i++) {
        int idx = tid + i * 128;
        int r = idx >> 5, c = (idx & 31) * 8;
        *(uint4*)&Qs[r * QS_LD + c] = *(const uint4*)&Qg[(size_t)r * HD + c];
    }

    float m2[2]   = {-1e30f, -1e30f};
    float lrow[2] = {0.f, 0.f};
    float O[32][4];
    #pragma unroll
    for (int n = 0; n < 32; n++) { O[n][0] = O[n][1] = O[n][2] = O[n][3] = 0.f; }

    const float cscale = 0.09016994f;       // (1/16) * log2(e)
    const int ntiles = q0 / KTILE + 4;

    for (int tile = 0; tile < ntiles; tile++) {
        const int kb = tile * KTILE;
        __syncthreads();
        #pragma unroll
        for (int i = 0; i < 4; i++) {
            int idx = tid + i * 128;
            int r = idx >> 5, c = (idx & 31) * 8;
            *(uint4*)&Ks[r * KS_LD + c] = *(const uint4*)&Kg[(size_t)(kb + r) * HD + c];
            uint4 v = *(const uint4*)&Vg[(size_t)(kb + r) * HD + c];
            const __half* hv = (const __half*)&v;
            #pragma unroll
            for (int j = 0; j < 8; j++) VT[(c + j) * VT_LD + r] = hv[j];
        }
        __syncthreads();

        if (kb > q0 + wr + 15) continue;

        // ---- QK^T ----
        float s[2][4] = {{0.f,0.f,0.f,0.f},{0.f,0.f,0.f,0.f}};
        #pragma unroll
        for (int c = 0; c < 16; c++) {
            const int col = c * 16 + 2 * t;
            uint32_t a0 = *(const uint32_t*)&Qs[(wr + g)     * QS_LD + col];
            uint32_t a1 = *(const uint32_t*)&Qs[(wr + 8 + g) * QS_LD + col];
            uint32_t a2 = *(const uint32_t*)&Qs[(wr + g)     * QS_LD + col + 8];
            uint32_t a3 = *(const uint32_t*)&Qs[(wr + 8 + g) * QS_LD + col + 8];
            #pragma unroll
            for (int nt = 0; nt < 2; nt++) {
                uint32_t b0 = *(const uint32_t*)&Ks[(nt * 8 + g) * KS_LD + col];
                uint32_t b1 = *(const uint32_t*)&Ks[(nt * 8 + g) * KS_LD + col + 8];
                mma16(s[nt], a0, a1, a2, a3, b0, b1);
            }
        }

        // ---- causal mask ----
        if (kb + 15 > q0 + wr) {
            int r0 = q0 + wr + g, r8 = r0 + 8;
            #pragma unroll
            for (int nt = 0; nt < 2; nt++) {
                int kp = kb + nt * 8 + 2 * t;
                if (kp     > r0) s[nt][0] = -1e30f;
                if (kp + 1 > r0) s[nt][1] = -1e30f;
                if (kp     > r8) s[nt][2] = -1e30f;
                if (kp + 1 > r8) s[nt][3] = -1e30f;
            }
        }

        // ---- online softmax ----
        float r0m = fmaxf(fmaxf(s[0][0], s[0][1]), fmaxf(s[1][0], s[1][1]));
        float r8m = fmaxf(fmaxf(s[0][2], s[0][3]), fmaxf(s[1][2], s[1][3]));
        r0m = fmaxf(r0m, __shfl_xor_sync(0xffffffffu, r0m, 1));
        r0m = fmaxf(r0m, __shfl_xor_sync(0xffffffffu, r0m, 2));
        r8m = fmaxf(r8m, __shfl_xor_sync(0xffffffffu, r8m, 1));
        r8m = fmaxf(r8m, __shfl_xor_sync(0xffffffffu, r8m, 2));
        float m2n0 = fmaxf(m2[0], r0m * cscale);
        float m2n8 = fmaxf(m2[1], r8m * cscale);
        float corr0 = ex2f(m2[0] - m2n0);
        float corr8 = ex2f(m2[1] - m2n8);
        m2[0] = m2n0; m2[1] = m2n8;

        float p[2][4];
        #pragma unroll
        for (int nt = 0; nt < 2; nt++) {
            p[nt][0] = ex2f(fmaf(s[nt][0], cscale, -m2n0));
            p[nt][1] = ex2f(fmaf(s[nt][1], cscale, -m2n0));
            p[nt][2] = ex2f(fmaf(s[nt][2], cscale, -m2n8));
            p[nt][3] = ex2f(fmaf(s[nt][3], cscale, -m2n8));
        }
        lrow[0] = lrow[0] * corr0 + (p[0][0] + p[0][1]) + (p[1][0] + p[1][1]);
        lrow[1] = lrow[1] * corr8 + (p[0][2] + p[0][3]) + (p[1][2] + p[1][3]);

        __half2 h0 = __float22half2_rn(make_float2(p[0][0], p[0][1]));
        __half2 h1 = __float22half2_rn(make_float2(p[0][2], p[0][3]));
        __half2 h2 = __float22half2_rn(make_float2(p[1][0], p[1][1]));
        __half2 h3 = __float22half2_rn(make_float2(p[1][2], p[1][3]));
        uint32_t pa0 = *(uint32_t*)&h0;
        uint32_t pa1 = *(uint32_t*)&h1;
        uint32_t pa2 = *(uint32_t*)&h2;
        uint32_t pa3 = *(uint32_t*)&h3;

        #pragma unroll
        for (int n = 0; n < 32; n++) {
            O[n][0] *= corr0; O[n][1] *= corr0;
            O[n][2] *= corr8; O[n][3] *= corr8;
            uint32_t b0 = *(const uint32_t*)&VT[(n * 8 + g) * VT_LD + 2 * t];
            uint32_t b1 = *(const uint32_t*)&VT[(n * 8 + g) * VT_LD + 2 * t + 8];
            mma16(O[n], pa0, pa1, pa2, pa3, b0, b1);
        }
    }

    // ---- fused epilogue: 1/l, silu(gate), pack fp16 A-fragments ----
    float l0 = lrow[0];
    l0 += __shfl_xor_sync(0xffffffffu, l0, 1);
    l0 += __shfl_xor_sync(0xffffffffu, l0, 2);
    float l8 = lrow[1];
    l8 += __shfl_xor_sync(0xffffffffu, l8, 1);
    l8 += __shfl_xor_sync(0xffffffffu, l8, 2);
    float inv0 = __fdividef(1.f, l0);
    float inv8 = __fdividef(1.f, l8);

    const int r0l = q0 + wr + g;                 // within-batch row (row g)
    const int mt  = (b * LL + q0 + wr) >> 7;     // 128-row tile of packed A
    const int mb  = ((q0 & 64) >> 4) + wid;      // 16-row block within tile
    const float* gate0 = g_qkv + (size_t)(b * LL + r0l) * NQKV + INNER + h * HD;
    const float* gate8 = gate0 + (size_t)8 * NQKV;

    #pragma unroll
    for (int n = 0; n < 32; n += 2) {
        int kt = h * 8 + (n >> 2);
        int ks = (n >> 1) & 1;
        size_t off = (((size_t)mt * 128 + kt) * 512 + (ks * 8 + mb) * 32 + lane) * 8;
        int c0 = n * 8 + 2 * t;
        float2 gA0 = *(const float2*)&gate0[c0];
        float2 gB0 = *(const float2*)&gate8[c0];
        float2 gA1 = *(const float2*)&gate0[c0 + 8];
        float2 gB1 = *(const float2*)&gate8[c0 + 8];
        float sA0x = gA0.x / (1.f + __expf(-gA0.x));
        float sA0y = gA0.y / (1.f + __expf(-gA0.y));
        float sB0x = gB0.x / (1.f + __expf(-gB0.x));
        float sB0y = gB0.y / (1.f + __expf(-gB0.y));
        float sA1x = gA1.x / (1.f + __expf(-gA1.x));
        float sA1y = gA1.y / (1.f + __expf(-gA1.y));
        float sB1x = gB1.x / (1.f + __expf(-gB1.x));
        float sB1y = gB1.y / (1.f + __expf(-gB1.y));
        __half hb[8];
        hb[0] = __float2half_rn(O[n][0]     * inv0 * sA0x);
        hb[1] = __float2half_rn(O[n][1]     * inv0 * sA0y);
        hb[2] = __float2half_rn(O[n][2]     * inv8 * sB0x);
        hb[3] = __float2half_rn(O[n][3]     * inv8 * sB0y);
        hb[4] = __float2half_rn(O[n + 1][0] * inv0 * sA1x);
        hb[5] = __float2half_rn(O[n + 1][1] * inv0 * sA1y);
        hb[6] = __float2half_rn(O[n + 1][2] * inv8 * sB1x);
        hb[7] = __float2half_rn(O[n + 1][3] * inv8 * sB1y);
        *(uint4*)&g_attp[off] = *(uint4*)hb;
    }
}

// ---------------- launch ----------------------------------------------------
extern "C" void kernel_launch(void* const* d_in, const int* in_sizes, int n_in,
                              void* d_out, int out_size)
{
    const float* X    = (const float*)d_in[0];
    const float* cosb = (const float*)d_in[1];
    const float* sinb = (const float*)d_in[2];
    const float* Wq   = (const float*)d_in[3];
    const float* Wk   = (const float*)d_in[4];
    const float* Wv   = (const float*)d_in[5];
    const float* Wo   = (const float*)d_in[6];
    const float* qw   = (const float*)d_in[7];
    const float* kw   = (const float*)d_in[8];
    float* out = (float*)d_out;

    float* qkv;
    __half *xp, *attp, *wqkvp, *wop;
    cudaGetSymbolAddress((void**)&qkv,   g_qkv);
    cudaGetSymbolAddress((void**)&xp,    g_xp);
    cudaGetSymbolAddress((void**)&attp,  g_attp);
    cudaGetSymbolAddress((void**)&wqkvp, g_wqkvp);
    cudaGetSymbolAddress((void**)&wop,   g_wop);

    static bool attr_set = false;
    if (!attr_set) {
        cudaFuncSetAttribute(gemm_tc, cudaFuncAttributeMaxDynamicSharedMemorySize,
                             GEMM_SMEM);
        cudaFuncSetAttribute(attn_mma, cudaFuncAttributeMaxDynamicSharedMemorySize,
                             ATT_SMEM);
        attr_set = true;
    }

    constexpr int KTH = HID / 32;
    __half* wq_dst = wqkvp;
    __half* wk_dst = wqkvp + (size_t)(2 * INNER / 128) * KTH * 4096;
    __half* wv_dst = wk_dst + (size_t)(NKV * HD / 128) * KTH * 4096;

    // 0) operand packing
    pack_a<<<(unsigned)((size_t)ROWS * HID      / 2048), 256>>>(X,  xp,  HID);
    pack_b<<<(unsigned)((size_t)HID * 2 * INNER / 1024), 256>>>(Wq, wq_dst, HID, 2 * INNER);
    pack_b<<<(unsigned)((size_t)HID * NKV * HD  / 1024), 256>>>(Wk, wk_dst, HID, NKV * HD);
    pack_b<<<(unsigned)((size_t)HID * NKV * HD  / 1024), 256>>>(Wv, wv_dst, HID, NKV * HD);
    pack_b<<<(unsigned)((size_t)INNER * HID     / 1024), 256>>>(Wo, wop, INNER, HID);

    // 1) fused QKV projection
    gemm_tc<<<dim3(NQKV / 128, ROWS / 128), 256, GEMM_SMEM>>>(xp, wqkvp, qkv, HID, NQKV);

    // 2) per-head RMSNorm + RoPE -> fp16
    q_prep <<<dim3(ROWS, NH),  256>>>(qkv, cosb, sinb, qw);
    kv_prep<<<dim3(ROWS, NKV), 256>>>(qkv, cosb, sinb, kw);

    // 3) mma flash attention (+ gate + pack fused in epilogue)
    attn_mma<<<dim3(LL / QTILE, NH, BB), 128, ATT_SMEM>>>();

    // 4) output projection
    gemm_tc<<<dim3(HID / 128, ROWS / 128), 256, GEMM_SMEM>>>(attp, wop, out, INNER, HID);
}

// round 10
// speedup vs baseline: 10.6227x; 1.3327x over previous
#include <cuda_runtime.h>
#include <cuda_fp16.h>
#include <math.h>
#include <stdint.h>

// ---------------- problem constants ----------------
constexpr int BB     = 2;
constexpr int LL     = 2048;
constexpr int HID    = 2560;
constexpr int NH     = 16;
constexpr int NKV    = 4;
constexpr int HD     = 256;
constexpr int GQA    = NH / NKV;      // 4
constexpr int INNER  = NH * HD;       // 4096
constexpr int ROWS   = BB * LL;       // 4096
constexpr int NQKV   = 2 * INNER + 2 * NKV * HD;   // 10240
constexpr float EPS  = 1e-6f;

// ---------------- scratch (device globals) ----------------------------------
__device__ float  g_qkv [(size_t)ROWS * NQKV];       // fused q|gate|k|v
__device__ __half g_q16 [(size_t)BB * NH  * LL * HD];
__device__ __half g_k16 [(size_t)BB * NKV * LL * HD];
__device__ __half g_v16 [(size_t)BB * NKV * LL * HD];
// fragment-packed fp16 GEMM operands
__device__ __half g_xp   [(size_t)ROWS * HID];
__device__ __half g_attp [(size_t)ROWS * INNER];     // written by attn epilogue
__device__ __half g_wqkvp[(size_t)HID * NQKV];
__device__ __half g_wop  [(size_t)INNER * HID];

// ================= mma / ldmatrix helpers ====================================
__device__ __forceinline__ void mma16(float* d, uint32_t a0, uint32_t a1,
                                      uint32_t a2, uint32_t a3,
                                      uint32_t b0, uint32_t b1) {
    asm volatile(
        "mma.sync.aligned.m16n8k16.row.col.f32.f16.f16.f32 "
        "{%0,%1,%2,%3}, {%4,%5,%6,%7}, {%8,%9}, {%0,%1,%2,%3};"
        : "+f"(d[0]), "+f"(d[1]), "+f"(d[2]), "+f"(d[3])
        : "r"(a0), "r"(a1), "r"(a2), "r"(a3), "r"(b0), "r"(b1));
}

__device__ __forceinline__ void ldsm_x2_t(uint32_t& r0, uint32_t& r1, uint32_t addr) {
    asm volatile("ldmatrix.sync.aligned.m8n8.x2.trans.shared.b16 {%0,%1}, [%2];"
                 : "=r"(r0), "=r"(r1) : "r"(addr));
}

__device__ __forceinline__ float ex2f(float x) {
    float r; asm("ex2.approx.f32 %0, %1;" : "=f"(r) : "f"(x));
    return r;
}

// ================= operand packing (fp16 fragment layout) ====================
// A region per (mt,kt): slot=(ks*8+mb)*32+lane, 8 halves (uint4) = one A-frag.
// B region per (nt,kt): slot=(ks*8+q)*32+lane, 8 halves = b-frags of nb=2q,2q+1.
__global__ void __launch_bounds__(256) pack_a(
    const float* __restrict__ A, __half* __restrict__ Ap, int K)
{
    size_t slot = (size_t)blockIdx.x * 256 + threadIdx.x;
    int lane = slot & 31, mb = (slot >> 5) & 7, ks = (slot >> 8) & 1;
    size_t rest = slot >> 9;
    int KT = K / 32;
    int kt = (int)(rest % KT), mt = (int)(rest / KT);
    int g = lane >> 2, t = lane & 3;
    int row = mt * 128 + mb * 16 + g;
    int col = kt * 32 + ks * 16 + 2 * t;
    const float* r0 = &A[(size_t)row * K + col];
    const float* r1 = &A[(size_t)(row + 8) * K + col];
    __half h[8];
    h[0] = __float2half_rn(r0[0]); h[1] = __float2half_rn(r0[1]);
    h[2] = __float2half_rn(r1[0]); h[3] = __float2half_rn(r1[1]);
    h[4] = __float2half_rn(r0[8]); h[5] = __float2half_rn(r0[9]);
    h[6] = __float2half_rn(r1[8]); h[7] = __float2half_rn(r1[9]);
    *(uint4*)&Ap[slot * 8] = *(uint4*)h;
}

__global__ void __launch_bounds__(256) pack_b(
    const float* __restrict__ Bm, __half* __restrict__ Bp, int K, int N)
{
    size_t slot = (size_t)blockIdx.x * 256 + threadIdx.x;
    int lane = slot & 31, q = (slot >> 5) & 7, ks = (slot >> 8) & 1;
    size_t rest = slot >> 9;
    int KT = K / 32;
    int kt = (int)(rest % KT), nt = (int)(rest / KT);
    int g = lane >> 2, t = lane & 3;
    int k  = kt * 32 + ks * 16 + 2 * t;
    int n0 = nt * 128 + q * 16 + g;
    int n1 = n0 + 8;
    __half h[8];
    h[0] = __float2half_rn(Bm[(size_t)k * N + n0]);
    h[1] = __float2half_rn(Bm[(size_t)(k + 1) * N + n0]);
    h[2] = __float2half_rn(Bm[(size_t)(k + 8) * N + n0]);
    h[3] = __float2half_rn(Bm[(size_t)(k + 9) * N + n0]);
    h[4] = __float2half_rn(Bm[(size_t)k * N + n1]);
    h[5] = __float2half_rn(Bm[(size_t)(k + 1) * N + n1]);
    h[6] = __float2half_rn(Bm[(size_t)(k + 8) * N + n1]);
    h[7] = __float2half_rn(Bm[(size_t)(k + 9) * N + n1]);
    *(uint4*)&Bp[slot * 8] = *(uint4*)h;
}

// ================= fp16 mma GEMM: 4 warps, warp tile 64x64 ===================
constexpr int NSTG   = 4;
constexpr int ASTG_B = 8192;
constexpr int BSTG_B = 8192;
constexpr int GEMM_SMEM = NSTG * (ASTG_B + BSTG_B);   // 65536

__device__ __forceinline__ void cp16(uint32_t dst, const void* src) {
    asm volatile("cp.async.cg.shared.global [%0], [%1], 16;" :: "r"(dst), "l"(src));
}

__global__ void __launch_bounds__(128) gemm_tc(
    const __half* __restrict__ Ap, const __half* __restrict__ Bp,
    float* __restrict__ C, int K, int ldc)
{
    extern __shared__ char smem[];
    char* Abuf = smem;
    char* Bbuf = smem + NSTG * ASTG_B;
    const uint32_t sA = (uint32_t)__cvta_generic_to_shared(Abuf);
    const uint32_t sB = (uint32_t)__cvta_generic_to_shared(Bbuf);

    const int tid  = threadIdx.x;
    const int wid  = tid >> 5;
    const int lane = tid & 31;
    const int wm   = wid & 1;                 // warp m offset wm*64
    const int wn   = wid >> 1;                // warp n offset wn*64
    const int g    = lane >> 2;
    const int t    = lane & 3;
    const int KT   = K / 32;

    const size_t abase = (size_t)blockIdx.y * KT * 4096;
    const size_t bbase = (size_t)blockIdx.x * KT * 4096;

    float d[4][8][4];
    #pragma unroll
    for (int i = 0; i < 4; i++)
        #pragma unroll
        for (int j = 0; j < 8; j++)
            #pragma unroll
            for (int r = 0; r < 4; r++) d[i][j][r] = 0.f;

    auto stage = [&](int buf, int s) {
        #pragma unroll
        for (int i = 0; i < 4; i++) {
            int idx = tid + i * 128;          // 0..511 16B chunks
            cp16(sA + (uint32_t)(buf * ASTG_B + idx * 16),
                 Ap + abase + (size_t)s * 4096 + idx * 8);
            cp16(sB + (uint32_t)(buf * BSTG_B + idx * 16),
                 Bp + bbase + (size_t)s * 4096 + idx * 8);
        }
        asm volatile("cp.async.commit_group;" ::: "memory");
    };

    stage(0, 0);
    stage(1, 1);
    stage(2, 2);

    for (int s = 0; s < KT; s++) {
        asm volatile("cp.async.wait_group 2;" ::: "memory");
        __syncthreads();
        if (s + 3 < KT) stage((s + 3) & (NSTG - 1), s + 3);
        else asm volatile("cp.async.commit_group;" ::: "memory");

        const uint4* At = (const uint4*)(Abuf + (s & (NSTG - 1)) * ASTG_B);
        const uint4* Bt = (const uint4*)(Bbuf + (s & (NSTG - 1)) * BSTG_B);
        #pragma unroll
        for (int ks = 0; ks < 2; ks++) {
            uint4 a[4], bb[4];
            #pragma unroll
            for (int i = 0; i < 4; i++)
                a[i] = At[(ks * 8 + wm * 4 + i) * 32 + lane];
            #pragma unroll
            for (int p = 0; p < 4; p++)
                bb[p] = Bt[(ks * 8 + wn * 4 + p) * 32 + lane];
            #pragma unroll
            for (int i = 0; i < 4; i++)
                #pragma unroll
                for (int p = 0; p < 4; p++) {
                    mma16(d[i][2 * p],     a[i].x, a[i].y, a[i].z, a[i].w, bb[p].x, bb[p].y);
                    mma16(d[i][2 * p + 1], a[i].x, a[i].y, a[i].z, a[i].w, bb[p].z, bb[p].w);
                }
        }
    }

    #pragma unroll
    for (int i = 0; i < 4; i++) {
        int r = blockIdx.y * 128 + wm * 64 + i * 16 + g;
        #pragma unroll
        for (int j = 0; j < 8; j++) {
            int c = blockIdx.x * 128 + wn * 64 + j * 8 + 2 * t;
            *(float2*)&C[(size_t)r * ldc + c]       = make_float2(d[i][j][0], d[i][j][1]);
            *(float2*)&C[(size_t)(r + 8) * ldc + c] = make_float2(d[i][j][2], d[i][j][3]);
        }
    }
}

// ---------------- per-head RMSNorm + RoPE (fp16 outputs) --------------------
__device__ __forceinline__ float block_sumsq(float v, float* red)
{
    #pragma unroll
    for (int o = 16; o; o >>= 1) v += __shfl_xor_sync(0xffffffffu, v, o);
    int lane = threadIdx.x & 31, warp = threadIdx.x >> 5;
    if (lane == 0) red[warp] = v;
    __syncthreads();
    float s = red[0];
    #pragma unroll
    for (int w = 1; w < 8; w++) s += red[w];
    return s;
}

__global__ void __launch_bounds__(256) q_prep(
    const float* __restrict__ qkv, const float* __restrict__ cosb,
    const float* __restrict__ sinb, const float* __restrict__ w)
{
    __shared__ float red[8];
    int row = blockIdx.x, h = blockIdx.y, d = threadIdx.x;
    int l = row & (LL - 1), b = row >> 11;

    const float* src = qkv + (size_t)row * NQKV + h * HD;
    float x  = src[d];
    float ss = block_sumsq(x * x, red);
    float rms = rsqrtf(ss * (1.0f / HD) + EPS);

    int   dp  = (d < HD/2) ? d + HD/2 : d - HD/2;
    float xp  = src[dp];
    float xn  = x  * rms * w[d];
    float xpn = xp * rms * w[dp];
    float rot = (d < HD/2) ? -xpn : xpn;
    float c = cosb[(size_t)l * HD + d];
    float s = sinb[(size_t)l * HD + d];
    g_q16[(((size_t)b * NH + h) * LL + l) * HD + d] = __float2half_rn(xn * c + rot * s);
}

__global__ void __launch_bounds__(256) kv_prep(
    const float* __restrict__ qkv, const float* __restrict__ cosb,
    const float* __restrict__ sinb, const float* __restrict__ w)
{
    __shared__ float red[8];
    int row = blockIdx.x, h = blockIdx.y, d = threadIdx.x;
    int l = row & (LL - 1), b = row >> 11;

    const float* src = qkv + (size_t)row * NQKV + 2 * INNER + h * HD;
    float x  = src[d];
    float ss = block_sumsq(x * x, red);
    float rms = rsqrtf(ss * (1.0f / HD) + EPS);

    int   dp  = (d < HD/2) ? d + HD/2 : d - HD/2;
    float xp  = src[dp];
    float xn  = x  * rms * w[d];
    float xpn = xp * rms * w[dp];
    float rot = (d < HD/2) ? -xpn : xpn;
    float c = cosb[(size_t)l * HD + d];
    float s = sinb[(size_t)l * HD + d];
    size_t dst = (((size_t)b * NKV + h) * LL + l) * HD + d;
    g_k16[dst] = __float2half_rn(xn * c + rot * s);
    g_v16[dst] = __float2half_rn(qkv[(size_t)row * NQKV + 2 * INNER + NKV * HD + h * HD + d]);
}

// ---------------- mma flash attention + fused gate + packed-A epilogue ------
constexpr int QTILE = 64;
constexpr int KTILE = 16;
constexpr int QS_LD = 264;
constexpr int KS_LD = 264;
constexpr int ATT_SMEM = (QTILE * QS_LD + 2 * KTILE * KS_LD) * 2;  // 50688

__global__ void __launch_bounds__(128) attn_mma()
{
    extern __shared__ __half sm[];
    __half* Qs = sm;                        // [64][264]
    __half* Ks = Qs + QTILE * QS_LD;        // [16][264]
    __half* Vs = Ks + KTILE * KS_LD;        // [16][264] row-major (ldmatrix.trans)

    const int b  = blockIdx.z, h = blockIdx.y;
    const int q0 = (gridDim.x - 1 - blockIdx.x) * QTILE;   // heavy CTAs first
    const int kv = h >> 2;
    const int tid = threadIdx.x, wid = tid >> 5, lane = tid & 31;
    const int g = lane >> 2, t = lane & 3;
    const int wr = wid * 16;

    const __half* Qg = g_q16 + (((size_t)b * NH  + h)  * LL + q0) * HD;
    const __half* Kg = g_k16 + (((size_t)b * NKV + kv) * LL) * HD;
    const __half* Vg = g_v16 + (((size_t)b * NKV + kv) * LL) * HD;

    // stage Q once
    #pragma unroll
    for (int i = 0; i < 16; i++) {
        int idx = tid + i * 128;
        int r = idx >> 5, c = (idx & 31) * 8;
        *(uint4*)&Qs[r * QS_LD + c] = *(const uint4*)&Qg[(size_t)r * HD + c];
    }

    const uint32_t sVrow = (uint32_t)__cvta_generic_to_shared(Vs)
                           + (uint32_t)(lane & 15) * KS_LD * 2;

    float m2[2]   = {-1e30f, -1e30f};
    float lrow[2] = {0.f, 0.f};
    float O[32][4];
    #pragma unroll
    for (int n = 0; n < 32; n++) { O[n][0] = O[n][1] = O[n][2] = O[n][3] = 0.f; }

    const float cscale = 0.09016994f;       // (1/16) * log2(e)
    const int ntiles = q0 / KTILE + 4;

    for (int tile = 0; tile < ntiles; tile++) {
        const int kb = tile * KTILE;
        __syncthreads();
        #pragma unroll
        for (int i = 0; i < 4; i++) {
            int idx = tid + i * 128;
            int r = idx >> 5, c = (idx & 31) * 8;
            *(uint4*)&Ks[r * KS_LD + c] = *(const uint4*)&Kg[(size_t)(kb + r) * HD + c];
            *(uint4*)&Vs[r * KS_LD + c] = *(const uint4*)&Vg[(size_t)(kb + r) * HD + c];
        }
        __syncthreads();

        if (kb > q0 + wr + 15) continue;

        // ---- QK^T ----
        float s[2][4] = {{0.f,0.f,0.f,0.f},{0.f,0.f,0.f,0.f}};
        #pragma unroll
        for (int c = 0; c < 16; c++) {
            const int col = c * 16 + 2 * t;
            uint32_t a0 = *(const uint32_t*)&Qs[(wr + g)     * QS_LD + col];
            uint32_t a1 = *(const uint32_t*)&Qs[(wr + 8 + g) * QS_LD + col];
            uint32_t a2 = *(const uint32_t*)&Qs[(wr + g)     * QS_LD + col + 8];
            uint32_t a3 = *(const uint32_t*)&Qs[(wr + 8 + g) * QS_LD + col + 8];
            #pragma unroll
            for (int nt = 0; nt < 2; nt++) {
                uint32_t b0 = *(const uint32_t*)&Ks[(nt * 8 + g) * KS_LD + col];
                uint32_t b1 = *(const uint32_t*)&Ks[(nt * 8 + g) * KS_LD + col + 8];
                mma16(s[nt], a0, a1, a2, a3, b0, b1);
            }
        }

        // ---- causal mask ----
        if (kb + 15 > q0 + wr) {
            int r0 = q0 + wr + g, r8 = r0 + 8;
            #pragma unroll
            for (int nt = 0; nt < 2; nt++) {
                int kp = kb + nt * 8 + 2 * t;
                if (kp     > r0) s[nt][0] = -1e30f;
                if (kp + 1 > r0) s[nt][1] = -1e30f;
                if (kp     > r8) s[nt][2] = -1e30f;
                if (kp + 1 > r8) s[nt][3] = -1e30f;
            }
        }

        // ---- online softmax ----
        float r0m = fmaxf(fmaxf(s[0][0], s[0][1]), fmaxf(s[1][0], s[1][1]));
        float r8m = fmaxf(fmaxf(s[0][2], s[0][3]), fmaxf(s[1][2], s[1][3]));
        r0m = fmaxf(r0m, __shfl_xor_sync(0xffffffffu, r0m, 1));
        r0m = fmaxf(r0m, __shfl_xor_sync(0xffffffffu, r0m, 2));
        r8m = fmaxf(r8m, __shfl_xor_sync(0xffffffffu, r8m, 1));
        r8m = fmaxf(r8m, __shfl_xor_sync(0xffffffffu, r8m, 2));
        float m2n0 = fmaxf(m2[0], r0m * cscale);
        float m2n8 = fmaxf(m2[1], r8m * cscale);
        float corr0 = ex2f(m2[0] - m2n0);
        float corr8 = ex2f(m2[1] - m2n8);
        m2[0] = m2n0; m2[1] = m2n8;

        float p[2][4];
        #pragma unroll
        for (int nt = 0; nt < 2; nt++) {
            p[nt][0] = ex2f(fmaf(s[nt][0], cscale, -m2n0));
            p[nt][1] = ex2f(fmaf(s[nt][1], cscale, -m2n0));
            p[nt][2] = ex2f(fmaf(s[nt][2], cscale, -m2n8));
            p[nt][3] = ex2f(fmaf(s[nt][3], cscale, -m2n8));
        }
        lrow[0] = lrow[0] * corr0 + (p[0][0] + p[0][1]) + (p[1][0] + p[1][1]);
        lrow[1] = lrow[1] * corr8 + (p[0][2] + p[0][3]) + (p[1][2] + p[1][3]);

        __half2 h0 = __float22half2_rn(make_float2(p[0][0], p[0][1]));
        __half2 h1 = __float22half2_rn(make_float2(p[0][2], p[0][3]));
        __half2 h2 = __float22half2_rn(make_float2(p[1][0], p[1][1]));
        __half2 h3 = __float22half2_rn(make_float2(p[1][2], p[1][3]));
        uint32_t pa0 = *(uint32_t*)&h0;
        uint32_t pa1 = *(uint32_t*)&h1;
        uint32_t pa2 = *(uint32_t*)&h2;
        uint32_t pa3 = *(uint32_t*)&h3;

        #pragma unroll
        for (int n = 0; n < 32; n++) {
            O[n][0] *= corr0; O[n][1] *= corr0;
            O[n][2] *= corr8; O[n][3] *= corr8;
            uint32_t b0, b1;
            ldsm_x2_t(b0, b1, sVrow + n * 16);
            mma16(O[n], pa0, pa1, pa2, pa3, b0, b1);
        }
    }

    // ---- fused epilogue: 1/l, silu(gate), pack fp16 A-fragments ----
    float l0 = lrow[0];
    l0 += __shfl_xor_sync(0xffffffffu, l0, 1);
    l0 += __shfl_xor_sync(0xffffffffu, l0, 2);
    float l8 = lrow[1];
    l8 += __shfl_xor_sync(0xffffffffu, l8, 1);
    l8 += __shfl_xor_sync(0xffffffffu, l8, 2);
    float inv0 = __fdividef(1.f, l0);
    float inv8 = __fdividef(1.f, l8);

    const int r0l = q0 + wr + g;
    const int mt  = (b * LL + q0 + wr) >> 7;
    const int mb  = ((q0 & 64) >> 4) + wid;
    const float* gate0 = g_qkv + (size_t)(b * LL + r0l) * NQKV + INNER + h * HD;
    const float* gate8 = gate0 + (size_t)8 * NQKV;

    #pragma unroll
    for (int n = 0; n < 32; n += 2) {
        int kt = h * 8 + (n >> 2);
        int ks = (n >> 1) & 1;
        size_t off = (((size_t)mt * 128 + kt) * 512 + (ks * 8 + mb) * 32 + lane) * 8;
        int c0 = n * 8 + 2 * t;
        float2 gA0 = *(const float2*)&gate0[c0];
        float2 gB0 = *(const float2*)&gate8[c0];
        float2 gA1 = *(const float2*)&gate0[c0 + 8];
        float2 gB1 = *(const float2*)&gate8[c0 + 8];
        float sA0x = gA0.x / (1.f + __expf(-gA0.x));
        float sA0y = gA0.y / (1.f + __expf(-gA0.y));
        float sB0x = gB0.x / (1.f + __expf(-gB0.x));
        float sB0y = gB0.y / (1.f + __expf(-gB0.y));
        float sA1x = gA1.x / (1.f + __expf(-gA1.x));
        float sA1y = gA1.y / (1.f + __expf(-gA1.y));
        float sB1x = gB1.x / (1.f + __expf(-gB1.x));
        float sB1y = gB1.y / (1.f + __expf(-gB1.y));
        __half hb[8];
        hb[0] = __float2half_rn(O[n][0]     * inv0 * sA0x);
        hb[1] = __float2half_rn(O[n][1]     * inv0 * sA0y);
        hb[2] = __float2half_rn(O[n][2]     * inv8 * sB0x);
        hb[3] = __float2half_rn(O[n][3]     * inv8 * sB0y);
        hb[4] = __float2half_rn(O[n + 1][0] * inv0 * sA1x);
        hb[5] = __float2half_rn(O[n + 1][1] * inv0 * sA1y);
        hb[6] = __float2half_rn(O[n + 1][2] * inv8 * sB1x);
        hb[7] = __float2half_rn(O[n + 1][3] * inv8 * sB1y);
        *(uint4*)&g_attp[off] = *(uint4*)hb;
    }
}

// ---------------- launch ----------------------------------------------------
extern "C" void kernel_launch(void* const* d_in, const int* in_sizes, int n_in,
                              void* d_out, int out_size)
{
    const float* X    = (const float*)d_in[0];
    const float* cosb = (const float*)d_in[1];
    const float* sinb = (const float*)d_in[2];
    const float* Wq   = (const float*)d_in[3];
    const float* Wk   = (const float*)d_in[4];
    const float* Wv   = (const float*)d_in[5];
    const float* Wo   = (const float*)d_in[6];
    const float* qw   = (const float*)d_in[7];
    const float* kw   = (const float*)d_in[8];
    float* out = (float*)d_out;

    float* qkv;
    __half *xp, *attp, *wqkvp, *wop;
    cudaGetSymbolAddress((void**)&qkv,   g_qkv);
    cudaGetSymbolAddress((void**)&xp,    g_xp);
    cudaGetSymbolAddress((void**)&attp,  g_attp);
    cudaGetSymbolAddress((void**)&wqkvp, g_wqkvp);
    cudaGetSymbolAddress((void**)&wop,   g_wop);

    static bool attr_set = false;
    if (!attr_set) {
        cudaFuncSetAttribute(gemm_tc, cudaFuncAttributeMaxDynamicSharedMemorySize,
                             GEMM_SMEM);
        cudaFuncSetAttribute(attn_mma, cudaFuncAttributeMaxDynamicSharedMemorySize,
                             ATT_SMEM);
        attr_set = true;
    }

    constexpr int KTH = HID / 32;
    __half* wq_dst = wqkvp;
    __half* wk_dst = wqkvp + (size_t)(2 * INNER / 128) * KTH * 4096;
    __half* wv_dst = wk_dst + (size_t)(NKV * HD / 128) * KTH * 4096;

    // 0) operand packing
    pack_a<<<(unsigned)((size_t)ROWS * HID      / 2048), 256>>>(X,  xp,  HID);
    pack_b<<<(unsigned)((size_t)HID * 2 * INNER / 2048), 256>>>(Wq, wq_dst, HID, 2 * INNER);
    pack_b<<<(unsigned)((size_t)HID * NKV * HD  / 2048), 256>>>(Wk, wk_dst, HID, NKV * HD);
    pack_b<<<(unsigned)((size_t)HID * NKV * HD  / 2048), 256>>>(Wv, wv_dst, HID, NKV * HD);
    pack_b<<<(unsigned)((size_t)INNER * HID     / 2048), 256>>>(Wo, wop, INNER, HID);

    // 1) fused QKV projection
    gemm_tc<<<dim3(NQKV / 128, ROWS / 128), 128, GEMM_SMEM>>>(xp, wqkvp, qkv, HID, NQKV);

    // 2) per-head RMSNorm + RoPE -> fp16
    q_prep <<<dim3(ROWS, NH),  256>>>(qkv, cosb, sinb, qw);
    kv_prep<<<dim3(ROWS, NKV), 256>>>(qkv, cosb, sinb, kw);

    // 3) mma flash attention (+ gate + pack fused in epilogue)
    attn_mma<<<dim3(LL / QTILE, NH, BB), 128, ATT_SMEM>>>();

    // 4) output projection
    gemm_tc<<<dim3(HID / 128, ROWS / 128), 128, GEMM_SMEM>>>(attp, wop, out, INNER, HID);
}

// round 12
// speedup vs baseline: 10.8856x; 1.0247x over previous
#include <cuda_runtime.h>
#include <cuda_fp16.h>
#include <math.h>
#include <stdint.h>

// ---------------- problem constants ----------------
constexpr int BB     = 2;
constexpr int LL     = 2048;
constexpr int HID    = 2560;
constexpr int NH     = 16;
constexpr int NKV    = 4;
constexpr int HD     = 256;
constexpr int GQA    = NH / NKV;      // 4
constexpr int INNER  = NH * HD;       // 4096
constexpr int ROWS   = BB * LL;       // 4096
constexpr int NQKV   = 2 * INNER + 2 * NKV * HD;   // 10240
constexpr float EPS  = 1e-6f;

// ---------------- scratch (device globals) ----------------------------------
__device__ float  g_qkv [(size_t)ROWS * NQKV];       // fused q|gate|k|v
__device__ __half g_q16 [(size_t)BB * NH  * LL * HD];
__device__ __half g_k16 [(size_t)BB * NKV * LL * HD];
__device__ __half g_v16 [(size_t)BB * NKV * LL * HD];
// fragment-packed fp16 GEMM operands
__device__ __half g_xp   [(size_t)ROWS * HID];
__device__ __half g_attp [(size_t)ROWS * INNER];     // written by attn epilogue
__device__ __half g_wqkvp[(size_t)HID * NQKV];
__device__ __half g_wop  [(size_t)INNER * HID];

// ================= mma / ldmatrix helpers ====================================
__device__ __forceinline__ void mma16(float* d, uint32_t a0, uint32_t a1,
                                      uint32_t a2, uint32_t a3,
                                      uint32_t b0, uint32_t b1) {
    asm volatile(
        "mma.sync.aligned.m16n8k16.row.col.f32.f16.f16.f32 "
        "{%0,%1,%2,%3}, {%4,%5,%6,%7}, {%8,%9}, {%0,%1,%2,%3};"
        : "+f"(d[0]), "+f"(d[1]), "+f"(d[2]), "+f"(d[3])
        : "r"(a0), "r"(a1), "r"(a2), "r"(a3), "r"(b0), "r"(b1));
}

__device__ __forceinline__ void ldsm_x2_t(uint32_t& r0, uint32_t& r1, uint32_t addr) {
    asm volatile("ldmatrix.sync.aligned.m8n8.x2.trans.shared.b16 {%0,%1}, [%2];"
                 : "=r"(r0), "=r"(r1) : "r"(addr));
}

__device__ __forceinline__ void ldsm_x4(uint32_t& r0, uint32_t& r1,
                                        uint32_t& r2, uint32_t& r3, uint32_t addr) {
    asm volatile("ldmatrix.sync.aligned.m8n8.x4.shared.b16 {%0,%1,%2,%3}, [%4];"
                 : "=r"(r0), "=r"(r1), "=r"(r2), "=r"(r3) : "r"(addr));
}

__device__ __forceinline__ float ex2f(float x) {
    float r; asm("ex2.approx.f32 %0, %1;" : "=f"(r) : "f"(x));
    return r;
}

// ================= operand packing (fp16 fragment layout) ====================
__global__ void __launch_bounds__(256) pack_a(
    const float* __restrict__ A, __half* __restrict__ Ap, int K)
{
    size_t slot = (size_t)blockIdx.x * 256 + threadIdx.x;
    int lane = slot & 31, mb = (slot >> 5) & 7, ks = (slot >> 8) & 1;
    size_t rest = slot >> 9;
    int KT = K / 32;
    int kt = (int)(rest % KT), mt = (int)(rest / KT);
    int g = lane >> 2, t = lane & 3;
    int row = mt * 128 + mb * 16 + g;
    int col = kt * 32 + ks * 16 + 2 * t;
    const float* r0 = &A[(size_t)row * K + col];
    const float* r1 = &A[(size_t)(row + 8) * K + col];
    __half h[8];
    h[0] = __float2half_rn(r0[0]); h[1] = __float2half_rn(r0[1]);
    h[2] = __float2half_rn(r1[0]); h[3] = __float2half_rn(r1[1]);
    h[4] = __float2half_rn(r0[8]); h[5] = __float2half_rn(r0[9]);
    h[6] = __float2half_rn(r1[8]); h[7] = __float2half_rn(r1[9]);
    *(uint4*)&Ap[slot * 8] = *(uint4*)h;
}

__global__ void __launch_bounds__(256) pack_b(
    const float* __restrict__ Bm, __half* __restrict__ Bp, int K, int N)
{
    size_t slot = (size_t)blockIdx.x * 256 + threadIdx.x;
    int lane = slot & 31, q = (slot >> 5) & 7, ks = (slot >> 8) & 1;
    size_t rest = slot >> 9;
    int KT = K / 32;
    int kt = (int)(rest % KT), nt = (int)(rest / KT);
    int g = lane >> 2, t = lane & 3;
    int k  = kt * 32 + ks * 16 + 2 * t;
    int n0 = nt * 128 + q * 16 + g;
    int n1 = n0 + 8;
    __half h[8];
    h[0] = __float2half_rn(Bm[(size_t)k * N + n0]);
    h[1] = __float2half_rn(Bm[(size_t)(k + 1) * N + n0]);
    h[2] = __float2half_rn(Bm[(size_t)(k + 8) * N + n0]);
    h[3] = __float2half_rn(Bm[(size_t)(k + 9) * N + n0]);
    h[4] = __float2half_rn(Bm[(size_t)k * N + n1]);
    h[5] = __float2half_rn(Bm[(size_t)(k + 1) * N + n1]);
    h[6] = __float2half_rn(Bm[(size_t)(k + 8) * N + n1]);
    h[7] = __float2half_rn(Bm[(size_t)(k + 9) * N + n1]);
    *(uint4*)&Bp[slot * 8] = *(uint4*)h;
}

// ================= fp16 mma GEMM: 4 warps, warp tile 64x64 ===================
constexpr int NSTG   = 4;
constexpr int ASTG_B = 8192;
constexpr int BSTG_B = 8192;
constexpr int GEMM_SMEM = NSTG * (ASTG_B + BSTG_B);   // 65536

__device__ __forceinline__ void cp16(uint32_t dst, const void* src) {
    asm volatile("cp.async.cg.shared.global [%0], [%1], 16;" :: "r"(dst), "l"(src));
}

__global__ void __launch_bounds__(128) gemm_tc(
    const __half* __restrict__ Ap, const __half* __restrict__ Bp,
    float* __restrict__ C, int K, int ldc)
{
    extern __shared__ char smem[];
    char* Abuf = smem;
    char* Bbuf = smem + NSTG * ASTG_B;
    const uint32_t sA = (uint32_t)__cvta_generic_to_shared(Abuf);
    const uint32_t sB = (uint32_t)__cvta_generic_to_shared(Bbuf);

    const int tid  = threadIdx.x;
    const int wid  = tid >> 5;
    const int lane = tid & 31;
    const int wm   = wid & 1;
    const int wn   = wid >> 1;
    const int g    = lane >> 2;
    const int t    = lane & 3;
    const int KT   = K / 32;

    const size_t abase = (size_t)blockIdx.y * KT * 4096;
    const size_t bbase = (size_t)blockIdx.x * KT * 4096;

    float d[4][8][4];
    #pragma unroll
    for (int i = 0; i < 4; i++)
        #pragma unroll
        for (int j = 0; j < 8; j++)
            #pragma unroll
            for (int r = 0; r < 4; r++) d[i][j][r] = 0.f;

    auto stage = [&](int buf, int s) {
        #pragma unroll
        for (int i = 0; i < 4; i++) {
            int idx = tid + i * 128;
            cp16(sA + (uint32_t)(buf * ASTG_B + idx * 16),
                 Ap + abase + (size_t)s * 4096 + idx * 8);
            cp16(sB + (uint32_t)(buf * BSTG_B + idx * 16),
                 Bp + bbase + (size_t)s * 4096 + idx * 8);
        }
        asm volatile("cp.async.commit_group;" ::: "memory");
    };

    stage(0, 0);
    stage(1, 1);
    stage(2, 2);

    for (int s = 0; s < KT; s++) {
        asm volatile("cp.async.wait_group 2;" ::: "memory");
        __syncthreads();
        if (s + 3 < KT) stage((s + 3) & (NSTG - 1), s + 3);
        else asm volatile("cp.async.commit_group;" ::: "memory");

        const uint4* At = (const uint4*)(Abuf + (s & (NSTG - 1)) * ASTG_B);
        const uint4* Bt = (const uint4*)(Bbuf + (s & (NSTG - 1)) * BSTG_B);
        #pragma unroll
        for (int ks = 0; ks < 2; ks++) {
            uint4 a[4], bb[4];
            #pragma unroll
            for (int i = 0; i < 4; i++)
                a[i] = At[(ks * 8 + wm * 4 + i) * 32 + lane];
            #pragma unroll
            for (int p = 0; p < 4; p++)
                bb[p] = Bt[(ks * 8 + wn * 4 + p) * 32 + lane];
            #pragma unroll
            for (int i = 0; i < 4; i++)
                #pragma unroll
                for (int p = 0; p < 4; p++) {
                    mma16(d[i][2 * p],     a[i].x, a[i].y, a[i].z, a[i].w, bb[p].x, bb[p].y);
                    mma16(d[i][2 * p + 1], a[i].x, a[i].y, a[i].z, a[i].w, bb[p].z, bb[p].w);
                }
        }
    }

    #pragma unroll
    for (int i = 0; i < 4; i++) {
        int r = blockIdx.y * 128 + wm * 64 + i * 16 + g;
        #pragma unroll
        for (int j = 0; j < 8; j++) {
            int c = blockIdx.x * 128 + wn * 64 + j * 8 + 2 * t;
            *(float2*)&C[(size_t)r * ldc + c]       = make_float2(d[i][j][0], d[i][j][1]);
            *(float2*)&C[(size_t)(r + 8) * ldc + c] = make_float2(d[i][j][2], d[i][j][3]);
        }
    }
}

// ---------------- warp-level per-head RMSNorm + RoPE (fp16 outputs) ---------
// Warp owns one (row, head); lane owns dims d = lane + 32j. RoPE partner
// d +/- 128 is the lane's own register j^4 -> no smem, no block sync.
__device__ __forceinline__ float warp_sumsq(const float* x)
{
    float ss = 0.f;
    #pragma unroll
    for (int j = 0; j < 8; j++) ss = fmaf(x[j], x[j], ss);
    #pragma unroll
    for (int o = 16; o; o >>= 1) ss += __shfl_xor_sync(0xffffffffu, ss, o);
    return ss;
}

__global__ void __launch_bounds__(256) q_prep(
    const float* __restrict__ qkv, const float* __restrict__ cosb,
    const float* __restrict__ sinb, const float* __restrict__ w)
{
    int row  = blockIdx.x;
    int h    = blockIdx.y * 8 + (threadIdx.x >> 5);
    int lane = threadIdx.x & 31;
    int l    = row & (LL - 1), b = row >> 11;

    const float* src = qkv + (size_t)row * NQKV + h * HD;
    float x[8];
    #pragma unroll
    for (int j = 0; j < 8; j++) x[j] = src[lane + 32 * j];
    float rms = rsqrtf(warp_sumsq(x) * (1.0f / HD) + EPS);

    float xn[8];
    #pragma unroll
    for (int j = 0; j < 8; j++) xn[j] = x[j] * rms * w[lane + 32 * j];

    __half* dst = g_q16 + (((size_t)b * NH + h) * LL + l) * HD;
    #pragma unroll
    for (int j = 0; j < 8; j++) {
        int   d   = lane + 32 * j;
        float rot = (j < 4) ? -xn[j + 4] : xn[j - 4];
        float c   = cosb[(size_t)l * HD + d];
        float s   = sinb[(size_t)l * HD + d];
        dst[d] = __float2half_rn(xn[j] * c + rot * s);
    }
}

__global__ void __launch_bounds__(256) kv_prep(
    const float* __restrict__ qkv, const float* __restrict__ cosb,
    const float* __restrict__ sinb, const float* __restrict__ w)
{
    int row  = blockIdx.x;
    int wid  = threadIdx.x >> 5;
    int lane = threadIdx.x & 31;
    int l    = row & (LL - 1), b = row >> 11;

    if (wid < 4) {                            // K: norm + rope
        int h = wid;
        const float* src = qkv + (size_t)row * NQKV + 2 * INNER + h * HD;
        float x[8];
        #pragma unroll
        for (int j = 0; j < 8; j++) x[j] = src[lane + 32 * j];
        float rms = rsqrtf(warp_sumsq(x) * (1.0f / HD) + EPS);
        float xn[8];
        #pragma unroll
        for (int j = 0; j < 8; j++) xn[j] = x[j] * rms * w[lane + 32 * j];
        __half* dst = g_k16 + (((size_t)b * NKV + h) * LL + l) * HD;
        #pragma unroll
        for (int j = 0; j < 8; j++) {
            int   d   = lane + 32 * j;
            float rot = (j < 4) ? -xn[j + 4] : xn[j - 4];
            float c   = cosb[(size_t)l * HD + d];
            float s   = sinb[(size_t)l * HD + d];
            dst[d] = __float2half_rn(xn[j] * c + rot * s);
        }
    } else {                                  // V: fp32 -> fp16 copy
        int h = wid - 4;
        const float* src = qkv + (size_t)row * NQKV + 2 * INNER + NKV * HD + h * HD;
        __half* dst = g_v16 + (((size_t)b * NKV + h) * LL + l) * HD;
        #pragma unroll
        for (int j = 0; j < 8; j++) {
            int d = lane + 32 * j;
            dst[d] = __float2half_rn(src[d]);
        }
    }
}

// ---------------- mma flash attention + fused gate + packed-A epilogue ------
constexpr int QTILE = 64;
constexpr int KTILE = 16;
constexpr int QS_LD = 264;
constexpr int KS_LD = 264;
constexpr int ATT_SMEM = (QTILE * QS_LD + 2 * KTILE * KS_LD) * 2;  // 50688

__global__ void __launch_bounds__(128) attn_mma()
{
    extern __shared__ __half sm[];
    __half* Qs = sm;                        // [64][264]
    __half* Ks = Qs + QTILE * QS_LD;        // [16][264]
    __half* Vs = Ks + KTILE * KS_LD;        // [16][264] row-major (ldmatrix.trans)

    const int b  = blockIdx.z, h = blockIdx.y;
    const int q0 = (gridDim.x - 1 - blockIdx.x) * QTILE;   // heavy CTAs first
    const int kv = h >> 2;
    const int tid = threadIdx.x, wid = tid >> 5, lane = tid & 31;
    const int g = lane >> 2, t = lane & 3;
    const int wr = wid * 16;

    const __half* Qg = g_q16 + (((size_t)b * NH  + h)  * LL + q0) * HD;
    const __half* Kg = g_k16 + (((size_t)b * NKV + kv) * LL) * HD;
    const __half* Vg = g_v16 + (((size_t)b * NKV + kv) * LL) * HD;

    // stage Q once
    #pragma unroll
    for (int i = 0; i < 16; i++) {
        int idx = tid + i * 128;
        int r = idx >> 5, c = (idx & 31) * 8;
        *(uint4*)&Qs[r * QS_LD + c] = *(const uint4*)&Qg[(size_t)r * HD + c];
    }

    // ldmatrix source addresses (bytes)
    const int lrow = ((lane >> 3) & 1) * 8 + (lane & 7);   // row within 16
    const int lcol = (lane >> 4) * 8;                      // col half (0 / 8)
    const uint32_t sQfrag = (uint32_t)__cvta_generic_to_shared(Qs)
                            + (uint32_t)(wr + lrow) * (QS_LD * 2) + lcol * 2;
    const uint32_t sKfrag = (uint32_t)__cvta_generic_to_shared(Ks)
                            + (uint32_t)lrow * (KS_LD * 2) + lcol * 2;
    const uint32_t sVrow  = (uint32_t)__cvta_generic_to_shared(Vs)
                            + (uint32_t)(lane & 15) * KS_LD * 2;

    float m2[2]   = {-1e30f, -1e30f};
    float lrowv[2] = {0.f, 0.f};
    float O[32][4];
    #pragma unroll
    for (int n = 0; n < 32; n++) { O[n][0] = O[n][1] = O[n][2] = O[n][3] = 0.f; }

    const float cscale = 0.09016994f;       // (1/16) * log2(e)
    const int ntiles = q0 / KTILE + 4;

    for (int tile = 0; tile < ntiles; tile++) {
        const int kb = tile * KTILE;
        __syncthreads();
        #pragma unroll
        for (int i = 0; i < 4; i++) {
            int idx = tid + i * 128;
            int r = idx >> 5, c = (idx & 31) * 8;
            *(uint4*)&Ks[r * KS_LD + c] = *(const uint4*)&Kg[(size_t)(kb + r) * HD + c];
            *(uint4*)&Vs[r * KS_LD + c] = *(const uint4*)&Vg[(size_t)(kb + r) * HD + c];
        }
        __syncthreads();

        if (kb > q0 + wr + 15) continue;

        // ---- QK^T via ldmatrix.x4 (1 Q-frag + 4 K b-frags per k-chunk) ----
        float s[2][4] = {{0.f,0.f,0.f,0.f},{0.f,0.f,0.f,0.f}};
        #pragma unroll
        for (int c = 0; c < 16; c++) {
            uint32_t a0, a1, a2, a3, k0, k1, k2, k3;
            ldsm_x4(a0, a1, a2, a3, sQfrag + c * 32);
            ldsm_x4(k0, k1, k2, k3, sKfrag + c * 32);
            mma16(s[0], a0, a1, a2, a3, k0, k2);
            mma16(s[1], a0, a1, a2, a3, k1, k3);
        }

        // ---- causal mask ----
        if (kb + 15 > q0 + wr) {
            int r0 = q0 + wr + g, r8 = r0 + 8;
            #pragma unroll
            for (int nt = 0; nt < 2; nt++) {
                int kp = kb + nt * 8 + 2 * t;
                if (kp     > r0) s[nt][0] = -1e30f;
                if (kp + 1 > r0) s[nt][1] = -1e30f;
                if (kp     > r8) s[nt][2] = -1e30f;
                if (kp + 1 > r8) s[nt][3] = -1e30f;
            }
        }

        // ---- online softmax ----
        float r0m = fmaxf(fmaxf(s[0][0], s[0][1]), fmaxf(s[1][0], s[1][1]));
        float r8m = fmaxf(fmaxf(s[0][2], s[0][3]), fmaxf(s[1][2], s[1][3]));
        r0m = fmaxf(r0m, __shfl_xor_sync(0xffffffffu, r0m, 1));
        r0m = fmaxf(r0m, __shfl_xor_sync(0xffffffffu, r0m, 2));
        r8m = fmaxf(r8m, __shfl_xor_sync(0xffffffffu, r8m, 1));
        r8m = fmaxf(r8m, __shfl_xor_sync(0xffffffffu, r8m, 2));
        float m2n0 = fmaxf(m2[0], r0m * cscale);
        float m2n8 = fmaxf(m2[1], r8m * cscale);
        float corr0 = ex2f(m2[0] - m2n0);
        float corr8 = ex2f(m2[1] - m2n8);
        m2[0] = m2n0; m2[1] = m2n8;

        float p[2][4];
        #pragma unroll
        for (int nt = 0; nt < 2; nt++) {
            p[nt][0] = ex2f(fmaf(s[nt][0], cscale, -m2n0));
            p[nt][1] = ex2f(fmaf(s[nt][1], cscale, -m2n0));
            p[nt][2] = ex2f(fmaf(s[nt][2], cscale, -m2n8));
            p[nt][3] = ex2f(fmaf(s[nt][3], cscale, -m2n8));
        }
        lrowv[0] = lrowv[0] * corr0 + (p[0][0] + p[0][1]) + (p[1][0] + p[1][1]);
        lrowv[1] = lrowv[1] * corr8 + (p[0][2] + p[0][3]) + (p[1][2] + p[1][3]);

        __half2 h0 = __float22half2_rn(make_float2(p[0][0], p[0][1]));
        __half2 h1 = __float22half2_rn(make_float2(p[0][2], p[0][3]));
        __half2 h2 = __float22half2_rn(make_float2(p[1][0], p[1][1]));
        __half2 h3 = __float22half2_rn(make_float2(p[1][2], p[1][3]));
        uint32_t pa0 = *(uint32_t*)&h0;
        uint32_t pa1 = *(uint32_t*)&h1;
        uint32_t pa2 = *(uint32_t*)&h2;
        uint32_t pa3 = *(uint32_t*)&h3;

        #pragma unroll
        for (int n = 0; n < 32; n++) {
            O[n][0] *= corr0; O[n][1] *= corr0;
            O[n][2] *= corr8; O[n][3] *= corr8;
            uint32_t b0, b1;
            ldsm_x2_t(b0, b1, sVrow + n * 16);
            mma16(O[n], pa0, pa1, pa2, pa3, b0, b1);
        }
    }

    // ---- fused epilogue: 1/l, silu(gate), pack fp16 A-fragments ----
    float l0 = lrowv[0];
    l0 += __shfl_xor_sync(0xffffffffu, l0, 1);
    l0 += __shfl_xor_sync(0xffffffffu, l0, 2);
    float l8 = lrowv[1];
    l8 += __shfl_xor_sync(0xffffffffu, l8, 1);
    l8 += __shfl_xor_sync(0xffffffffu, l8, 2);
    float inv0 = __fdividef(1.f, l0);
    float inv8 = __fdividef(1.f, l8);

    const int r0l = q0 + wr + g;
    const int mt  = (b * LL + q0 + wr) >> 7;
    const int mb  = ((q0 & 64) >> 4) + wid;
    const float* gate0 = g_qkv + (size_t)(b * LL + r0l) * NQKV + INNER + h * HD;
    const float* gate8 = gate0 + (size_t)8 * NQKV;

    #pragma unroll
    for (int n = 0; n < 32; n += 2) {
        int kt = h * 8 + (n >> 2);
        int ks = (n >> 1) & 1;
        size_t off = (((size_t)mt * 128 + kt) * 512 + (ks * 8 + mb) * 32 + lane) * 8;
        int c0 = n * 8 + 2 * t;
        float2 gA0 = *(const float2*)&gate0[c0];
        float2 gB0 = *(const float2*)&gate8[c0];
        float2 gA1 = *(const float2*)&gate0[c0 + 8];
        float2 gB1 = *(const float2*)&gate8[c0 + 8];
        float sA0x = gA0.x / (1.f + __expf(-gA0.x));
        float sA0y = gA0.y / (1.f + __expf(-gA0.y));
        float sB0x = gB0.x / (1.f + __expf(-gB0.x));
        float sB0y = gB0.y / (1.f + __expf(-gB0.y));
        float sA1x = gA1.x / (1.f + __expf(-gA1.x));
        float sA1y = gA1.y / (1.f + __expf(-gA1.y));
        float sB1x = gB1.x / (1.f + __expf(-gB1.x));
        float sB1y = gB1.y / (1.f + __expf(-gB1.y));
        __half hb[8];
        hb[0] = __float2half_rn(O[n][0]     * inv0 * sA0x);
        hb[1] = __float2half_rn(O[n][1]     * inv0 * sA0y);
        hb[2] = __float2half_rn(O[n][2]     * inv8 * sB0x);
        hb[3] = __float2half_rn(O[n][3]     * inv8 * sB0y);
        hb[4] = __float2half_rn(O[n + 1][0] * inv0 * sA1x);
        hb[5] = __float2half_rn(O[n + 1][1] * inv0 * sA1y);
        hb[6] = __float2half_rn(O[n + 1][2] * inv8 * sB1x);
        hb[7] = __float2half_rn(O[n + 1][3] * inv8 * sB1y);
        *(uint4*)&g_attp[off] = *(uint4*)hb;
    }
}

// ---------------- launch ----------------------------------------------------
extern "C" void kernel_launch(void* const* d_in, const int* in_sizes, int n_in,
                              void* d_out, int out_size)
{
    const float* X    = (const float*)d_in[0];
    const float* cosb = (const float*)d_in[1];
    const float* sinb = (const float*)d_in[2];
    const float* Wq   = (const float*)d_in[3];
    const float* Wk   = (const float*)d_in[4];
    const float* Wv   = (const float*)d_in[5];
    const float* Wo   = (const float*)d_in[6];
    const float* qw   = (const float*)d_in[7];
    const float* kw   = (const float*)d_in[8];
    float* out = (float*)d_out;

    float* qkv;
    __half *xp, *attp, *wqkvp, *wop;
    cudaGetSymbolAddress((void**)&qkv,   g_qkv);
    cudaGetSymbolAddress((void**)&xp,    g_xp);
    cudaGetSymbolAddress((void**)&attp,  g_attp);
    cudaGetSymbolAddress((void**)&wqkvp, g_wqkvp);
    cudaGetSymbolAddress((void**)&wop,   g_wop);

    static bool attr_set = false;
    if (!attr_set) {
        cudaFuncSetAttribute(gemm_tc, cudaFuncAttributeMaxDynamicSharedMemorySize,
                             GEMM_SMEM);
        cudaFuncSetAttribute(attn_mma, cudaFuncAttributeMaxDynamicSharedMemorySize,
                             ATT_SMEM);
        attr_set = true;
    }

    constexpr int KTH = HID / 32;
    __half* wq_dst = wqkvp;
    __half* wk_dst = wqkvp + (size_t)(2 * INNER / 128) * KTH * 4096;
    __half* wv_dst = wk_dst + (size_t)(NKV * HD / 128) * KTH * 4096;

    // 0) operand packing
    pack_a<<<(unsigned)((size_t)ROWS * HID      / 2048), 256>>>(X,  xp,  HID);
    pack_b<<<(unsigned)((size_t)HID * 2 * INNER / 2048), 256>>>(Wq, wq_dst, HID, 2 * INNER);
    pack_b<<<(unsigned)((size_t)HID * NKV * HD  / 2048), 256>>>(Wk, wk_dst, HID, NKV * HD);
    pack_b<<<(unsigned)((size_t)HID * NKV * HD  / 2048), 256>>>(Wv, wv_dst, HID, NKV * HD);
    pack_b<<<(unsigned)((size_t)INNER * HID     / 2048), 256>>>(Wo, wop, INNER, HID);

    // 1) fused QKV projection
    gemm_tc<<<dim3(NQKV / 128, ROWS / 128), 128, GEMM_SMEM>>>(xp, wqkvp, qkv, HID, NQKV);

    // 2) warp-level per-head RMSNorm + RoPE -> fp16
    q_prep <<<dim3(ROWS, NH / 8), 256>>>(qkv, cosb, sinb, qw);
    kv_prep<<<ROWS, 256>>>(qkv, cosb, sinb, kw);

    // 3) mma flash attention (+ gate + pack fused in epilogue)
    attn_mma<<<dim3(LL / QTILE, NH, BB), 128, ATT_SMEM>>>();

    // 4) output projection
    gemm_tc<<<dim3(HID / 128, ROWS / 128), 128, GEMM_SMEM>>>(attp, wop, out, INNER, HID);
}

// round 13
// speedup vs baseline: 11.5926x; 1.0649x over previous
#include <cuda_runtime.h>
#include <cuda_fp16.h>
#include <math.h>
#include <stdint.h>

// ---------------- problem constants ----------------
constexpr int BB     = 2;
constexpr int LL     = 2048;
constexpr int HID    = 2560;
constexpr int NH     = 16;
constexpr int NKV    = 4;
constexpr int HD     = 256;
constexpr int GQA    = NH / NKV;      // 4
constexpr int INNER  = NH * HD;       // 4096
constexpr int ROWS   = BB * LL;       // 4096
constexpr int NQKV   = 2 * INNER + 2 * NKV * HD;   // 10240
constexpr float EPS  = 1e-6f;

// ---------------- scratch (device globals) ----------------------------------
__device__ float  g_qkv [(size_t)ROWS * NQKV];       // fused q|gate|k|v
__device__ __half g_q16 [(size_t)BB * NH  * LL * HD];
__device__ __half g_k16 [(size_t)BB * NKV * LL * HD];
__device__ __half g_v16 [(size_t)BB * NKV * LL * HD];
// fragment-packed fp16 GEMM operands
__device__ __half g_xp   [(size_t)ROWS * HID];
__device__ __half g_attp [(size_t)ROWS * INNER];     // written by attn epilogue
__device__ __half g_wqkvp[(size_t)HID * NQKV];
__device__ __half g_wop  [(size_t)INNER * HID];

// ================= mma / ldmatrix helpers ====================================
__device__ __forceinline__ void mma16(float* d, uint32_t a0, uint32_t a1,
                                      uint32_t a2, uint32_t a3,
                                      uint32_t b0, uint32_t b1) {
    asm volatile(
        "mma.sync.aligned.m16n8k16.row.col.f32.f16.f16.f32 "
        "{%0,%1,%2,%3}, {%4,%5,%6,%7}, {%8,%9}, {%0,%1,%2,%3};"
        : "+f"(d[0]), "+f"(d[1]), "+f"(d[2]), "+f"(d[3])
        : "r"(a0), "r"(a1), "r"(a2), "r"(a3), "r"(b0), "r"(b1));
}

__device__ __forceinline__ void ldsm_x2_t(uint32_t& r0, uint32_t& r1, uint32_t addr) {
    asm volatile("ldmatrix.sync.aligned.m8n8.x2.trans.shared.b16 {%0,%1}, [%2];"
                 : "=r"(r0), "=r"(r1) : "r"(addr));
}

__device__ __forceinline__ void ldsm_x4(uint32_t& r0, uint32_t& r1,
                                        uint32_t& r2, uint32_t& r3, uint32_t addr) {
    asm volatile("ldmatrix.sync.aligned.m8n8.x4.shared.b16 {%0,%1,%2,%3}, [%4];"
                 : "=r"(r0), "=r"(r1), "=r"(r2), "=r"(r3) : "r"(addr));
}

__device__ __forceinline__ float ex2f(float x) {
    float r; asm("ex2.approx.f32 %0, %1;" : "=f"(r) : "f"(x));
    return r;
}

// ================= operand packing (fp16 fragment layout) ====================
__global__ void __launch_bounds__(256) pack_a(
    const float* __restrict__ A, __half* __restrict__ Ap, int K)
{
    size_t slot = (size_t)blockIdx.x * 256 + threadIdx.x;
    int lane = slot & 31, mb = (slot >> 5) & 7, ks = (slot >> 8) & 1;
    size_t rest = slot >> 9;
    int KT = K / 32;
    int kt = (int)(rest % KT), mt = (int)(rest / KT);
    int g = lane >> 2, t = lane & 3;
    int row = mt * 128 + mb * 16 + g;
    int col = kt * 32 + ks * 16 + 2 * t;
    const float* r0 = &A[(size_t)row * K + col];
    const float* r1 = &A[(size_t)(row + 8) * K + col];
    __half h[8];
    h[0] = __float2half_rn(r0[0]); h[1] = __float2half_rn(r0[1]);
    h[2] = __float2half_rn(r1[0]); h[3] = __float2half_rn(r1[1]);
    h[4] = __float2half_rn(r0[8]); h[5] = __float2half_rn(r0[9]);
    h[6] = __float2half_rn(r1[8]); h[7] = __float2half_rn(r1[9]);
    *(uint4*)&Ap[slot * 8] = *(uint4*)h;
}

__global__ void __launch_bounds__(256) pack_b(
    const float* __restrict__ Bm, __half* __restrict__ Bp, int K, int N)
{
    size_t slot = (size_t)blockIdx.x * 256 + threadIdx.x;
    int lane = slot & 31, q = (slot >> 5) & 7, ks = (slot >> 8) & 1;
    size_t rest = slot >> 9;
    int KT = K / 32;
    int kt = (int)(rest % KT), nt = (int)(rest / KT);
    int g = lane >> 2, t = lane & 3;
    int k  = kt * 32 + ks * 16 + 2 * t;
    int n0 = nt * 128 + q * 16 + g;
    int n1 = n0 + 8;
    __half h[8];
    h[0] = __float2half_rn(Bm[(size_t)k * N + n0]);
    h[1] = __float2half_rn(Bm[(size_t)(k + 1) * N + n0]);
    h[2] = __float2half_rn(Bm[(size_t)(k + 8) * N + n0]);
    h[3] = __float2half_rn(Bm[(size_t)(k + 9) * N + n0]);
    h[4] = __float2half_rn(Bm[(size_t)k * N + n1]);
    h[5] = __float2half_rn(Bm[(size_t)(k + 1) * N + n1]);
    h[6] = __float2half_rn(Bm[(size_t)(k + 8) * N + n1]);
    h[7] = __float2half_rn(Bm[(size_t)(k + 9) * N + n1]);
    *(uint4*)&Bp[slot * 8] = *(uint4*)h;
}

// ================= fp16 mma GEMM: 4 warps, warp tile 64x64 ===================
constexpr int NSTG   = 4;
constexpr int ASTG_B = 8192;
constexpr int BSTG_B = 8192;
constexpr int GEMM_SMEM = NSTG * (ASTG_B + BSTG_B);   // 65536

__device__ __forceinline__ void cp16(uint32_t dst, const void* src) {
    asm volatile("cp.async.cg.shared.global [%0], [%1], 16;" :: "r"(dst), "l"(src));
}

__global__ void __launch_bounds__(128) gemm_tc(
    const __half* __restrict__ Ap, const __half* __restrict__ Bp,
    float* __restrict__ C, int K, int ldc)
{
    extern __shared__ char smem[];
    char* Abuf = smem;
    char* Bbuf = smem + NSTG * ASTG_B;
    const uint32_t sA = (uint32_t)__cvta_generic_to_shared(Abuf);
    const uint32_t sB = (uint32_t)__cvta_generic_to_shared(Bbuf);

    const int tid  = threadIdx.x;
    const int wid  = tid >> 5;
    const int lane = tid & 31;
    const int wm   = wid & 1;
    const int wn   = wid >> 1;
    const int g    = lane >> 2;
    const int t    = lane & 3;
    const int KT   = K / 32;

    const size_t abase = (size_t)blockIdx.y * KT * 4096;
    const size_t bbase = (size_t)blockIdx.x * KT * 4096;

    float d[4][8][4];
    #pragma unroll
    for (int i = 0; i < 4; i++)
        #pragma unroll
        for (int j = 0; j < 8; j++)
            #pragma unroll
            for (int r = 0; r < 4; r++) d[i][j][r] = 0.f;

    auto stage = [&](int buf, int s) {
        #pragma unroll
        for (int i = 0; i < 4; i++) {
            int idx = tid + i * 128;
            cp16(sA + (uint32_t)(buf * ASTG_B + idx * 16),
                 Ap + abase + (size_t)s * 4096 + idx * 8);
            cp16(sB + (uint32_t)(buf * BSTG_B + idx * 16),
                 Bp + bbase + (size_t)s * 4096 + idx * 8);
        }
        asm volatile("cp.async.commit_group;" ::: "memory");
    };

    stage(0, 0);
    stage(1, 1);
    stage(2, 2);

    for (int s = 0; s < KT; s++) {
        asm volatile("cp.async.wait_group 2;" ::: "memory");
        __syncthreads();
        if (s + 3 < KT) stage((s + 3) & (NSTG - 1), s + 3);
        else asm volatile("cp.async.commit_group;" ::: "memory");

        const uint4* At = (const uint4*)(Abuf + (s & (NSTG - 1)) * ASTG_B);
        const uint4* Bt = (const uint4*)(Bbuf + (s & (NSTG - 1)) * BSTG_B);
        #pragma unroll
        for (int ks = 0; ks < 2; ks++) {
            uint4 a[4], bb[4];
            #pragma unroll
            for (int i = 0; i < 4; i++)
                a[i] = At[(ks * 8 + wm * 4 + i) * 32 + lane];
            #pragma unroll
            for (int p = 0; p < 4; p++)
                bb[p] = Bt[(ks * 8 + wn * 4 + p) * 32 + lane];
            #pragma unroll
            for (int i = 0; i < 4; i++)
                #pragma unroll
                for (int p = 0; p < 4; p++) {
                    mma16(d[i][2 * p],     a[i].x, a[i].y, a[i].z, a[i].w, bb[p].x, bb[p].y);
                    mma16(d[i][2 * p + 1], a[i].x, a[i].y, a[i].z, a[i].w, bb[p].z, bb[p].w);
                }
        }
    }

    #pragma unroll
    for (int i = 0; i < 4; i++) {
        int r = blockIdx.y * 128 + wm * 64 + i * 16 + g;
        #pragma unroll
        for (int j = 0; j < 8; j++) {
            int c = blockIdx.x * 128 + wn * 64 + j * 8 + 2 * t;
            *(float2*)&C[(size_t)r * ldc + c]       = make_float2(d[i][j][0], d[i][j][1]);
            *(float2*)&C[(size_t)(r + 8) * ldc + c] = make_float2(d[i][j][2], d[i][j][3]);
        }
    }
}

// ---------------- fused warp-level RMSNorm + RoPE (Q,K) + V copy ------------
// One block per row, 24 warps: 0-15 Q heads, 16-19 K heads, 20-23 V heads.
__device__ __forceinline__ float warp_sumsq(const float* x)
{
    float ss = 0.f;
    #pragma unroll
    for (int j = 0; j < 8; j++) ss = fmaf(x[j], x[j], ss);
    #pragma unroll
    for (int o = 16; o; o >>= 1) ss += __shfl_xor_sync(0xffffffffu, ss, o);
    return ss;
}

__global__ void __launch_bounds__(768) qkv_prep(
    const float* __restrict__ qkv, const float* __restrict__ cosb,
    const float* __restrict__ sinb, const float* __restrict__ qw,
    const float* __restrict__ kw)
{
    int row  = blockIdx.x;
    int wid  = threadIdx.x >> 5;
    int lane = threadIdx.x & 31;
    int l    = row & (LL - 1), b = row >> 11;

    if (wid < 16) {                           // Q heads
        int h = wid;
        const float* src = qkv + (size_t)row * NQKV + h * HD;
        float x[8];
        #pragma unroll
        for (int j = 0; j < 8; j++) x[j] = src[lane + 32 * j];
        float rms = rsqrtf(warp_sumsq(x) * (1.0f / HD) + EPS);
        float xn[8];
        #pragma unroll
        for (int j = 0; j < 8; j++) xn[j] = x[j] * rms * qw[lane + 32 * j];
        __half* dst = g_q16 + (((size_t)b * NH + h) * LL + l) * HD;
        #pragma unroll
        for (int j = 0; j < 8; j++) {
            int   d   = lane + 32 * j;
            float rot = (j < 4) ? -xn[j + 4] : xn[j - 4];
            float c   = cosb[(size_t)l * HD + d];
            float s   = sinb[(size_t)l * HD + d];
            dst[d] = __float2half_rn(xn[j] * c + rot * s);
        }
    } else if (wid < 20) {                    // K heads
        int h = wid - 16;
        const float* src = qkv + (size_t)row * NQKV + 2 * INNER + h * HD;
        float x[8];
        #pragma unroll
        for (int j = 0; j < 8; j++) x[j] = src[lane + 32 * j];
        float rms = rsqrtf(warp_sumsq(x) * (1.0f / HD) + EPS);
        float xn[8];
        #pragma unroll
        for (int j = 0; j < 8; j++) xn[j] = x[j] * rms * kw[lane + 32 * j];
        __half* dst = g_k16 + (((size_t)b * NKV + h) * LL + l) * HD;
        #pragma unroll
        for (int j = 0; j < 8; j++) {
            int   d   = lane + 32 * j;
            float rot = (j < 4) ? -xn[j + 4] : xn[j - 4];
            float c   = cosb[(size_t)l * HD + d];
            float s   = sinb[(size_t)l * HD + d];
            dst[d] = __float2half_rn(xn[j] * c + rot * s);
        }
    } else {                                  // V heads: fp32 -> fp16 copy
        int h = wid - 20;
        const float* src = qkv + (size_t)row * NQKV + 2 * INNER + NKV * HD + h * HD;
        __half* dst = g_v16 + (((size_t)b * NKV + h) * LL + l) * HD;
        #pragma unroll
        for (int j = 0; j < 8; j++) {
            int d = lane + 32 * j;
            dst[d] = __float2half_rn(src[d]);
        }
    }
}

// ---------------- mma flash attention + fused gate + packed-A epilogue ------
constexpr int QTILE = 64;
constexpr int KTILE = 32;
constexpr int QS_LD = 264;
constexpr int KS_LD = 264;
constexpr int ATT_SMEM = (QTILE * QS_LD + 2 * KTILE * KS_LD) * 2;  // 67584

__global__ void __launch_bounds__(128) attn_mma()
{
    extern __shared__ __half sm[];
    __half* Qs = sm;                        // [64][264]
    __half* Ks = Qs + QTILE * QS_LD;        // [32][264]
    __half* Vs = Ks + KTILE * KS_LD;        // [32][264] row-major (ldmatrix.trans)

    const int b  = blockIdx.z, h = blockIdx.y;
    const int q0 = (gridDim.x - 1 - blockIdx.x) * QTILE;   // heavy CTAs first
    const int kv = h >> 2;
    const int tid = threadIdx.x, wid = tid >> 5, lane = tid & 31;
    const int g = lane >> 2, t = lane & 3;
    const int wr = wid * 16;

    const __half* Qg = g_q16 + (((size_t)b * NH  + h)  * LL + q0) * HD;
    const __half* Kg = g_k16 + (((size_t)b * NKV + kv) * LL) * HD;
    const __half* Vg = g_v16 + (((size_t)b * NKV + kv) * LL) * HD;

    // stage Q once
    #pragma unroll
    for (int i = 0; i < 16; i++) {
        int idx = tid + i * 128;
        int r = idx >> 5, c = (idx & 31) * 8;
        *(uint4*)&Qs[r * QS_LD + c] = *(const uint4*)&Qg[(size_t)r * HD + c];
    }

    // ldmatrix source addresses (bytes)
    const int lrow = ((lane >> 3) & 1) * 8 + (lane & 7);
    const int lcol = (lane >> 4) * 8;
    const uint32_t sQfrag  = (uint32_t)__cvta_generic_to_shared(Qs)
                             + (uint32_t)(wr + lrow) * (QS_LD * 2) + lcol * 2;
    const uint32_t sKfrag  = (uint32_t)__cvta_generic_to_shared(Ks)
                             + (uint32_t)lrow * (KS_LD * 2) + lcol * 2;
    const uint32_t sKfrag2 = sKfrag + 16 * KS_LD * 2;
    const uint32_t sVrow   = (uint32_t)__cvta_generic_to_shared(Vs)
                             + (uint32_t)(lane & 15) * KS_LD * 2;
    const uint32_t sVrow2  = sVrow + 16 * KS_LD * 2;

    float m2[2]    = {-1e30f, -1e30f};
    float lrowv[2] = {0.f, 0.f};
    float O[32][4];
    #pragma unroll
    for (int n = 0; n < 32; n++) { O[n][0] = O[n][1] = O[n][2] = O[n][3] = 0.f; }

    const float cscale = 0.09016994f;       // (1/16) * log2(e)
    const int ntiles = q0 / KTILE + 2;

    for (int tile = 0; tile < ntiles; tile++) {
        const int kb = tile * KTILE;
        __syncthreads();
        #pragma unroll
        for (int i = 0; i < 8; i++) {
            int idx = tid + i * 128;            // 0..1023 uint4 slots
            int r = idx >> 5, c = (idx & 31) * 8;
            *(uint4*)&Ks[r * KS_LD + c] = *(const uint4*)&Kg[(size_t)(kb + r) * HD + c];
            *(uint4*)&Vs[r * KS_LD + c] = *(const uint4*)&Vg[(size_t)(kb + r) * HD + c];
        }
        __syncthreads();

        if (kb > q0 + wr + 15) continue;

        // ---- QK^T: 16 q-rows x 32 k-rows ----
        float s[4][4];
        #pragma unroll
        for (int nt = 0; nt < 4; nt++)
            #pragma unroll
            for (int r = 0; r < 4; r++) s[nt][r] = 0.f;
        #pragma unroll
        for (int c = 0; c < 16; c++) {
            uint32_t a0, a1, a2, a3, k0, k1, k2, k3, k4, k5, k6, k7;
            ldsm_x4(a0, a1, a2, a3, sQfrag  + c * 32);
            ldsm_x4(k0, k1, k2, k3, sKfrag  + c * 32);
            ldsm_x4(k4, k5, k6, k7, sKfrag2 + c * 32);
            mma16(s[0], a0, a1, a2, a3, k0, k2);
            mma16(s[1], a0, a1, a2, a3, k1, k3);
            mma16(s[2], a0, a1, a2, a3, k4, k6);
            mma16(s[3], a0, a1, a2, a3, k5, k7);
        }

        // ---- causal mask ----
        if (kb + 31 > q0 + wr) {
            int r0 = q0 + wr + g, r8 = r0 + 8;
            #pragma unroll
            for (int nt = 0; nt < 4; nt++) {
                int kp = kb + nt * 8 + 2 * t;
                if (kp     > r0) s[nt][0] = -1e30f;
                if (kp + 1 > r0) s[nt][1] = -1e30f;
                if (kp     > r8) s[nt][2] = -1e30f;
                if (kp + 1 > r8) s[nt][3] = -1e30f;
            }
        }

        // ---- online softmax ----
        float r0m = fmaxf(fmaxf(s[0][0], s[0][1]), fmaxf(s[1][0], s[1][1]));
        r0m = fmaxf(r0m, fmaxf(fmaxf(s[2][0], s[2][1]), fmaxf(s[3][0], s[3][1])));
        float r8m = fmaxf(fmaxf(s[0][2], s[0][3]), fmaxf(s[1][2], s[1][3]));
        r8m = fmaxf(r8m, fmaxf(fmaxf(s[2][2], s[2][3]), fmaxf(s[3][2], s[3][3])));
        r0m = fmaxf(r0m, __shfl_xor_sync(0xffffffffu, r0m, 1));
        r0m = fmaxf(r0m, __shfl_xor_sync(0xffffffffu, r0m, 2));
        r8m = fmaxf(r8m, __shfl_xor_sync(0xffffffffu, r8m, 1));
        r8m = fmaxf(r8m, __shfl_xor_sync(0xffffffffu, r8m, 2));
        float m2n0 = fmaxf(m2[0], r0m * cscale);
        float m2n8 = fmaxf(m2[1], r8m * cscale);
        float corr0 = ex2f(m2[0] - m2n0);
        float corr8 = ex2f(m2[1] - m2n8);
        m2[0] = m2n0; m2[1] = m2n8;

        float p[4][4];
        #pragma unroll
        for (int nt = 0; nt < 4; nt++) {
            p[nt][0] = ex2f(fmaf(s[nt][0], cscale, -m2n0));
            p[nt][1] = ex2f(fmaf(s[nt][1], cscale, -m2n0));
            p[nt][2] = ex2f(fmaf(s[nt][2], cscale, -m2n8));
            p[nt][3] = ex2f(fmaf(s[nt][3], cscale, -m2n8));
        }
        lrowv[0] = lrowv[0] * corr0 + (p[0][0] + p[0][1]) + (p[1][0] + p[1][1])
                                    + (p[2][0] + p[2][1]) + (p[3][0] + p[3][1]);
        lrowv[1] = lrowv[1] * corr8 + (p[0][2] + p[0][3]) + (p[1][2] + p[1][3])
                                    + (p[2][2] + p[2][3]) + (p[3][2] + p[3][3]);

        // P fragments for the two 16-k chunks
        uint32_t pc[2][4];
        #pragma unroll
        for (int ch = 0; ch < 2; ch++) {
            __half2 h0 = __float22half2_rn(make_float2(p[2*ch][0],   p[2*ch][1]));
            __half2 h1 = __float22half2_rn(make_float2(p[2*ch][2],   p[2*ch][3]));
            __half2 h2 = __float22half2_rn(make_float2(p[2*ch+1][0], p[2*ch+1][1]));
            __half2 h3 = __float22half2_rn(make_float2(p[2*ch+1][2], p[2*ch+1][3]));
            pc[ch][0] = *(uint32_t*)&h0;
            pc[ch][1] = *(uint32_t*)&h1;
            pc[ch][2] = *(uint32_t*)&h2;
            pc[ch][3] = *(uint32_t*)&h3;
        }

        #pragma unroll
        for (int n = 0; n < 32; n++) {
            O[n][0] *= corr0; O[n][1] *= corr0;
            O[n][2] *= corr8; O[n][3] *= corr8;
            uint32_t b0, b1;
            ldsm_x2_t(b0, b1, sVrow + n * 16);
            mma16(O[n], pc[0][0], pc[0][1], pc[0][2], pc[0][3], b0, b1);
            ldsm_x2_t(b0, b1, sVrow2 + n * 16);
            mma16(O[n], pc[1][0], pc[1][1], pc[1][2], pc[1][3], b0, b1);
        }
    }

    // ---- fused epilogue: 1/l, silu(gate), pack fp16 A-fragments ----
    float l0 = lrowv[0];
    l0 += __shfl_xor_sync(0xffffffffu, l0, 1);
    l0 += __shfl_xor_sync(0xffffffffu, l0, 2);
    float l8 = lrowv[1];
    l8 += __shfl_xor_sync(0xffffffffu, l8, 1);
    l8 += __shfl_xor_sync(0xffffffffu, l8, 2);
    float inv0 = __fdividef(1.f, l0);
    float inv8 = __fdividef(1.f, l8);

    const int r0l = q0 + wr + g;
    const int mt  = (b * LL + q0 + wr) >> 7;
    const int mb  = ((q0 & 64) >> 4) + wid;
    const float* gate0 = g_qkv + (size_t)(b * LL + r0l) * NQKV + INNER + h * HD;
    const float* gate8 = gate0 + (size_t)8 * NQKV;

    #pragma unroll
    for (int n = 0; n < 32; n += 2) {
        int kt = h * 8 + (n >> 2);
        int ks = (n >> 1) & 1;
        size_t off = (((size_t)mt * 128 + kt) * 512 + (ks * 8 + mb) * 32 + lane) * 8;
        int c0 = n * 8 + 2 * t;
        float2 gA0 = *(const float2*)&gate0[c0];
        float2 gB0 = *(const float2*)&gate8[c0];
        float2 gA1 = *(const float2*)&gate0[c0 + 8];
        float2 gB1 = *(const float2*)&gate8[c0 + 8];
        float sA0x = gA0.x / (1.f + __expf(-gA0.x));
        float sA0y = gA0.y / (1.f + __expf(-gA0.y));
        float sB0x = gB0.x / (1.f + __expf(-gB0.x));
        float sB0y = gB0.y / (1.f + __expf(-gB0.y));
        float sA1x = gA1.x / (1.f + __expf(-gA1.x));
        float sA1y = gA1.y / (1.f + __expf(-gA1.y));
        float sB1x = gB1.x / (1.f + __expf(-gB1.x));
        float sB1y = gB1.y / (1.f + __expf(-gB1.y));
        __half hb[8];
        hb[0] = __float2half_rn(O[n][0]     * inv0 * sA0x);
        hb[1] = __float2half_rn(O[n][1]     * inv0 * sA0y);
        hb[2] = __float2half_rn(O[n][2]     * inv8 * sB0x);
        hb[3] = __float2half_rn(O[n][3]     * inv8 * sB0y);
        hb[4] = __float2half_rn(O[n + 1][0] * inv0 * sA1x);
        hb[5] = __float2half_rn(O[n + 1][1] * inv0 * sA1y);
        hb[6] = __float2half_rn(O[n + 1][2] * inv8 * sB1x);
        hb[7] = __float2half_rn(O[n + 1][3] * inv8 * sB1y);
        *(uint4*)&g_attp[off] = *(uint4*)hb;
    }
}

// ---------------- launch ----------------------------------------------------
extern "C" void kernel_launch(void* const* d_in, const int* in_sizes, int n_in,
                              void* d_out, int out_size)
{
    const float* X    = (const float*)d_in[0];
    const float* cosb = (const float*)d_in[1];
    const float* sinb = (const float*)d_in[2];
    const float* Wq   = (const float*)d_in[3];
    const float* Wk   = (const float*)d_in[4];
    const float* Wv   = (const float*)d_in[5];
    const float* Wo   = (const float*)d_in[6];
    const float* qw   = (const float*)d_in[7];
    const float* kw   = (const float*)d_in[8];
    float* out = (float*)d_out;

    float* qkv;
    __half *xp, *attp, *wqkvp, *wop;
    cudaGetSymbolAddress((void**)&qkv,   g_qkv);
    cudaGetSymbolAddress((void**)&xp,    g_xp);
    cudaGetSymbolAddress((void**)&attp,  g_attp);
    cudaGetSymbolAddress((void**)&wqkvp, g_wqkvp);
    cudaGetSymbolAddress((void**)&wop,   g_wop);

    static bool attr_set = false;
    if (!attr_set) {
        cudaFuncSetAttribute(gemm_tc, cudaFuncAttributeMaxDynamicSharedMemorySize,
                             GEMM_SMEM);
        cudaFuncSetAttribute(attn_mma, cudaFuncAttributeMaxDynamicSharedMemorySize,
                             ATT_SMEM);
        attr_set = true;
    }

    constexpr int KTH = HID / 32;
    __half* wq_dst = wqkvp;
    __half* wk_dst = wqkvp + (size_t)(2 * INNER / 128) * KTH * 4096;
    __half* wv_dst = wk_dst + (size_t)(NKV * HD / 128) * KTH * 4096;

    // 0) operand packing
    pack_a<<<(unsigned)((size_t)ROWS * HID      / 2048), 256>>>(X,  xp,  HID);
    pack_b<<<(unsigned)((size_t)HID * 2 * INNER / 2048), 256>>>(Wq, wq_dst, HID, 2 * INNER);
    pack_b<<<(unsigned)((size_t)HID * NKV * HD  / 2048), 256>>>(Wk, wk_dst, HID, NKV * HD);
    pack_b<<<(unsigned)((size_t)HID * NKV * HD  / 2048), 256>>>(Wv, wv_dst, HID, NKV * HD);
    pack_b<<<(unsigned)((size_t)INNER * HID     / 2048), 256>>>(Wo, wop, INNER, HID);

    // 1) fused QKV projection
    gemm_tc<<<dim3(NQKV / 128, ROWS / 128), 128, GEMM_SMEM>>>(xp, wqkvp, qkv, HID, NQKV);

    // 2) fused warp-level RMSNorm + RoPE -> fp16 (Q, K) + V copy
    qkv_prep<<<ROWS, 768>>>(qkv, cosb, sinb, qw, kw);

    // 3) mma flash attention (+ gate + pack fused in epilogue)
    attn_mma<<<dim3(LL / QTILE, NH, BB), 128, ATT_SMEM>>>();

    // 4) output projection
    gemm_tc<<<dim3(HID / 128, ROWS / 128), 128, GEMM_SMEM>>>(attp, wop, out, INNER, HID);
}